// round 10
// baseline (speedup 1.0000x reference)
#include <cuda_runtime.h>
#include <math.h>
#include <stdint.h>

// ---------------- problem constants ----------------
#define BB    2
#define LL    4096
#define DD    512
#define HH    8
#define DHD   64
#define MM    266
#define NROWS (BB*LL)        // 8192
#define CHUNK 64
#define NCH   (LL/CHUNK)     // 64
#define BHT   (BB*HH)        // 16

#define INV_S4      0.21022410381342863f   // 512^-0.25
#define INV_SQRT512 0.04419417382415922f   // 512^-0.5

// ---------------- scratch ----------------
__device__ float g_Q[NROWS*DD];
__device__ float g_K[NROWS*DD];
__device__ float g_V[NROWS*DD];
__device__ float g_hq[NROWS*HH];
__device__ float g_hk[NROWS*HH];
__device__ float g_qp[(size_t)BHT*LL*MM];
__device__ float g_kp[(size_t)BHT*LL*MM];
__device__ float g_S [(size_t)BHT*NCH*MM*DHD];
__device__ float g_z [(size_t)BHT*NCH*MM];
__device__ float g_ctx[NROWS*DD];

// ---------------- TF32 helpers ----------------
__device__ __forceinline__ uint32_t f2tf(float f) {
    uint32_t u;
    asm("cvt.rna.tf32.f32 %0, %1;" : "=r"(u) : "f"(f));
    return u;
}
__device__ __forceinline__ void mma_tf32(float* c, const uint32_t* a,
                                         uint32_t b0, uint32_t b1) {
    asm volatile(
        "mma.sync.aligned.m16n8k8.row.col.f32.tf32.tf32.f32 "
        "{%0,%1,%2,%3}, {%4,%5,%6,%7}, {%8,%9}, {%0,%1,%2,%3};"
        : "+f"(c[0]), "+f"(c[1]), "+f"(c[2]), "+f"(c[3])
        : "r"(a[0]), "r"(a[1]), "r"(a[2]), "r"(a[3]), "r"(b0), "r"(b1));
}

// ---------------- TF32 GEMM (R7 version: unpacked smem + register-prefetch) ----------------
__global__ void __launch_bounds__(256, 2)
tf32_gemm(const float* __restrict__ A0, const float* __restrict__ W0,
          const float* __restrict__ bb0, float* __restrict__ C0,
          const float* __restrict__ A1, const float* __restrict__ W1,
          const float* __restrict__ bb1, float* __restrict__ C1,
          const float* __restrict__ A2, const float* __restrict__ W2,
          const float* __restrict__ bb2, float* __restrict__ C2) {
    __shared__ uint32_t As[128][36];
    __shared__ uint32_t Ws[128][36];

    const float* A; const float* W; const float* bias; float* C;
    if (blockIdx.z == 0)      { A = A0; W = W0; bias = bb0; C = C0; }
    else if (blockIdx.z == 1) { A = A1; W = W1; bias = bb1; C = C1; }
    else                      { A = A2; W = W2; bias = bb2; C = C2; }

    const int t = threadIdx.x;
    const int wid = t >> 5, lane = t & 31;
    const int warp_m = (wid & 3) * 32;
    const int warp_n = (wid >> 2) * 64;
    const int row0 = blockIdx.y * 128, col0 = blockIdx.x * 128;
    const int g = lane >> 2, tg = lane & 3;
    const int rl = t >> 3;
    const int ql = (t & 7) * 4;

    float c[2][8][4];
    #pragma unroll
    for (int f = 0; f < 2; f++)
        #pragma unroll
        for (int j = 0; j < 8; j++)
            #pragma unroll
            for (int q = 0; q < 4; q++) c[f][j][q] = 0.f;

    float4 aR[4], wR[4];
    #pragma unroll
    for (int i = 0; i < 4; i++) {
        aR[i] = *(const float4*)&A[(size_t)(row0 + rl + i * 32) * DD + ql];
        wR[i] = *(const float4*)&W[(size_t)(col0 + rl + i * 32) * DD + ql];
    }
    #pragma unroll
    for (int i = 0; i < 4; i++) {
        *(uint4*)&As[rl + i * 32][ql] =
            make_uint4(f2tf(aR[i].x), f2tf(aR[i].y), f2tf(aR[i].z), f2tf(aR[i].w));
        *(uint4*)&Ws[rl + i * 32][ql] =
            make_uint4(f2tf(wR[i].x), f2tf(wR[i].y), f2tf(wR[i].z), f2tf(wR[i].w));
    }
    __syncthreads();

    for (int kt = 0; kt < DD / 32; kt++) {
        if (kt < DD / 32 - 1) {
            int ks = (kt + 1) * 32;
            #pragma unroll
            for (int i = 0; i < 4; i++) {
                aR[i] = *(const float4*)&A[(size_t)(row0 + rl + i * 32) * DD + ks + ql];
                wR[i] = *(const float4*)&W[(size_t)(col0 + rl + i * 32) * DD + ks + ql];
            }
        }
        #pragma unroll
        for (int k8 = 0; k8 < 32; k8 += 8) {
            uint32_t a[2][4];
            #pragma unroll
            for (int f = 0; f < 2; f++) {
                int m0 = warp_m + 16 * f;
                a[f][0] = As[m0 + g][k8 + tg];
                a[f][1] = As[m0 + g + 8][k8 + tg];
                a[f][2] = As[m0 + g][k8 + tg + 4];
                a[f][3] = As[m0 + g + 8][k8 + tg + 4];
            }
            #pragma unroll
            for (int j = 0; j < 8; j++) {
                uint32_t b0 = Ws[warp_n + 8 * j + g][k8 + tg];
                uint32_t b1 = Ws[warp_n + 8 * j + g][k8 + tg + 4];
                mma_tf32(c[0][j], a[0], b0, b1);
                mma_tf32(c[1][j], a[1], b0, b1);
            }
        }
        if (kt < DD / 32 - 1) {
            __syncthreads();
            #pragma unroll
            for (int i = 0; i < 4; i++) {
                *(uint4*)&As[rl + i * 32][ql] =
                    make_uint4(f2tf(aR[i].x), f2tf(aR[i].y), f2tf(aR[i].z), f2tf(aR[i].w));
                *(uint4*)&Ws[rl + i * 32][ql] =
                    make_uint4(f2tf(wR[i].x), f2tf(wR[i].y), f2tf(wR[i].z), f2tf(wR[i].w));
            }
            __syncthreads();
        }
    }

    #pragma unroll
    for (int f = 0; f < 2; f++) {
        int r0 = row0 + warp_m + 16 * f + g;
        #pragma unroll
        for (int j = 0; j < 8; j++) {
            int cidx = col0 + warp_n + 8 * j + 2 * tg;
            float bx = bias[cidx], by = bias[cidx + 1];
            float2 o0 = make_float2(c[f][j][0] + bx, c[f][j][1] + by);
            float2 o1 = make_float2(c[f][j][2] + bx, c[f][j][3] + by);
            *(float2*)&C[(size_t)r0 * DD + cidx] = o0;
            *(float2*)&C[(size_t)(r0 + 8) * DD + cidx] = o1;
        }
    }
}

// ---------------- hq (merged Q/K) ----------------
__global__ void hq_kernel(const float* __restrict__ Xq, const float* __restrict__ Xk,
                          float* __restrict__ hq, float* __restrict__ hk) {
    int row = blockIdx.x;
    const float* X = blockIdx.y ? Xk : Xq;
    float* hout    = blockIdx.y ? hk : hq;
    int w = threadIdx.x >> 5, lane = threadIdx.x & 31;
    const float* xr = X + (size_t)row * DD + w * DHD;
    float2 v = *(const float2*)&xr[lane * 2];
    float s = v.x * v.x + v.y * v.y;
    #pragma unroll
    for (int off = 16; off; off >>= 1) s += __shfl_xor_sync(0xffffffffu, s, off);
    if (lane == 0) hout[(size_t)row * HH + w] = -0.5f * INV_SQRT512 * s;
}

// ---------------- feature map (TF32 mma, merged Q/K) ----------------
__global__ void __launch_bounds__(256) feat_gemm(const float* __restrict__ Xq,
                                                 const float* __restrict__ Xk,
                                                 const float* __restrict__ RF,
                                                 const float* __restrict__ hqv,
                                                 const float* __restrict__ hkv,
                                                 float* __restrict__ outq,
                                                 float* __restrict__ outk) {
    __shared__ uint32_t Xs[128][36];
    __shared__ uint32_t Rs[64][36];

    const int t = threadIdx.x;
    const int wid = t >> 5, lane = t & 31;
    const int g = lane >> 2, tg = lane & 3;
    const int warp_m = (wid & 3) * 32;
    const int warp_n = (wid >> 2) * 32;
    const int sel = blockIdx.z >> 3;
    const int h  = blockIdx.z & 7;
    const float* X  = sel ? Xk : Xq;
    const float* hv = sel ? hkv : hqv;
    float* outp     = sel ? outk : outq;
    const int r0 = blockIdx.y * 128;
    const int m0 = blockIdx.x * 64;
    const bool full = (m0 + 64 <= MM);

    float c[2][4][4];
    #pragma unroll
    for (int f = 0; f < 2; f++)
        #pragma unroll
        for (int j = 0; j < 4; j++)
            #pragma unroll
            for (int q = 0; q < 4; q++) c[f][j][q] = 0.f;

    for (int kc = 0; kc < DHD; kc += 32) {
        #pragma unroll
        for (int i = 0; i < 4; i++) {
            int idx = t + i * 256;
            int r = idx >> 3, q = idx & 7;
            float4 xv = *(const float4*)&X[(size_t)(r0 + r) * DD + h * DHD + kc + q * 4];
            uint4 xu = make_uint4(f2tf(xv.x * INV_S4), f2tf(xv.y * INV_S4),
                                  f2tf(xv.z * INV_S4), f2tf(xv.w * INV_S4));
            *(uint4*)&Xs[r][q * 4] = xu;
        }
        if (full) {
            #pragma unroll
            for (int i = 0; i < 2; i++) {
                int idx = t + i * 256;
                int mr = idx >> 3, q = idx & 7;
                float4 rv = *(const float4*)&RF[(size_t)(m0 + mr) * DHD + kc + q * 4];
                *(uint4*)&Rs[mr][q * 4] =
                    make_uint4(f2tf(rv.x), f2tf(rv.y), f2tf(rv.z), f2tf(rv.w));
            }
        } else {
            #pragma unroll
            for (int i = 0; i < 2; i++) {
                int idx = t + i * 256;
                int mr = idx >> 3, q = idx & 7;
                float4 rv = make_float4(0.f, 0.f, 0.f, 0.f);
                if (m0 + mr < MM) rv = *(const float4*)&RF[(size_t)(m0 + mr) * DHD + kc + q * 4];
                *(uint4*)&Rs[mr][q * 4] =
                    make_uint4(f2tf(rv.x), f2tf(rv.y), f2tf(rv.z), f2tf(rv.w));
            }
        }
        __syncthreads();
        #pragma unroll
        for (int k8 = 0; k8 < 32; k8 += 8) {
            uint32_t a[2][4];
            #pragma unroll
            for (int f = 0; f < 2; f++) {
                int mw = warp_m + 16 * f;
                a[f][0] = Xs[mw + g][k8 + tg];
                a[f][1] = Xs[mw + g + 8][k8 + tg];
                a[f][2] = Xs[mw + g][k8 + tg + 4];
                a[f][3] = Xs[mw + g + 8][k8 + tg + 4];
            }
            #pragma unroll
            for (int j = 0; j < 4; j++) {
                uint32_t b0 = Rs[warp_n + 8 * j + g][k8 + tg];
                uint32_t b1 = Rs[warp_n + 8 * j + g][k8 + tg + 4];
                mma_tf32(c[0][j], a[0], b0, b1);
                mma_tf32(c[1][j], a[1], b0, b1);
            }
        }
        __syncthreads();
    }

    #pragma unroll
    for (int f = 0; f < 2; f++) {
        int ra = r0 + warp_m + 16 * f + g;
        int rb = ra + 8;
        float ha = hv[(size_t)ra * HH + h];
        float hb = hv[(size_t)rb * HH + h];
        int ba = ra >> 12, la = ra & 4095;
        int bb = rb >> 12, lb = rb & 4095;
        size_t basea = (((size_t)(ba * HH + h)) * LL + la) * MM;
        size_t baseb = (((size_t)(bb * HH + h)) * LL + lb) * MM;
        if (full) {
            #pragma unroll
            for (int j = 0; j < 4; j++) {
                int m = m0 + warp_n + 8 * j + 2 * tg;
                *(float2*)&outp[basea + m] =
                    make_float2(__expf(c[f][j][0] + ha), __expf(c[f][j][1] + ha));
                *(float2*)&outp[baseb + m] =
                    make_float2(__expf(c[f][j][2] + hb), __expf(c[f][j][3] + hb));
            }
        } else {
            #pragma unroll
            for (int j = 0; j < 4; j++) {
                int m = m0 + warp_n + 8 * j + 2 * tg;
                if (m < MM)     outp[basea + m]     = __expf(c[f][j][0] + ha);
                if (m + 1 < MM) outp[basea + m + 1] = __expf(c[f][j][1] + ha);
                if (m < MM)     outp[baseb + m]     = __expf(c[f][j][2] + hb);
                if (m + 1 < MM) outp[baseb + m + 1] = __expf(c[f][j][3] + hb);
            }
        }
    }
}

// ---------------- phase A (TF32 mma, 17 warps, double-buffered, 2 blocks/SM) ----------------
__global__ void __launch_bounds__(544, 2) phaseA_kernel() {
    __shared__ uint32_t sk[2][16][276];
    __shared__ uint32_t sv[2][16][68];

    const int tid = threadIdx.x;
    const int wid = tid >> 5, lane = tid & 31;
    const int g = lane >> 2, tg = lane & 3;
    const int c = blockIdx.x, bh = blockIdx.y;
    const int b = bh >> 3, h = bh & 7;
    const int l0 = c * CHUNK;
    const float* kb = g_kp + ((size_t)bh * LL + l0) * MM;
    const float* vb = g_V + ((size_t)(b * LL + l0)) * DD + h * DHD;
    const int m0 = wid * 16;            // warp-private m tile

    float acc[8][4];
    #pragma unroll
    for (int j = 0; j < 8; j++)
        #pragma unroll
        for (int q = 0; q < 4; q++) acc[j][q] = 0.f;
    float zacc = 0.f;

    const int svt = tid >> 4, svd = (tid & 15) * 4;   // for tid<256

    // stage t-tile 0 into buffer 0
    #pragma unroll
    for (int idx = tid; idx < 16 * 136; idx += 544) {
        int t = idx / 136, m2 = (idx % 136) * 2;
        float2 kv = make_float2(0.f, 0.f);
        if (m2 < MM) kv = *(const float2*)&kb[(size_t)t * MM + m2];
        sk[0][t][m2]     = f2tf(kv.x);
        sk[0][t][m2 + 1] = f2tf(kv.y);
    }
    if (tid < 256) {
        float4 vv = *(const float4*)&vb[(size_t)svt * DD + svd];
        sv[0][svt][svd]     = f2tf(vv.x);
        sv[0][svt][svd + 1] = f2tf(vv.y);
        sv[0][svt][svd + 2] = f2tf(vv.z);
        sv[0][svt][svd + 3] = f2tf(vv.w);
    }
    __syncthreads();

    int buf = 0;
    #pragma unroll
    for (int it = 0; it < 4; it++) {
        // stage next tile into alternate buffer (no sync needed: other buffer)
        if (it < 3) {
            int t0 = (it + 1) * 16;
            #pragma unroll
            for (int idx = tid; idx < 16 * 136; idx += 544) {
                int t = idx / 136, m2 = (idx % 136) * 2;
                float2 kv = make_float2(0.f, 0.f);
                if (m2 < MM) kv = *(const float2*)&kb[(size_t)(t0 + t) * MM + m2];
                sk[buf ^ 1][t][m2]     = f2tf(kv.x);
                sk[buf ^ 1][t][m2 + 1] = f2tf(kv.y);
            }
            if (tid < 256) {
                float4 vv = *(const float4*)&vb[(size_t)(t0 + svt) * DD + svd];
                sv[buf ^ 1][svt][svd]     = f2tf(vv.x);
                sv[buf ^ 1][svt][svd + 1] = f2tf(vv.y);
                sv[buf ^ 1][svt][svd + 2] = f2tf(vv.z);
                sv[buf ^ 1][svt][svd + 3] = f2tf(vv.w);
            }
        }
        // z partial on current buffer
        if (tid < 272) {
            #pragma unroll
            for (int t = 0; t < 16; t++) zacc += __uint_as_float(sk[buf][t][tid]);
        }
        // mma on current buffer
        #pragma unroll
        for (int k8 = 0; k8 < 16; k8 += 8) {
            uint32_t a[4];
            a[0] = sk[buf][k8 + tg][m0 + g];
            a[1] = sk[buf][k8 + tg][m0 + g + 8];
            a[2] = sk[buf][k8 + tg + 4][m0 + g];
            a[3] = sk[buf][k8 + tg + 4][m0 + g + 8];
            #pragma unroll
            for (int j = 0; j < 8; j++) {
                uint32_t b0 = sv[buf][k8 + tg][j * 8 + g];
                uint32_t b1 = sv[buf][k8 + tg + 4][j * 8 + g];
                mma_tf32(acc[j], a, b0, b1);
            }
        }
        __syncthreads();
        buf ^= 1;
    }

    float* Sb = g_S + ((size_t)bh * NCH + c) * (MM * DHD);
    int mlo = m0 + g, mhi = m0 + g + 8;
    #pragma unroll
    for (int j = 0; j < 8; j++) {
        int d = j * 8 + 2 * tg;
        if (mlo < MM) *(float2*)&Sb[(size_t)mlo * DHD + d] =
            make_float2(acc[j][0], acc[j][1]);
        if (mhi < MM) *(float2*)&Sb[(size_t)mhi * DHD + d] =
            make_float2(acc[j][2], acc[j][3]);
    }
    if (tid < MM) g_z[((size_t)bh * NCH + c) * MM + tid] = zacc;
}

// ---------------- exclusive prefix over chunks ----------------
__global__ void scan_kernel(float* data, int per) {
    int gid = blockIdx.x * blockDim.x + threadIdx.x;
    if (gid >= BHT * per) return;
    int bh = gid / per, e = gid % per;
    size_t base = (size_t)bh * NCH * per + e;
    float run = 0.f;
    #pragma unroll 4
    for (int c = 0; c < NCH; c++) {
        size_t idx = base + (size_t)c * per;
        float cur = data[idx];
        data[idx] = run;
        run += cur;
    }
}

// ---------------- phase C (TF32 mma, fused scores + inter pass, 3 blocks/SM) ----------------
__global__ void __launch_bounds__(256, 3) phaseC_kernel() {
    __shared__ uint32_t A_sh[64][68];
    __shared__ uint32_t wbuf[4608];
    __shared__ uint32_t Ssb[32 * 68];
    __shared__ float zs[32];
    __shared__ float dred[4][64];
    __shared__ float den_sh[64];

    uint32_t (*qs)[36] = (uint32_t(*)[36])wbuf;
    uint32_t (*ks)[36] = (uint32_t(*)[36])(wbuf + 2304);
    uint32_t (*Vs)[68] = (uint32_t(*)[68])wbuf;
    uint32_t (*Ss)[68] = (uint32_t(*)[68])Ssb;

    const int tid = threadIdx.x;
    const int wid = tid >> 5, lane = tid & 31;
    const int g = lane >> 2, tg = lane & 3;
    const int t0 = (wid & 3) * 16;
    const int n0 = (wid >> 2) * 32;
    const int c = blockIdx.x, bh = blockIdx.y;
    const int b = bh >> 3, h = bh & 7;
    const int l0 = c * CHUNK;
    const float* qb = g_qp + ((size_t)bh * LL + l0) * MM;
    const float* kb = g_kp + ((size_t)bh * LL + l0) * MM;
    const float* zb = g_z + ((size_t)bh * NCH + c) * MM;
    const float* Sb = g_S + ((size_t)bh * NCH + c) * (MM * DHD);

    float c1[4][4], c2[4][4];
    #pragma unroll
    for (int j = 0; j < 4; j++)
        #pragma unroll
        for (int q = 0; q < 4; q++) { c1[j][q] = 0.f; c2[j][q] = 0.f; }
    float dq = 0.f;
    const int dt = tid & 63, dslice = tid >> 6;

    for (int m0 = 0; m0 < 272; m0 += 32) {
        #pragma unroll 4
        for (int idx = tid; idx < 64 * 16; idx += 256) {
            int t = idx >> 4, m2 = (idx & 15) * 2;
            int m = m0 + m2;
            float2 qv = make_float2(0.f, 0.f), kv = make_float2(0.f, 0.f);
            if (m < MM) {
                qv = *(const float2*)&qb[(size_t)t * MM + m];
                kv = *(const float2*)&kb[(size_t)t * MM + m];
            }
            qs[t][m2] = f2tf(qv.x); qs[t][m2 + 1] = f2tf(qv.y);
            ks[t][m2] = f2tf(kv.x); ks[t][m2 + 1] = f2tf(kv.y);
        }
        #pragma unroll 2
        for (int idx = tid; idx < 32 * 16; idx += 256) {
            int mm = idx >> 4, d4 = (idx & 15) * 4;
            int m = m0 + mm;
            float4 sv4 = make_float4(0.f, 0.f, 0.f, 0.f);
            if (m < MM) sv4 = *(const float4*)&Sb[(size_t)m * DHD + d4];
            Ss[mm][d4]     = f2tf(sv4.x);
            Ss[mm][d4 + 1] = f2tf(sv4.y);
            Ss[mm][d4 + 2] = f2tf(sv4.z);
            Ss[mm][d4 + 3] = f2tf(sv4.w);
        }
        if (tid < 32) zs[tid] = (m0 + tid < MM) ? zb[m0 + tid] : 0.f;
        __syncthreads();
        #pragma unroll
        for (int i = 0; i < 8; i++) {
            int mm = dslice * 8 + i;
            dq += __uint_as_float(qs[dt][mm]) * zs[mm];
        }
        #pragma unroll
        for (int k8 = 0; k8 < 32; k8 += 8) {
            uint32_t a[4];
            a[0] = qs[t0 + g][k8 + tg];
            a[1] = qs[t0 + g + 8][k8 + tg];
            a[2] = qs[t0 + g][k8 + tg + 4];
            a[3] = qs[t0 + g + 8][k8 + tg + 4];
            #pragma unroll
            for (int j = 0; j < 4; j++) {
                uint32_t b0 = ks[n0 + j * 8 + g][k8 + tg];
                uint32_t b1 = ks[n0 + j * 8 + g][k8 + tg + 4];
                mma_tf32(c1[j], a, b0, b1);
            }
            #pragma unroll
            for (int j = 0; j < 4; j++) {
                uint32_t b0 = Ss[k8 + tg][n0 + j * 8 + g];
                uint32_t b1 = Ss[k8 + tg + 4][n0 + j * 8 + g];
                mma_tf32(c2[j], a, b0, b1);
            }
        }
        __syncthreads();
    }
    dred[dslice][dt] = dq;

    {
        int ta = t0 + g, tb2 = t0 + g + 8;
        #pragma unroll
        for (int j = 0; j < 4; j++) {
            int s = n0 + j * 8 + 2 * tg;
            A_sh[ta][s]      = f2tf((s     <= ta)  ? c1[j][0] : 0.f);
            A_sh[ta][s + 1]  = f2tf((s + 1 <= ta)  ? c1[j][1] : 0.f);
            A_sh[tb2][s]     = f2tf((s     <= tb2) ? c1[j][2] : 0.f);
            A_sh[tb2][s + 1] = f2tf((s + 1 <= tb2) ? c1[j][3] : 0.f);
        }
    }
    __syncthreads();

    if (tid < 64) {
        float r = dred[0][tid] + dred[1][tid] + dred[2][tid] + dred[3][tid];
        #pragma unroll 8
        for (int s = 0; s < 64; s++) r += __uint_as_float(A_sh[tid][s]);
        den_sh[tid] = r;
    }

    {
        int t = tid >> 2, d16 = (tid & 3) * 16;
        const float* vr = &g_V[((size_t)(b * LL + l0 + t)) * DD + h * DHD + d16];
        #pragma unroll
        for (int q = 0; q < 4; q++) {
            float4 vv = *(const float4*)&vr[q * 4];
            Vs[t][d16 + q * 4]     = f2tf(vv.x);
            Vs[t][d16 + q * 4 + 1] = f2tf(vv.y);
            Vs[t][d16 + q * 4 + 2] = f2tf(vv.z);
            Vs[t][d16 + q * 4 + 3] = f2tf(vv.w);
        }
    }
    __syncthreads();

    #pragma unroll
    for (int k8 = 0; k8 < 64; k8 += 8) {
        uint32_t a[4];
        a[0] = A_sh[t0 + g][k8 + tg];
        a[1] = A_sh[t0 + g + 8][k8 + tg];
        a[2] = A_sh[t0 + g][k8 + tg + 4];
        a[3] = A_sh[t0 + g + 8][k8 + tg + 4];
        #pragma unroll
        for (int j = 0; j < 4; j++) {
            uint32_t b0 = Vs[k8 + tg][n0 + j * 8 + g];
            uint32_t b1 = Vs[k8 + tg + 4][n0 + j * 8 + g];
            mma_tf32(c2[j], a, b0, b1);
        }
    }

    {
        int ta = t0 + g, tb2 = t0 + g + 8;
        float inva = 1.0f / den_sh[ta];
        float invb = 1.0f / den_sh[tb2];
        #pragma unroll
        for (int j = 0; j < 4; j++) {
            int d = n0 + j * 8 + 2 * tg;
            *(float2*)&g_ctx[((size_t)(b * LL + l0 + ta)) * DD + h * DHD + d] =
                make_float2(c2[j][0] * inva, c2[j][1] * inva);
            *(float2*)&g_ctx[((size_t)(b * LL + l0 + tb2)) * DD + h * DHD + d] =
                make_float2(c2[j][2] * invb, c2[j][3] * invb);
        }
    }
}

// ---------------- launch ----------------
extern "C" void kernel_launch(void* const* d_in, const int* in_sizes, int n_in,
                              void* d_out, int out_size) {
    const float* query = (const float*)d_in[0];
    const float* key   = (const float*)d_in[1];
    const float* value = (const float*)d_in[2];
    const float* Wq    = (const float*)d_in[3];
    const float* bq    = (const float*)d_in[4];
    const float* Wk    = (const float*)d_in[5];
    const float* bk    = (const float*)d_in[6];
    const float* Wv    = (const float*)d_in[7];
    const float* bv    = (const float*)d_in[8];
    const float* Wout  = (const float*)d_in[9];
    const float* bout  = (const float*)d_in[10];
    const float* RF    = (const float*)d_in[11];

    float *Qp, *Kp, *Vp, *hqp, *hkp, *qpp, *kpp, *Sp, *zp, *ctxp;
    cudaGetSymbolAddress((void**)&Qp,  g_Q);
    cudaGetSymbolAddress((void**)&Kp,  g_K);
    cudaGetSymbolAddress((void**)&Vp,  g_V);
    cudaGetSymbolAddress((void**)&hqp, g_hq);
    cudaGetSymbolAddress((void**)&hkp, g_hk);
    cudaGetSymbolAddress((void**)&qpp, g_qp);
    cudaGetSymbolAddress((void**)&kpp, g_kp);
    cudaGetSymbolAddress((void**)&Sp,  g_S);
    cudaGetSymbolAddress((void**)&zp,  g_z);
    cudaGetSymbolAddress((void**)&ctxp, g_ctx);

    dim3 gp(DD / 128, NROWS / 128, 3);
    tf32_gemm<<<gp, 256>>>(query, Wq, bq, Qp,
                           key,   Wk, bk, Kp,
                           value, Wv, bv, Vp);

    dim3 hg(NROWS, 2);
    hq_kernel<<<hg, 256>>>(Qp, Kp, hqp, hkp);

    dim3 fg((MM + 63) / 64, NROWS / 128, 2 * HH);
    feat_gemm<<<fg, 256>>>(Qp, Kp, RF, hqp, hkp, qpp, kpp);

    dim3 pg(NCH, BHT);
    phaseA_kernel<<<pg, 544>>>();

    int perS = MM * DHD;
    scan_kernel<<<(BHT * perS + 255) / 256, 256>>>(Sp, perS);
    scan_kernel<<<(BHT * MM + 255) / 256, 256>>>(zp, MM);

    phaseC_kernel<<<pg, 256>>>();

    dim3 go(DD / 128, NROWS / 128, 1);
    tf32_gemm<<<go, 256>>>(ctxp, Wout, bout, (float*)d_out,
                           ctxp, Wout, bout, (float*)d_out,
                           ctxp, Wout, bout, (float*)d_out);
}

// round 11
// speedup vs baseline: 1.0971x; 1.0971x over previous
#include <cuda_runtime.h>
#include <math.h>
#include <stdint.h>

// ---------------- problem constants ----------------
#define BB    2
#define LL    4096
#define DD    512
#define HH    8
#define DHD   64
#define MM    266
#define NROWS (BB*LL)        // 8192
#define CHUNK 64
#define NCH   (LL/CHUNK)     // 64
#define BHT   (BB*HH)        // 16

#define INV_S4      0.21022410381342863f   // 512^-0.25
#define INV_SQRT512 0.04419417382415922f   // 512^-0.5

// ---------------- scratch ----------------
__device__ float g_Q[NROWS*DD];
__device__ float g_K[NROWS*DD];
__device__ float g_V[NROWS*DD];
__device__ float g_hq[NROWS*HH];
__device__ float g_hk[NROWS*HH];
__device__ float g_qp[(size_t)BHT*LL*MM];
__device__ float g_kp[(size_t)BHT*LL*MM];
__device__ float g_S [(size_t)BHT*NCH*MM*DHD];
__device__ float g_z [(size_t)BHT*NCH*MM];
__device__ float g_ctx[NROWS*DD];

// ---------------- TF32 helpers ----------------
__device__ __forceinline__ uint32_t f2tf(float f) {
    uint32_t u;
    asm("cvt.rna.tf32.f32 %0, %1;" : "=r"(u) : "f"(f));
    return u;
}
__device__ __forceinline__ void mma_tf32(float* c, const uint32_t* a,
                                         uint32_t b0, uint32_t b1) {
    asm volatile(
        "mma.sync.aligned.m16n8k8.row.col.f32.tf32.tf32.f32 "
        "{%0,%1,%2,%3}, {%4,%5,%6,%7}, {%8,%9}, {%0,%1,%2,%3};"
        : "+f"(c[0]), "+f"(c[1]), "+f"(c[2]), "+f"(c[3])
        : "r"(a[0]), "r"(a[1]), "r"(a[2]), "r"(a[3]), "r"(b0), "r"(b1));
}

// ---------------- TF32 GEMM (unpacked smem + register-prefetch) ----------------
__global__ void __launch_bounds__(256, 2)
tf32_gemm(const float* __restrict__ A0, const float* __restrict__ W0,
          const float* __restrict__ bb0, float* __restrict__ C0,
          const float* __restrict__ A1, const float* __restrict__ W1,
          const float* __restrict__ bb1, float* __restrict__ C1,
          const float* __restrict__ A2, const float* __restrict__ W2,
          const float* __restrict__ bb2, float* __restrict__ C2) {
    __shared__ uint32_t As[128][36];
    __shared__ uint32_t Ws[128][36];

    const float* A; const float* W; const float* bias; float* C;
    if (blockIdx.z == 0)      { A = A0; W = W0; bias = bb0; C = C0; }
    else if (blockIdx.z == 1) { A = A1; W = W1; bias = bb1; C = C1; }
    else                      { A = A2; W = W2; bias = bb2; C = C2; }

    const int t = threadIdx.x;
    const int wid = t >> 5, lane = t & 31;
    const int warp_m = (wid & 3) * 32;
    const int warp_n = (wid >> 2) * 64;
    const int row0 = blockIdx.y * 128, col0 = blockIdx.x * 128;
    const int g = lane >> 2, tg = lane & 3;
    const int rl = t >> 3;
    const int ql = (t & 7) * 4;

    float c[2][8][4];
    #pragma unroll
    for (int f = 0; f < 2; f++)
        #pragma unroll
        for (int j = 0; j < 8; j++)
            #pragma unroll
            for (int q = 0; q < 4; q++) c[f][j][q] = 0.f;

    float4 aR[4], wR[4];
    #pragma unroll
    for (int i = 0; i < 4; i++) {
        aR[i] = *(const float4*)&A[(size_t)(row0 + rl + i * 32) * DD + ql];
        wR[i] = *(const float4*)&W[(size_t)(col0 + rl + i * 32) * DD + ql];
    }
    #pragma unroll
    for (int i = 0; i < 4; i++) {
        *(uint4*)&As[rl + i * 32][ql] =
            make_uint4(f2tf(aR[i].x), f2tf(aR[i].y), f2tf(aR[i].z), f2tf(aR[i].w));
        *(uint4*)&Ws[rl + i * 32][ql] =
            make_uint4(f2tf(wR[i].x), f2tf(wR[i].y), f2tf(wR[i].z), f2tf(wR[i].w));
    }
    __syncthreads();

    for (int kt = 0; kt < DD / 32; kt++) {
        if (kt < DD / 32 - 1) {
            int ks = (kt + 1) * 32;
            #pragma unroll
            for (int i = 0; i < 4; i++) {
                aR[i] = *(const float4*)&A[(size_t)(row0 + rl + i * 32) * DD + ks + ql];
                wR[i] = *(const float4*)&W[(size_t)(col0 + rl + i * 32) * DD + ks + ql];
            }
        }
        #pragma unroll
        for (int k8 = 0; k8 < 32; k8 += 8) {
            uint32_t a[2][4];
            #pragma unroll
            for (int f = 0; f < 2; f++) {
                int m0 = warp_m + 16 * f;
                a[f][0] = As[m0 + g][k8 + tg];
                a[f][1] = As[m0 + g + 8][k8 + tg];
                a[f][2] = As[m0 + g][k8 + tg + 4];
                a[f][3] = As[m0 + g + 8][k8 + tg + 4];
            }
            #pragma unroll
            for (int j = 0; j < 8; j++) {
                uint32_t b0 = Ws[warp_n + 8 * j + g][k8 + tg];
                uint32_t b1 = Ws[warp_n + 8 * j + g][k8 + tg + 4];
                mma_tf32(c[0][j], a[0], b0, b1);
                mma_tf32(c[1][j], a[1], b0, b1);
            }
        }
        if (kt < DD / 32 - 1) {
            __syncthreads();
            #pragma unroll
            for (int i = 0; i < 4; i++) {
                *(uint4*)&As[rl + i * 32][ql] =
                    make_uint4(f2tf(aR[i].x), f2tf(aR[i].y), f2tf(aR[i].z), f2tf(aR[i].w));
                *(uint4*)&Ws[rl + i * 32][ql] =
                    make_uint4(f2tf(wR[i].x), f2tf(wR[i].y), f2tf(wR[i].z), f2tf(wR[i].w));
            }
            __syncthreads();
        }
    }

    #pragma unroll
    for (int f = 0; f < 2; f++) {
        int r0 = row0 + warp_m + 16 * f + g;
        #pragma unroll
        for (int j = 0; j < 8; j++) {
            int cidx = col0 + warp_n + 8 * j + 2 * tg;
            float bx = bias[cidx], by = bias[cidx + 1];
            float2 o0 = make_float2(c[f][j][0] + bx, c[f][j][1] + by);
            float2 o1 = make_float2(c[f][j][2] + bx, c[f][j][3] + by);
            *(float2*)&C[(size_t)r0 * DD + cidx] = o0;
            *(float2*)&C[(size_t)(r0 + 8) * DD + cidx] = o1;
        }
    }
}

// ---------------- hq (merged Q/K) ----------------
__global__ void hq_kernel(const float* __restrict__ Xq, const float* __restrict__ Xk,
                          float* __restrict__ hq, float* __restrict__ hk) {
    int row = blockIdx.x;
    const float* X = blockIdx.y ? Xk : Xq;
    float* hout    = blockIdx.y ? hk : hq;
    int w = threadIdx.x >> 5, lane = threadIdx.x & 31;
    const float* xr = X + (size_t)row * DD + w * DHD;
    float2 v = *(const float2*)&xr[lane * 2];
    float s = v.x * v.x + v.y * v.y;
    #pragma unroll
    for (int off = 16; off; off >>= 1) s += __shfl_xor_sync(0xffffffffu, s, off);
    if (lane == 0) hout[(size_t)row * HH + w] = -0.5f * INV_SQRT512 * s;
}

// ---------------- feature map (TF32 mma, merged Q/K) ----------------
__global__ void __launch_bounds__(256) feat_gemm(const float* __restrict__ Xq,
                                                 const float* __restrict__ Xk,
                                                 const float* __restrict__ RF,
                                                 const float* __restrict__ hqv,
                                                 const float* __restrict__ hkv,
                                                 float* __restrict__ outq,
                                                 float* __restrict__ outk) {
    __shared__ uint32_t Xs[128][36];
    __shared__ uint32_t Rs[64][36];

    const int t = threadIdx.x;
    const int wid = t >> 5, lane = t & 31;
    const int g = lane >> 2, tg = lane & 3;
    const int warp_m = (wid & 3) * 32;
    const int warp_n = (wid >> 2) * 32;
    const int sel = blockIdx.z >> 3;
    const int h  = blockIdx.z & 7;
    const float* X  = sel ? Xk : Xq;
    const float* hv = sel ? hkv : hqv;
    float* outp     = sel ? outk : outq;
    const int r0 = blockIdx.y * 128;
    const int m0 = blockIdx.x * 64;
    const bool full = (m0 + 64 <= MM);

    float c[2][4][4];
    #pragma unroll
    for (int f = 0; f < 2; f++)
        #pragma unroll
        for (int j = 0; j < 4; j++)
            #pragma unroll
            for (int q = 0; q < 4; q++) c[f][j][q] = 0.f;

    for (int kc = 0; kc < DHD; kc += 32) {
        #pragma unroll
        for (int i = 0; i < 4; i++) {
            int idx = t + i * 256;
            int r = idx >> 3, q = idx & 7;
            float4 xv = *(const float4*)&X[(size_t)(r0 + r) * DD + h * DHD + kc + q * 4];
            uint4 xu = make_uint4(f2tf(xv.x * INV_S4), f2tf(xv.y * INV_S4),
                                  f2tf(xv.z * INV_S4), f2tf(xv.w * INV_S4));
            *(uint4*)&Xs[r][q * 4] = xu;
        }
        if (full) {
            #pragma unroll
            for (int i = 0; i < 2; i++) {
                int idx = t + i * 256;
                int mr = idx >> 3, q = idx & 7;
                float4 rv = *(const float4*)&RF[(size_t)(m0 + mr) * DHD + kc + q * 4];
                *(uint4*)&Rs[mr][q * 4] =
                    make_uint4(f2tf(rv.x), f2tf(rv.y), f2tf(rv.z), f2tf(rv.w));
            }
        } else {
            #pragma unroll
            for (int i = 0; i < 2; i++) {
                int idx = t + i * 256;
                int mr = idx >> 3, q = idx & 7;
                float4 rv = make_float4(0.f, 0.f, 0.f, 0.f);
                if (m0 + mr < MM) rv = *(const float4*)&RF[(size_t)(m0 + mr) * DHD + kc + q * 4];
                *(uint4*)&Rs[mr][q * 4] =
                    make_uint4(f2tf(rv.x), f2tf(rv.y), f2tf(rv.z), f2tf(rv.w));
            }
        }
        __syncthreads();
        #pragma unroll
        for (int k8 = 0; k8 < 32; k8 += 8) {
            uint32_t a[2][4];
            #pragma unroll
            for (int f = 0; f < 2; f++) {
                int mw = warp_m + 16 * f;
                a[f][0] = Xs[mw + g][k8 + tg];
                a[f][1] = Xs[mw + g + 8][k8 + tg];
                a[f][2] = Xs[mw + g][k8 + tg + 4];
                a[f][3] = Xs[mw + g + 8][k8 + tg + 4];
            }
            #pragma unroll
            for (int j = 0; j < 4; j++) {
                uint32_t b0 = Rs[warp_n + 8 * j + g][k8 + tg];
                uint32_t b1 = Rs[warp_n + 8 * j + g][k8 + tg + 4];
                mma_tf32(c[0][j], a[0], b0, b1);
                mma_tf32(c[1][j], a[1], b0, b1);
            }
        }
        __syncthreads();
    }

    #pragma unroll
    for (int f = 0; f < 2; f++) {
        int ra = r0 + warp_m + 16 * f + g;
        int rb = ra + 8;
        float ha = hv[(size_t)ra * HH + h];
        float hb = hv[(size_t)rb * HH + h];
        int ba = ra >> 12, la = ra & 4095;
        int bb = rb >> 12, lb = rb & 4095;
        size_t basea = (((size_t)(ba * HH + h)) * LL + la) * MM;
        size_t baseb = (((size_t)(bb * HH + h)) * LL + lb) * MM;
        if (full) {
            #pragma unroll
            for (int j = 0; j < 4; j++) {
                int m = m0 + warp_n + 8 * j + 2 * tg;
                *(float2*)&outp[basea + m] =
                    make_float2(__expf(c[f][j][0] + ha), __expf(c[f][j][1] + ha));
                *(float2*)&outp[baseb + m] =
                    make_float2(__expf(c[f][j][2] + hb), __expf(c[f][j][3] + hb));
            }
        } else {
            #pragma unroll
            for (int j = 0; j < 4; j++) {
                int m = m0 + warp_n + 8 * j + 2 * tg;
                if (m < MM)     outp[basea + m]     = __expf(c[f][j][0] + ha);
                if (m + 1 < MM) outp[basea + m + 1] = __expf(c[f][j][1] + ha);
                if (m < MM)     outp[baseb + m]     = __expf(c[f][j][2] + hb);
                if (m + 1 < MM) outp[baseb + m + 1] = __expf(c[f][j][3] + hb);
            }
        }
    }
}

// ---------------- phase A (TF32 mma, 17 warps, double-buffered, 2 blocks/SM) ----------------
__global__ void __launch_bounds__(544, 2) phaseA_kernel() {
    __shared__ uint32_t sk[2][16][276];
    __shared__ uint32_t sv[2][16][68];

    const int tid = threadIdx.x;
    const int wid = tid >> 5, lane = tid & 31;
    const int g = lane >> 2, tg = lane & 3;
    const int c = blockIdx.x, bh = blockIdx.y;
    const int b = bh >> 3, h = bh & 7;
    const int l0 = c * CHUNK;
    const float* kb = g_kp + ((size_t)bh * LL + l0) * MM;
    const float* vb = g_V + ((size_t)(b * LL + l0)) * DD + h * DHD;
    const int m0 = wid * 16;            // warp-private m tile

    float acc[8][4];
    #pragma unroll
    for (int j = 0; j < 8; j++)
        #pragma unroll
        for (int q = 0; q < 4; q++) acc[j][q] = 0.f;
    float zacc = 0.f;

    const int svt = tid >> 4, svd = (tid & 15) * 4;   // for tid<256

    // stage t-tile 0 into buffer 0
    #pragma unroll
    for (int idx = tid; idx < 16 * 136; idx += 544) {
        int t = idx / 136, m2 = (idx % 136) * 2;
        float2 kv = make_float2(0.f, 0.f);
        if (m2 < MM) kv = *(const float2*)&kb[(size_t)t * MM + m2];
        sk[0][t][m2]     = f2tf(kv.x);
        sk[0][t][m2 + 1] = f2tf(kv.y);
    }
    if (tid < 256) {
        float4 vv = *(const float4*)&vb[(size_t)svt * DD + svd];
        sv[0][svt][svd]     = f2tf(vv.x);
        sv[0][svt][svd + 1] = f2tf(vv.y);
        sv[0][svt][svd + 2] = f2tf(vv.z);
        sv[0][svt][svd + 3] = f2tf(vv.w);
    }
    __syncthreads();

    int buf = 0;
    #pragma unroll
    for (int it = 0; it < 4; it++) {
        if (it < 3) {
            int t0 = (it + 1) * 16;
            #pragma unroll
            for (int idx = tid; idx < 16 * 136; idx += 544) {
                int t = idx / 136, m2 = (idx % 136) * 2;
                float2 kv = make_float2(0.f, 0.f);
                if (m2 < MM) kv = *(const float2*)&kb[(size_t)(t0 + t) * MM + m2];
                sk[buf ^ 1][t][m2]     = f2tf(kv.x);
                sk[buf ^ 1][t][m2 + 1] = f2tf(kv.y);
            }
            if (tid < 256) {
                float4 vv = *(const float4*)&vb[(size_t)(t0 + svt) * DD + svd];
                sv[buf ^ 1][svt][svd]     = f2tf(vv.x);
                sv[buf ^ 1][svt][svd + 1] = f2tf(vv.y);
                sv[buf ^ 1][svt][svd + 2] = f2tf(vv.z);
                sv[buf ^ 1][svt][svd + 3] = f2tf(vv.w);
            }
        }
        if (tid < 272) {
            #pragma unroll
            for (int t = 0; t < 16; t++) zacc += __uint_as_float(sk[buf][t][tid]);
        }
        #pragma unroll
        for (int k8 = 0; k8 < 16; k8 += 8) {
            uint32_t a[4];
            a[0] = sk[buf][k8 + tg][m0 + g];
            a[1] = sk[buf][k8 + tg][m0 + g + 8];
            a[2] = sk[buf][k8 + tg + 4][m0 + g];
            a[3] = sk[buf][k8 + tg + 4][m0 + g + 8];
            #pragma unroll
            for (int j = 0; j < 8; j++) {
                uint32_t b0 = sv[buf][k8 + tg][j * 8 + g];
                uint32_t b1 = sv[buf][k8 + tg + 4][j * 8 + g];
                mma_tf32(acc[j], a, b0, b1);
            }
        }
        __syncthreads();
        buf ^= 1;
    }

    float* Sb = g_S + ((size_t)bh * NCH + c) * (MM * DHD);
    int mlo = m0 + g, mhi = m0 + g + 8;
    #pragma unroll
    for (int j = 0; j < 8; j++) {
        int d = j * 8 + 2 * tg;
        if (mlo < MM) *(float2*)&Sb[(size_t)mlo * DHD + d] =
            make_float2(acc[j][0], acc[j][1]);
        if (mhi < MM) *(float2*)&Sb[(size_t)mhi * DHD + d] =
            make_float2(acc[j][2], acc[j][3]);
    }
    if (tid < MM) g_z[((size_t)bh * NCH + c) * MM + tid] = zacc;
}

// ---------------- exclusive prefix over chunks ----------------
__global__ void scan_kernel(float* data, int per) {
    int gid = blockIdx.x * blockDim.x + threadIdx.x;
    if (gid >= BHT * per) return;
    int bh = gid / per, e = gid % per;
    size_t base = (size_t)bh * NCH * per + e;
    float run = 0.f;
    #pragma unroll 4
    for (int c = 0; c < NCH; c++) {
        size_t idx = base + (size_t)c * per;
        float cur = data[idx];
        data[idx] = run;
        run += cur;
    }
}

// ---------------- phase C (TF32 mma, fused scores + inter pass; natural regs) ----------------
__global__ void __launch_bounds__(256) phaseC_kernel() {
    __shared__ uint32_t A_sh[64][68];
    __shared__ uint32_t wbuf[4608];
    __shared__ uint32_t Ssb[32 * 68];
    __shared__ float zs[32];
    __shared__ float dred[4][64];
    __shared__ float den_sh[64];

    uint32_t (*qs)[36] = (uint32_t(*)[36])wbuf;
    uint32_t (*ks)[36] = (uint32_t(*)[36])(wbuf + 2304);
    uint32_t (*Vs)[68] = (uint32_t(*)[68])wbuf;
    uint32_t (*Ss)[68] = (uint32_t(*)[68])Ssb;

    const int tid = threadIdx.x;
    const int wid = tid >> 5, lane = tid & 31;
    const int g = lane >> 2, tg = lane & 3;
    const int t0 = (wid & 3) * 16;
    const int n0 = (wid >> 2) * 32;
    const int c = blockIdx.x, bh = blockIdx.y;
    const int b = bh >> 3, h = bh & 7;
    const int l0 = c * CHUNK;
    const float* qb = g_qp + ((size_t)bh * LL + l0) * MM;
    const float* kb = g_kp + ((size_t)bh * LL + l0) * MM;
    const float* zb = g_z + ((size_t)bh * NCH + c) * MM;
    const float* Sb = g_S + ((size_t)bh * NCH + c) * (MM * DHD);

    float c1[4][4], c2[4][4];
    #pragma unroll
    for (int j = 0; j < 4; j++)
        #pragma unroll
        for (int q = 0; q < 4; q++) { c1[j][q] = 0.f; c2[j][q] = 0.f; }
    float dq = 0.f;
    const int dt = tid & 63, dslice = tid >> 6;

    for (int m0 = 0; m0 < 272; m0 += 32) {
        #pragma unroll 4
        for (int idx = tid; idx < 64 * 16; idx += 256) {
            int t = idx >> 4, m2 = (idx & 15) * 2;
            int m = m0 + m2;
            float2 qv = make_float2(0.f, 0.f), kv = make_float2(0.f, 0.f);
            if (m < MM) {
                qv = *(const float2*)&qb[(size_t)t * MM + m];
                kv = *(const float2*)&kb[(size_t)t * MM + m];
            }
            qs[t][m2] = f2tf(qv.x); qs[t][m2 + 1] = f2tf(qv.y);
            ks[t][m2] = f2tf(kv.x); ks[t][m2 + 1] = f2tf(kv.y);
        }
        #pragma unroll 2
        for (int idx = tid; idx < 32 * 16; idx += 256) {
            int mm = idx >> 4, d4 = (idx & 15) * 4;
            int m = m0 + mm;
            float4 sv4 = make_float4(0.f, 0.f, 0.f, 0.f);
            if (m < MM) sv4 = *(const float4*)&Sb[(size_t)m * DHD + d4];
            Ss[mm][d4]     = f2tf(sv4.x);
            Ss[mm][d4 + 1] = f2tf(sv4.y);
            Ss[mm][d4 + 2] = f2tf(sv4.z);
            Ss[mm][d4 + 3] = f2tf(sv4.w);
        }
        if (tid < 32) zs[tid] = (m0 + tid < MM) ? zb[m0 + tid] : 0.f;
        __syncthreads();
        #pragma unroll
        for (int i = 0; i < 8; i++) {
            int mm = dslice * 8 + i;
            dq += __uint_as_float(qs[dt][mm]) * zs[mm];
        }
        #pragma unroll
        for (int k8 = 0; k8 < 32; k8 += 8) {
            uint32_t a[4];
            a[0] = qs[t0 + g][k8 + tg];
            a[1] = qs[t0 + g + 8][k8 + tg];
            a[2] = qs[t0 + g][k8 + tg + 4];
            a[3] = qs[t0 + g + 8][k8 + tg + 4];
            #pragma unroll
            for (int j = 0; j < 4; j++) {
                uint32_t b0 = ks[n0 + j * 8 + g][k8 + tg];
                uint32_t b1 = ks[n0 + j * 8 + g][k8 + tg + 4];
                mma_tf32(c1[j], a, b0, b1);
            }
            #pragma unroll
            for (int j = 0; j < 4; j++) {
                uint32_t b0 = Ss[k8 + tg][n0 + j * 8 + g];
                uint32_t b1 = Ss[k8 + tg + 4][n0 + j * 8 + g];
                mma_tf32(c2[j], a, b0, b1);
            }
        }
        __syncthreads();
    }
    dred[dslice][dt] = dq;

    {
        int ta = t0 + g, tb2 = t0 + g + 8;
        #pragma unroll
        for (int j = 0; j < 4; j++) {
            int s = n0 + j * 8 + 2 * tg;
            A_sh[ta][s]      = f2tf((s     <= ta)  ? c1[j][0] : 0.f);
            A_sh[ta][s + 1]  = f2tf((s + 1 <= ta)  ? c1[j][1] : 0.f);
            A_sh[tb2][s]     = f2tf((s     <= tb2) ? c1[j][2] : 0.f);
            A_sh[tb2][s + 1] = f2tf((s + 1 <= tb2) ? c1[j][3] : 0.f);
        }
    }
    __syncthreads();

    if (tid < 64) {
        float r = dred[0][tid] + dred[1][tid] + dred[2][tid] + dred[3][tid];
        #pragma unroll 8
        for (int s = 0; s < 64; s++) r += __uint_as_float(A_sh[tid][s]);
        den_sh[tid] = r;
    }

    {
        int t = tid >> 2, d16 = (tid & 3) * 16;
        const float* vr = &g_V[((size_t)(b * LL + l0 + t)) * DD + h * DHD + d16];
        #pragma unroll
        for (int q = 0; q < 4; q++) {
            float4 vv = *(const float4*)&vr[q * 4];
            Vs[t][d16 + q * 4]     = f2tf(vv.x);
            Vs[t][d16 + q * 4 + 1] = f2tf(vv.y);
            Vs[t][d16 + q * 4 + 2] = f2tf(vv.z);
            Vs[t][d16 + q * 4 + 3] = f2tf(vv.w);
        }
    }
    __syncthreads();

    #pragma unroll
    for (int k8 = 0; k8 < 64; k8 += 8) {
        uint32_t a[4];
        a[0] = A_sh[t0 + g][k8 + tg];
        a[1] = A_sh[t0 + g + 8][k8 + tg];
        a[2] = A_sh[t0 + g][k8 + tg + 4];
        a[3] = A_sh[t0 + g + 8][k8 + tg + 4];
        #pragma unroll
        for (int j = 0; j < 4; j++) {
            uint32_t b0 = Vs[k8 + tg][n0 + j * 8 + g];
            uint32_t b1 = Vs[k8 + tg + 4][n0 + j * 8 + g];
            mma_tf32(c2[j], a, b0, b1);
        }
    }

    {
        int ta = t0 + g, tb2 = t0 + g + 8;
        float inva = 1.0f / den_sh[ta];
        float invb = 1.0f / den_sh[tb2];
        #pragma unroll
        for (int j = 0; j < 4; j++) {
            int d = n0 + j * 8 + 2 * tg;
            *(float2*)&g_ctx[((size_t)(b * LL + l0 + ta)) * DD + h * DHD + d] =
                make_float2(c2[j][0] * inva, c2[j][1] * inva);
            *(float2*)&g_ctx[((size_t)(b * LL + l0 + tb2)) * DD + h * DHD + d] =
                make_float2(c2[j][2] * invb, c2[j][3] * invb);
        }
    }
}

// ---------------- launch ----------------
extern "C" void kernel_launch(void* const* d_in, const int* in_sizes, int n_in,
                              void* d_out, int out_size) {
    const float* query = (const float*)d_in[0];
    const float* key   = (const float*)d_in[1];
    const float* value = (const float*)d_in[2];
    const float* Wq    = (const float*)d_in[3];
    const float* bq    = (const float*)d_in[4];
    const float* Wk    = (const float*)d_in[5];
    const float* bk    = (const float*)d_in[6];
    const float* Wv    = (const float*)d_in[7];
    const float* bv    = (const float*)d_in[8];
    const float* Wout  = (const float*)d_in[9];
    const float* bout  = (const float*)d_in[10];
    const float* RF    = (const float*)d_in[11];

    float *Qp, *Kp, *Vp, *hqp, *hkp, *qpp, *kpp, *Sp, *zp, *ctxp;
    cudaGetSymbolAddress((void**)&Qp,  g_Q);
    cudaGetSymbolAddress((void**)&Kp,  g_K);
    cudaGetSymbolAddress((void**)&Vp,  g_V);
    cudaGetSymbolAddress((void**)&hqp, g_hq);
    cudaGetSymbolAddress((void**)&hkp, g_hk);
    cudaGetSymbolAddress((void**)&qpp, g_qp);
    cudaGetSymbolAddress((void**)&kpp, g_kp);
    cudaGetSymbolAddress((void**)&Sp,  g_S);
    cudaGetSymbolAddress((void**)&zp,  g_z);
    cudaGetSymbolAddress((void**)&ctxp, g_ctx);

    dim3 gp(DD / 128, NROWS / 128, 3);
    tf32_gemm<<<gp, 256>>>(query, Wq, bq, Qp,
                           key,   Wk, bk, Kp,
                           value, Wv, bv, Vp);

    dim3 hg(NROWS, 2);
    hq_kernel<<<hg, 256>>>(Qp, Kp, hqp, hkp);

    dim3 fg((MM + 63) / 64, NROWS / 128, 2 * HH);
    feat_gemm<<<fg, 256>>>(Qp, Kp, RF, hqp, hkp, qpp, kpp);

    dim3 pg(NCH, BHT);
    phaseA_kernel<<<pg, 544>>>();

    int perS = MM * DHD;
    scan_kernel<<<(BHT * perS + 255) / 256, 256>>>(Sp, perS);
    scan_kernel<<<(BHT * MM + 255) / 256, 256>>>(zp, MM);

    phaseC_kernel<<<pg, 256>>>();

    dim3 go(DD / 128, NROWS / 128, 1);
    tf32_gemm<<<go, 256>>>(ctxp, Wout, bout, (float*)d_out,
                           ctxp, Wout, bout, (float*)d_out,
                           ctxp, Wout, bout, (float*)d_out);
}

// round 12
// speedup vs baseline: 1.1933x; 1.0876x over previous
#include <cuda_runtime.h>
#include <math.h>
#include <stdint.h>

// ---------------- problem constants ----------------
#define BB    2
#define LL    4096
#define DD    512
#define HH    8
#define DHD   64
#define MM    266
#define NROWS (BB*LL)        // 8192
#define CHUNK 64
#define NCH   (LL/CHUNK)     // 64
#define BHT   (BB*HH)        // 16

#define INV_S4      0.21022410381342863f   // 512^-0.25
#define INV_SQRT512 0.04419417382415922f   // 512^-0.5

// ---------------- scratch ----------------
__device__ float g_Q[NROWS*DD];
__device__ float g_K[NROWS*DD];
__device__ float g_V[NROWS*DD];
__device__ float g_hq[NROWS*HH];
__device__ float g_hk[NROWS*HH];
__device__ float g_qp[(size_t)BHT*LL*MM];
__device__ float g_kp[(size_t)BHT*LL*MM];
__device__ float g_S [(size_t)BHT*NCH*MM*DHD];
__device__ float g_z [(size_t)BHT*NCH*MM];
__device__ float g_ctx[NROWS*DD];

// ---------------- TF32 helpers ----------------
__device__ __forceinline__ uint32_t f2tf(float f) {
    uint32_t u;
    asm("cvt.rna.tf32.f32 %0, %1;" : "=r"(u) : "f"(f));
    return u;
}
__device__ __forceinline__ void mma_tf32(float* c, const uint32_t* a,
                                         uint32_t b0, uint32_t b1) {
    asm volatile(
        "mma.sync.aligned.m16n8k8.row.col.f32.tf32.tf32.f32 "
        "{%0,%1,%2,%3}, {%4,%5,%6,%7}, {%8,%9}, {%0,%1,%2,%3};"
        : "+f"(c[0]), "+f"(c[1]), "+f"(c[2]), "+f"(c[3])
        : "r"(a[0]), "r"(a[1]), "r"(a[2]), "r"(a[3]), "r"(b0), "r"(b1));
}

// ---------------- TF32 GEMM (unpacked smem + register-prefetch) ----------------
__global__ void __launch_bounds__(256, 2)
tf32_gemm(const float* __restrict__ A0, const float* __restrict__ W0,
          const float* __restrict__ bb0, float* __restrict__ C0,
          const float* __restrict__ A1, const float* __restrict__ W1,
          const float* __restrict__ bb1, float* __restrict__ C1,
          const float* __restrict__ A2, const float* __restrict__ W2,
          const float* __restrict__ bb2, float* __restrict__ C2) {
    __shared__ uint32_t As[128][36];
    __shared__ uint32_t Ws[128][36];

    const float* A; const float* W; const float* bias; float* C;
    if (blockIdx.z == 0)      { A = A0; W = W0; bias = bb0; C = C0; }
    else if (blockIdx.z == 1) { A = A1; W = W1; bias = bb1; C = C1; }
    else                      { A = A2; W = W2; bias = bb2; C = C2; }

    const int t = threadIdx.x;
    const int wid = t >> 5, lane = t & 31;
    const int warp_m = (wid & 3) * 32;
    const int warp_n = (wid >> 2) * 64;
    const int row0 = blockIdx.y * 128, col0 = blockIdx.x * 128;
    const int g = lane >> 2, tg = lane & 3;
    const int rl = t >> 3;
    const int ql = (t & 7) * 4;

    float c[2][8][4];
    #pragma unroll
    for (int f = 0; f < 2; f++)
        #pragma unroll
        for (int j = 0; j < 8; j++)
            #pragma unroll
            for (int q = 0; q < 4; q++) c[f][j][q] = 0.f;

    float4 aR[4], wR[4];
    #pragma unroll
    for (int i = 0; i < 4; i++) {
        aR[i] = *(const float4*)&A[(size_t)(row0 + rl + i * 32) * DD + ql];
        wR[i] = *(const float4*)&W[(size_t)(col0 + rl + i * 32) * DD + ql];
    }
    #pragma unroll
    for (int i = 0; i < 4; i++) {
        *(uint4*)&As[rl + i * 32][ql] =
            make_uint4(f2tf(aR[i].x), f2tf(aR[i].y), f2tf(aR[i].z), f2tf(aR[i].w));
        *(uint4*)&Ws[rl + i * 32][ql] =
            make_uint4(f2tf(wR[i].x), f2tf(wR[i].y), f2tf(wR[i].z), f2tf(wR[i].w));
    }
    __syncthreads();

    for (int kt = 0; kt < DD / 32; kt++) {
        if (kt < DD / 32 - 1) {
            int ks = (kt + 1) * 32;
            #pragma unroll
            for (int i = 0; i < 4; i++) {
                aR[i] = *(const float4*)&A[(size_t)(row0 + rl + i * 32) * DD + ks + ql];
                wR[i] = *(const float4*)&W[(size_t)(col0 + rl + i * 32) * DD + ks + ql];
            }
        }
        #pragma unroll
        for (int k8 = 0; k8 < 32; k8 += 8) {
            uint32_t a[2][4];
            #pragma unroll
            for (int f = 0; f < 2; f++) {
                int m0 = warp_m + 16 * f;
                a[f][0] = As[m0 + g][k8 + tg];
                a[f][1] = As[m0 + g + 8][k8 + tg];
                a[f][2] = As[m0 + g][k8 + tg + 4];
                a[f][3] = As[m0 + g + 8][k8 + tg + 4];
            }
            #pragma unroll
            for (int j = 0; j < 8; j++) {
                uint32_t b0 = Ws[warp_n + 8 * j + g][k8 + tg];
                uint32_t b1 = Ws[warp_n + 8 * j + g][k8 + tg + 4];
                mma_tf32(c[0][j], a[0], b0, b1);
                mma_tf32(c[1][j], a[1], b0, b1);
            }
        }
        if (kt < DD / 32 - 1) {
            __syncthreads();
            #pragma unroll
            for (int i = 0; i < 4; i++) {
                *(uint4*)&As[rl + i * 32][ql] =
                    make_uint4(f2tf(aR[i].x), f2tf(aR[i].y), f2tf(aR[i].z), f2tf(aR[i].w));
                *(uint4*)&Ws[rl + i * 32][ql] =
                    make_uint4(f2tf(wR[i].x), f2tf(wR[i].y), f2tf(wR[i].z), f2tf(wR[i].w));
            }
            __syncthreads();
        }
    }

    #pragma unroll
    for (int f = 0; f < 2; f++) {
        int r0 = row0 + warp_m + 16 * f + g;
        #pragma unroll
        for (int j = 0; j < 8; j++) {
            int cidx = col0 + warp_n + 8 * j + 2 * tg;
            float bx = bias[cidx], by = bias[cidx + 1];
            float2 o0 = make_float2(c[f][j][0] + bx, c[f][j][1] + by);
            float2 o1 = make_float2(c[f][j][2] + bx, c[f][j][3] + by);
            *(float2*)&C[(size_t)r0 * DD + cidx] = o0;
            *(float2*)&C[(size_t)(r0 + 8) * DD + cidx] = o1;
        }
    }
}

// ---------------- hq (merged Q/K) ----------------
__global__ void hq_kernel(const float* __restrict__ Xq, const float* __restrict__ Xk,
                          float* __restrict__ hq, float* __restrict__ hk) {
    int row = blockIdx.x;
    const float* X = blockIdx.y ? Xk : Xq;
    float* hout    = blockIdx.y ? hk : hq;
    int w = threadIdx.x >> 5, lane = threadIdx.x & 31;
    const float* xr = X + (size_t)row * DD + w * DHD;
    float2 v = *(const float2*)&xr[lane * 2];
    float s = v.x * v.x + v.y * v.y;
    #pragma unroll
    for (int off = 16; off; off >>= 1) s += __shfl_xor_sync(0xffffffffu, s, off);
    if (lane == 0) hout[(size_t)row * HH + w] = -0.5f * INV_SQRT512 * s;
}

// ---------------- feature map (TF32 mma, merged Q/K) ----------------
__global__ void __launch_bounds__(256) feat_gemm(const float* __restrict__ Xq,
                                                 const float* __restrict__ Xk,
                                                 const float* __restrict__ RF,
                                                 const float* __restrict__ hqv,
                                                 const float* __restrict__ hkv,
                                                 float* __restrict__ outq,
                                                 float* __restrict__ outk) {
    __shared__ uint32_t Xs[128][36];
    __shared__ uint32_t Rs[64][36];

    const int t = threadIdx.x;
    const int wid = t >> 5, lane = t & 31;
    const int g = lane >> 2, tg = lane & 3;
    const int warp_m = (wid & 3) * 32;
    const int warp_n = (wid >> 2) * 32;
    const int sel = blockIdx.z >> 3;
    const int h  = blockIdx.z & 7;
    const float* X  = sel ? Xk : Xq;
    const float* hv = sel ? hkv : hqv;
    float* outp     = sel ? outk : outq;
    const int r0 = blockIdx.y * 128;
    const int m0 = blockIdx.x * 64;
    const bool full = (m0 + 64 <= MM);

    float c[2][4][4];
    #pragma unroll
    for (int f = 0; f < 2; f++)
        #pragma unroll
        for (int j = 0; j < 4; j++)
            #pragma unroll
            for (int q = 0; q < 4; q++) c[f][j][q] = 0.f;

    for (int kc = 0; kc < DHD; kc += 32) {
        #pragma unroll
        for (int i = 0; i < 4; i++) {
            int idx = t + i * 256;
            int r = idx >> 3, q = idx & 7;
            float4 xv = *(const float4*)&X[(size_t)(r0 + r) * DD + h * DHD + kc + q * 4];
            uint4 xu = make_uint4(f2tf(xv.x * INV_S4), f2tf(xv.y * INV_S4),
                                  f2tf(xv.z * INV_S4), f2tf(xv.w * INV_S4));
            *(uint4*)&Xs[r][q * 4] = xu;
        }
        if (full) {
            #pragma unroll
            for (int i = 0; i < 2; i++) {
                int idx = t + i * 256;
                int mr = idx >> 3, q = idx & 7;
                float4 rv = *(const float4*)&RF[(size_t)(m0 + mr) * DHD + kc + q * 4];
                *(uint4*)&Rs[mr][q * 4] =
                    make_uint4(f2tf(rv.x), f2tf(rv.y), f2tf(rv.z), f2tf(rv.w));
            }
        } else {
            #pragma unroll
            for (int i = 0; i < 2; i++) {
                int idx = t + i * 256;
                int mr = idx >> 3, q = idx & 7;
                float4 rv = make_float4(0.f, 0.f, 0.f, 0.f);
                if (m0 + mr < MM) rv = *(const float4*)&RF[(size_t)(m0 + mr) * DHD + kc + q * 4];
                *(uint4*)&Rs[mr][q * 4] =
                    make_uint4(f2tf(rv.x), f2tf(rv.y), f2tf(rv.z), f2tf(rv.w));
            }
        }
        __syncthreads();
        #pragma unroll
        for (int k8 = 0; k8 < 32; k8 += 8) {
            uint32_t a[2][4];
            #pragma unroll
            for (int f = 0; f < 2; f++) {
                int mw = warp_m + 16 * f;
                a[f][0] = Xs[mw + g][k8 + tg];
                a[f][1] = Xs[mw + g + 8][k8 + tg];
                a[f][2] = Xs[mw + g][k8 + tg + 4];
                a[f][3] = Xs[mw + g + 8][k8 + tg + 4];
            }
            #pragma unroll
            for (int j = 0; j < 4; j++) {
                uint32_t b0 = Rs[warp_n + 8 * j + g][k8 + tg];
                uint32_t b1 = Rs[warp_n + 8 * j + g][k8 + tg + 4];
                mma_tf32(c[0][j], a[0], b0, b1);
                mma_tf32(c[1][j], a[1], b0, b1);
            }
        }
        __syncthreads();
    }

    #pragma unroll
    for (int f = 0; f < 2; f++) {
        int ra = r0 + warp_m + 16 * f + g;
        int rb = ra + 8;
        float ha = hv[(size_t)ra * HH + h];
        float hb = hv[(size_t)rb * HH + h];
        int ba = ra >> 12, la = ra & 4095;
        int bb = rb >> 12, lb = rb & 4095;
        size_t basea = (((size_t)(ba * HH + h)) * LL + la) * MM;
        size_t baseb = (((size_t)(bb * HH + h)) * LL + lb) * MM;
        if (full) {
            #pragma unroll
            for (int j = 0; j < 4; j++) {
                int m = m0 + warp_n + 8 * j + 2 * tg;
                *(float2*)&outp[basea + m] =
                    make_float2(__expf(c[f][j][0] + ha), __expf(c[f][j][1] + ha));
                *(float2*)&outp[baseb + m] =
                    make_float2(__expf(c[f][j][2] + hb), __expf(c[f][j][3] + hb));
            }
        } else {
            #pragma unroll
            for (int j = 0; j < 4; j++) {
                int m = m0 + warp_n + 8 * j + 2 * tg;
                if (m < MM)     outp[basea + m]     = __expf(c[f][j][0] + ha);
                if (m + 1 < MM) outp[basea + m + 1] = __expf(c[f][j][1] + ha);
                if (m < MM)     outp[baseb + m]     = __expf(c[f][j][2] + hb);
                if (m + 1 < MM) outp[baseb + m + 1] = __expf(c[f][j][3] + hb);
            }
        }
    }
}

// ---------------- phase A (TF32 mma, 17 warps, double-buffered, 2 blocks/SM) ----------------
__global__ void __launch_bounds__(544, 2) phaseA_kernel() {
    __shared__ uint32_t sk[2][16][276];
    __shared__ uint32_t sv[2][16][68];

    const int tid = threadIdx.x;
    const int wid = tid >> 5, lane = tid & 31;
    const int g = lane >> 2, tg = lane & 3;
    const int c = blockIdx.x, bh = blockIdx.y;
    const int b = bh >> 3, h = bh & 7;
    const int l0 = c * CHUNK;
    const float* kb = g_kp + ((size_t)bh * LL + l0) * MM;
    const float* vb = g_V + ((size_t)(b * LL + l0)) * DD + h * DHD;
    const int m0 = wid * 16;

    float acc[8][4];
    #pragma unroll
    for (int j = 0; j < 8; j++)
        #pragma unroll
        for (int q = 0; q < 4; q++) acc[j][q] = 0.f;
    float zacc = 0.f;

    const int svt = tid >> 4, svd = (tid & 15) * 4;

    #pragma unroll
    for (int idx = tid; idx < 16 * 136; idx += 544) {
        int t = idx / 136, m2 = (idx % 136) * 2;
        float2 kv = make_float2(0.f, 0.f);
        if (m2 < MM) kv = *(const float2*)&kb[(size_t)t * MM + m2];
        sk[0][t][m2]     = f2tf(kv.x);
        sk[0][t][m2 + 1] = f2tf(kv.y);
    }
    if (tid < 256) {
        float4 vv = *(const float4*)&vb[(size_t)svt * DD + svd];
        sv[0][svt][svd]     = f2tf(vv.x);
        sv[0][svt][svd + 1] = f2tf(vv.y);
        sv[0][svt][svd + 2] = f2tf(vv.z);
        sv[0][svt][svd + 3] = f2tf(vv.w);
    }
    __syncthreads();

    int buf = 0;
    #pragma unroll
    for (int it = 0; it < 4; it++) {
        if (it < 3) {
            int t0 = (it + 1) * 16;
            #pragma unroll
            for (int idx = tid; idx < 16 * 136; idx += 544) {
                int t = idx / 136, m2 = (idx % 136) * 2;
                float2 kv = make_float2(0.f, 0.f);
                if (m2 < MM) kv = *(const float2*)&kb[(size_t)(t0 + t) * MM + m2];
                sk[buf ^ 1][t][m2]     = f2tf(kv.x);
                sk[buf ^ 1][t][m2 + 1] = f2tf(kv.y);
            }
            if (tid < 256) {
                float4 vv = *(const float4*)&vb[(size_t)(t0 + svt) * DD + svd];
                sv[buf ^ 1][svt][svd]     = f2tf(vv.x);
                sv[buf ^ 1][svt][svd + 1] = f2tf(vv.y);
                sv[buf ^ 1][svt][svd + 2] = f2tf(vv.z);
                sv[buf ^ 1][svt][svd + 3] = f2tf(vv.w);
            }
        }
        if (tid < 272) {
            #pragma unroll
            for (int t = 0; t < 16; t++) zacc += __uint_as_float(sk[buf][t][tid]);
        }
        #pragma unroll
        for (int k8 = 0; k8 < 16; k8 += 8) {
            uint32_t a[4];
            a[0] = sk[buf][k8 + tg][m0 + g];
            a[1] = sk[buf][k8 + tg][m0 + g + 8];
            a[2] = sk[buf][k8 + tg + 4][m0 + g];
            a[3] = sk[buf][k8 + tg + 4][m0 + g + 8];
            #pragma unroll
            for (int j = 0; j < 8; j++) {
                uint32_t b0 = sv[buf][k8 + tg][j * 8 + g];
                uint32_t b1 = sv[buf][k8 + tg + 4][j * 8 + g];
                mma_tf32(acc[j], a, b0, b1);
            }
        }
        __syncthreads();
        buf ^= 1;
    }

    float* Sb = g_S + ((size_t)bh * NCH + c) * (MM * DHD);
    int mlo = m0 + g, mhi = m0 + g + 8;
    #pragma unroll
    for (int j = 0; j < 8; j++) {
        int d = j * 8 + 2 * tg;
        if (mlo < MM) *(float2*)&Sb[(size_t)mlo * DHD + d] =
            make_float2(acc[j][0], acc[j][1]);
        if (mhi < MM) *(float2*)&Sb[(size_t)mhi * DHD + d] =
            make_float2(acc[j][2], acc[j][3]);
    }
    if (tid < MM) g_z[((size_t)bh * NCH + c) * MM + tid] = zacc;
}

// ---------------- exclusive prefix over chunks (S and z merged) ----------------
__global__ void scan_kernel(float* dataS, float* dataZ) {
    const int perS = MM * DHD;
    const int totS = BHT * perS;
    int gid = blockIdx.x * blockDim.x + threadIdx.x;
    float* data;
    int per;
    if (gid < totS) {
        data = dataS; per = perS;
    } else {
        gid -= totS;
        if (gid >= BHT * MM) return;
        data = dataZ; per = MM;
    }
    int bh = gid / per, e = gid % per;
    size_t base = (size_t)bh * NCH * per + e;
    float run = 0.f;
    #pragma unroll 4
    for (int c = 0; c < NCH; c++) {
        size_t idx = base + (size_t)c * per;
        float cur = data[idx];
        data[idx] = run;
        run += cur;
    }
}

// ---------------- phase C (TF32 mma, fused passes, register-prefetch staging) ----------------
__global__ void __launch_bounds__(256, 2) phaseC_kernel() {
    __shared__ uint32_t A_sh[64][68];
    __shared__ uint32_t wbuf[4608];
    __shared__ uint32_t Ssb[32 * 68];
    __shared__ float zs[32];
    __shared__ float dred[4][64];
    __shared__ float den_sh[64];

    uint32_t (*qs)[36] = (uint32_t(*)[36])wbuf;
    uint32_t (*ks)[36] = (uint32_t(*)[36])(wbuf + 2304);
    uint32_t (*Vs)[68] = (uint32_t(*)[68])wbuf;
    uint32_t (*Ss)[68] = (uint32_t(*)[68])Ssb;

    const int tid = threadIdx.x;
    const int wid = tid >> 5, lane = tid & 31;
    const int g = lane >> 2, tg = lane & 3;
    const int t0 = (wid & 3) * 16;
    const int n0 = (wid >> 2) * 32;
    const int c = blockIdx.x, bh = blockIdx.y;
    const int b = bh >> 3, h = bh & 7;
    const int l0 = c * CHUNK;
    const float* qb = g_qp + ((size_t)bh * LL + l0) * MM;
    const float* kb = g_kp + ((size_t)bh * LL + l0) * MM;
    const float* zb = g_z + ((size_t)bh * NCH + c) * MM;
    const float* Sb = g_S + ((size_t)bh * NCH + c) * (MM * DHD);

    float c1[4][4], c2[4][4];
    #pragma unroll
    for (int j = 0; j < 4; j++)
        #pragma unroll
        for (int q = 0; q < 4; q++) { c1[j][q] = 0.f; c2[j][q] = 0.f; }
    float dq = 0.f;
    const int dt = tid & 63, dslice = tid >> 6;

    // per-thread staging coordinates
    const int sqt[4]  = { tid >> 4, (tid + 256) >> 4, (tid + 512) >> 4, (tid + 768) >> 4 };
    const int sqm[4]  = { (tid & 15) * 2, (tid & 15) * 2, (tid & 15) * 2, (tid & 15) * 2 };
    const int ssm[2]  = { tid >> 4, (tid + 256) >> 4 };
    const int ssd     = (tid & 15) * 4;

    float2 qR[4], kR[4];
    float4 sR[2];
    float zR = 0.f;

    // prefetch helper (m-tile base m0k)
    auto load_tile = [&](int m0k) {
        #pragma unroll
        for (int i = 0; i < 4; i++) {
            int m = m0k + sqm[i];
            qR[i] = make_float2(0.f, 0.f);
            kR[i] = make_float2(0.f, 0.f);
            if (m < MM) {
                qR[i] = *(const float2*)&qb[(size_t)sqt[i] * MM + m];
                kR[i] = *(const float2*)&kb[(size_t)sqt[i] * MM + m];
            }
        }
        #pragma unroll
        for (int i = 0; i < 2; i++) {
            int m = m0k + ssm[i];
            sR[i] = make_float4(0.f, 0.f, 0.f, 0.f);
            if (m < MM) sR[i] = *(const float4*)&Sb[(size_t)m * DHD + ssd];
        }
        if (tid < 32) zR = (m0k + tid < MM) ? zb[m0k + tid] : 0.f;
    };
    auto store_tile = [&]() {
        #pragma unroll
        for (int i = 0; i < 4; i++) {
            qs[sqt[i]][sqm[i]]     = f2tf(qR[i].x);
            qs[sqt[i]][sqm[i] + 1] = f2tf(qR[i].y);
            ks[sqt[i]][sqm[i]]     = f2tf(kR[i].x);
            ks[sqt[i]][sqm[i] + 1] = f2tf(kR[i].y);
        }
        #pragma unroll
        for (int i = 0; i < 2; i++) {
            Ss[ssm[i]][ssd]     = f2tf(sR[i].x);
            Ss[ssm[i]][ssd + 1] = f2tf(sR[i].y);
            Ss[ssm[i]][ssd + 2] = f2tf(sR[i].z);
            Ss[ssm[i]][ssd + 3] = f2tf(sR[i].w);
        }
        if (tid < 32) zs[tid] = zR;
    };

    load_tile(0);
    store_tile();
    __syncthreads();

    for (int mi = 0; mi < 9; mi++) {
        if (mi < 8) load_tile((mi + 1) * 32);   // LDGs overlap with mma below
        #pragma unroll
        for (int i = 0; i < 8; i++) {
            int mm = dslice * 8 + i;
            dq += __uint_as_float(qs[dt][mm]) * zs[mm];
        }
        #pragma unroll
        for (int k8 = 0; k8 < 32; k8 += 8) {
            uint32_t a[4];
            a[0] = qs[t0 + g][k8 + tg];
            a[1] = qs[t0 + g + 8][k8 + tg];
            a[2] = qs[t0 + g][k8 + tg + 4];
            a[3] = qs[t0 + g + 8][k8 + tg + 4];
            #pragma unroll
            for (int j = 0; j < 4; j++) {
                uint32_t b0 = ks[n0 + j * 8 + g][k8 + tg];
                uint32_t b1 = ks[n0 + j * 8 + g][k8 + tg + 4];
                mma_tf32(c1[j], a, b0, b1);
            }
            #pragma unroll
            for (int j = 0; j < 4; j++) {
                uint32_t b0 = Ss[k8 + tg][n0 + j * 8 + g];
                uint32_t b1 = Ss[k8 + tg + 4][n0 + j * 8 + g];
                mma_tf32(c2[j], a, b0, b1);
            }
        }
        __syncthreads();
        if (mi < 8) {
            store_tile();
            __syncthreads();
        }
    }
    dred[dslice][dt] = dq;

    {
        int ta = t0 + g, tb2 = t0 + g + 8;
        #pragma unroll
        for (int j = 0; j < 4; j++) {
            int s = n0 + j * 8 + 2 * tg;
            A_sh[ta][s]      = f2tf((s     <= ta)  ? c1[j][0] : 0.f);
            A_sh[ta][s + 1]  = f2tf((s + 1 <= ta)  ? c1[j][1] : 0.f);
            A_sh[tb2][s]     = f2tf((s     <= tb2) ? c1[j][2] : 0.f);
            A_sh[tb2][s + 1] = f2tf((s + 1 <= tb2) ? c1[j][3] : 0.f);
        }
    }
    __syncthreads();

    if (tid < 64) {
        float r = dred[0][tid] + dred[1][tid] + dred[2][tid] + dred[3][tid];
        #pragma unroll 8
        for (int s = 0; s < 64; s++) r += __uint_as_float(A_sh[tid][s]);
        den_sh[tid] = r;
    }

    {
        int t = tid >> 2, d16 = (tid & 3) * 16;
        const float* vr = &g_V[((size_t)(b * LL + l0 + t)) * DD + h * DHD + d16];
        #pragma unroll
        for (int q = 0; q < 4; q++) {
            float4 vv = *(const float4*)&vr[q * 4];
            Vs[t][d16 + q * 4]     = f2tf(vv.x);
            Vs[t][d16 + q * 4 + 1] = f2tf(vv.y);
            Vs[t][d16 + q * 4 + 2] = f2tf(vv.z);
            Vs[t][d16 + q * 4 + 3] = f2tf(vv.w);
        }
    }
    __syncthreads();

    #pragma unroll
    for (int k8 = 0; k8 < 64; k8 += 8) {
        uint32_t a[4];
        a[0] = A_sh[t0 + g][k8 + tg];
        a[1] = A_sh[t0 + g + 8][k8 + tg];
        a[2] = A_sh[t0 + g][k8 + tg + 4];
        a[3] = A_sh[t0 + g + 8][k8 + tg + 4];
        #pragma unroll
        for (int j = 0; j < 4; j++) {
            uint32_t b0 = Vs[k8 + tg][n0 + j * 8 + g];
            uint32_t b1 = Vs[k8 + tg + 4][n0 + j * 8 + g];
            mma_tf32(c2[j], a, b0, b1);
        }
    }

    {
        int ta = t0 + g, tb2 = t0 + g + 8;
        float inva = 1.0f / den_sh[ta];
        float invb = 1.0f / den_sh[tb2];
        #pragma unroll
        for (int j = 0; j < 4; j++) {
            int d = n0 + j * 8 + 2 * tg;
            *(float2*)&g_ctx[((size_t)(b * LL + l0 + ta)) * DD + h * DHD + d] =
                make_float2(c2[j][0] * inva, c2[j][1] * inva);
            *(float2*)&g_ctx[((size_t)(b * LL + l0 + tb2)) * DD + h * DHD + d] =
                make_float2(c2[j][2] * invb, c2[j][3] * invb);
        }
    }
}

// ---------------- launch ----------------
extern "C" void kernel_launch(void* const* d_in, const int* in_sizes, int n_in,
                              void* d_out, int out_size) {
    const float* query = (const float*)d_in[0];
    const float* key   = (const float*)d_in[1];
    const float* value = (const float*)d_in[2];
    const float* Wq    = (const float*)d_in[3];
    const float* bq    = (const float*)d_in[4];
    const float* Wk    = (const float*)d_in[5];
    const float* bk    = (const float*)d_in[6];
    const float* Wv    = (const float*)d_in[7];
    const float* bv    = (const float*)d_in[8];
    const float* Wout  = (const float*)d_in[9];
    const float* bout  = (const float*)d_in[10];
    const float* RF    = (const float*)d_in[11];

    float *Qp, *Kp, *Vp, *hqp, *hkp, *qpp, *kpp, *Sp, *zp, *ctxp;
    cudaGetSymbolAddress((void**)&Qp,  g_Q);
    cudaGetSymbolAddress((void**)&Kp,  g_K);
    cudaGetSymbolAddress((void**)&Vp,  g_V);
    cudaGetSymbolAddress((void**)&hqp, g_hq);
    cudaGetSymbolAddress((void**)&hkp, g_hk);
    cudaGetSymbolAddress((void**)&qpp, g_qp);
    cudaGetSymbolAddress((void**)&kpp, g_kp);
    cudaGetSymbolAddress((void**)&Sp,  g_S);
    cudaGetSymbolAddress((void**)&zp,  g_z);
    cudaGetSymbolAddress((void**)&ctxp, g_ctx);

    dim3 gp(DD / 128, NROWS / 128, 3);
    tf32_gemm<<<gp, 256>>>(query, Wq, bq, Qp,
                           key,   Wk, bk, Kp,
                           value, Wv, bv, Vp);

    dim3 hg(NROWS, 2);
    hq_kernel<<<hg, 256>>>(Qp, Kp, hqp, hkp);

    dim3 fg((MM + 63) / 64, NROWS / 128, 2 * HH);
    feat_gemm<<<fg, 256>>>(Qp, Kp, RF, hqp, hkp, qpp, kpp);

    dim3 pg(NCH, BHT);
    phaseA_kernel<<<pg, 544>>>();

    int tot = BHT * (MM * DHD + MM);
    scan_kernel<<<(tot + 255) / 256, 256>>>(Sp, zp);

    phaseC_kernel<<<pg, 256>>>();

    dim3 go(DD / 128, NROWS / 128, 1);
    tf32_gemm<<<go, 256>>>(ctxp, Wout, bout, (float*)d_out,
                           ctxp, Wout, bout, (float*)d_out,
                           ctxp, Wout, bout, (float*)d_out);
}

// round 13
// speedup vs baseline: 1.1961x; 1.0024x over previous
#include <cuda_runtime.h>
#include <math.h>
#include <stdint.h>

// ---------------- problem constants ----------------
#define BB    2
#define LL    4096
#define DD    512
#define HH    8
#define DHD   64
#define MM    266
#define NROWS (BB*LL)        // 8192
#define CHUNK 64
#define NCH   (LL/CHUNK)     // 64
#define BHT   (BB*HH)        // 16

#define INV_S4      0.21022410381342863f   // 512^-0.25
#define INV_SQRT512 0.04419417382415922f   // 512^-0.5

// ---------------- scratch ----------------
__device__ float g_Q[NROWS*DD];
__device__ float g_K[NROWS*DD];
__device__ float g_V[NROWS*DD];
__device__ float g_hq[NROWS*HH];
__device__ float g_hk[NROWS*HH];
__device__ float g_qp[(size_t)BHT*LL*MM];   // stored pre-rounded to tf32
__device__ float g_kp[(size_t)BHT*LL*MM];   // stored pre-rounded to tf32
__device__ float g_S [(size_t)BHT*NCH*MM*DHD];
__device__ float g_z [(size_t)BHT*NCH*MM];
__device__ float g_ctx[NROWS*DD];

// ---------------- TF32 helpers ----------------
__device__ __forceinline__ uint32_t f2tf(float f) {
    uint32_t u;
    asm("cvt.rna.tf32.f32 %0, %1;" : "=r"(u) : "f"(f));
    return u;
}
__device__ __forceinline__ void mma_tf32(float* c, const uint32_t* a,
                                         uint32_t b0, uint32_t b1) {
    asm volatile(
        "mma.sync.aligned.m16n8k8.row.col.f32.tf32.tf32.f32 "
        "{%0,%1,%2,%3}, {%4,%5,%6,%7}, {%8,%9}, {%0,%1,%2,%3};"
        : "+f"(c[0]), "+f"(c[1]), "+f"(c[2]), "+f"(c[3])
        : "r"(a[0]), "r"(a[1]), "r"(a[2]), "r"(a[3]), "r"(b0), "r"(b1));
}

// ---------------- TF32 GEMM (unpacked smem + register-prefetch) ----------------
__global__ void __launch_bounds__(256, 2)
tf32_gemm(const float* __restrict__ A0, const float* __restrict__ W0,
          const float* __restrict__ bb0, float* __restrict__ C0,
          const float* __restrict__ A1, const float* __restrict__ W1,
          const float* __restrict__ bb1, float* __restrict__ C1,
          const float* __restrict__ A2, const float* __restrict__ W2,
          const float* __restrict__ bb2, float* __restrict__ C2) {
    __shared__ uint32_t As[128][36];
    __shared__ uint32_t Ws[128][36];

    const float* A; const float* W; const float* bias; float* C;
    if (blockIdx.z == 0)      { A = A0; W = W0; bias = bb0; C = C0; }
    else if (blockIdx.z == 1) { A = A1; W = W1; bias = bb1; C = C1; }
    else                      { A = A2; W = W2; bias = bb2; C = C2; }

    const int t = threadIdx.x;
    const int wid = t >> 5, lane = t & 31;
    const int warp_m = (wid & 3) * 32;
    const int warp_n = (wid >> 2) * 64;
    const int row0 = blockIdx.y * 128, col0 = blockIdx.x * 128;
    const int g = lane >> 2, tg = lane & 3;
    const int rl = t >> 3;
    const int ql = (t & 7) * 4;

    float c[2][8][4];
    #pragma unroll
    for (int f = 0; f < 2; f++)
        #pragma unroll
        for (int j = 0; j < 8; j++)
            #pragma unroll
            for (int q = 0; q < 4; q++) c[f][j][q] = 0.f;

    float4 aR[4], wR[4];
    #pragma unroll
    for (int i = 0; i < 4; i++) {
        aR[i] = *(const float4*)&A[(size_t)(row0 + rl + i * 32) * DD + ql];
        wR[i] = *(const float4*)&W[(size_t)(col0 + rl + i * 32) * DD + ql];
    }
    #pragma unroll
    for (int i = 0; i < 4; i++) {
        *(uint4*)&As[rl + i * 32][ql] =
            make_uint4(f2tf(aR[i].x), f2tf(aR[i].y), f2tf(aR[i].z), f2tf(aR[i].w));
        *(uint4*)&Ws[rl + i * 32][ql] =
            make_uint4(f2tf(wR[i].x), f2tf(wR[i].y), f2tf(wR[i].z), f2tf(wR[i].w));
    }
    __syncthreads();

    for (int kt = 0; kt < DD / 32; kt++) {
        if (kt < DD / 32 - 1) {
            int ks = (kt + 1) * 32;
            #pragma unroll
            for (int i = 0; i < 4; i++) {
                aR[i] = *(const float4*)&A[(size_t)(row0 + rl + i * 32) * DD + ks + ql];
                wR[i] = *(const float4*)&W[(size_t)(col0 + rl + i * 32) * DD + ks + ql];
            }
        }
        #pragma unroll
        for (int k8 = 0; k8 < 32; k8 += 8) {
            uint32_t a[2][4];
            #pragma unroll
            for (int f = 0; f < 2; f++) {
                int m0 = warp_m + 16 * f;
                a[f][0] = As[m0 + g][k8 + tg];
                a[f][1] = As[m0 + g + 8][k8 + tg];
                a[f][2] = As[m0 + g][k8 + tg + 4];
                a[f][3] = As[m0 + g + 8][k8 + tg + 4];
            }
            #pragma unroll
            for (int j = 0; j < 8; j++) {
                uint32_t b0 = Ws[warp_n + 8 * j + g][k8 + tg];
                uint32_t b1 = Ws[warp_n + 8 * j + g][k8 + tg + 4];
                mma_tf32(c[0][j], a[0], b0, b1);
                mma_tf32(c[1][j], a[1], b0, b1);
            }
        }
        if (kt < DD / 32 - 1) {
            __syncthreads();
            #pragma unroll
            for (int i = 0; i < 4; i++) {
                *(uint4*)&As[rl + i * 32][ql] =
                    make_uint4(f2tf(aR[i].x), f2tf(aR[i].y), f2tf(aR[i].z), f2tf(aR[i].w));
                *(uint4*)&Ws[rl + i * 32][ql] =
                    make_uint4(f2tf(wR[i].x), f2tf(wR[i].y), f2tf(wR[i].z), f2tf(wR[i].w));
            }
            __syncthreads();
        }
    }

    #pragma unroll
    for (int f = 0; f < 2; f++) {
        int r0 = row0 + warp_m + 16 * f + g;
        #pragma unroll
        for (int j = 0; j < 8; j++) {
            int cidx = col0 + warp_n + 8 * j + 2 * tg;
            float bx = bias[cidx], by = bias[cidx + 1];
            float2 o0 = make_float2(c[f][j][0] + bx, c[f][j][1] + by);
            float2 o1 = make_float2(c[f][j][2] + bx, c[f][j][3] + by);
            *(float2*)&C[(size_t)r0 * DD + cidx] = o0;
            *(float2*)&C[(size_t)(r0 + 8) * DD + cidx] = o1;
        }
    }
}

// ---------------- hq (merged Q/K) ----------------
__global__ void hq_kernel(const float* __restrict__ Xq, const float* __restrict__ Xk,
                          float* __restrict__ hq, float* __restrict__ hk) {
    int row = blockIdx.x;
    const float* X = blockIdx.y ? Xk : Xq;
    float* hout    = blockIdx.y ? hk : hq;
    int w = threadIdx.x >> 5, lane = threadIdx.x & 31;
    const float* xr = X + (size_t)row * DD + w * DHD;
    float2 v = *(const float2*)&xr[lane * 2];
    float s = v.x * v.x + v.y * v.y;
    #pragma unroll
    for (int off = 16; off; off >>= 1) s += __shfl_xor_sync(0xffffffffu, s, off);
    if (lane == 0) hout[(size_t)row * HH + w] = -0.5f * INV_SQRT512 * s;
}

// ---------------- feature map (TF32 mma; outputs pre-rounded tf32; prefetch) ----------------
__global__ void __launch_bounds__(256) feat_gemm(const float* __restrict__ Xq,
                                                 const float* __restrict__ Xk,
                                                 const float* __restrict__ RF,
                                                 const float* __restrict__ hqv,
                                                 const float* __restrict__ hkv,
                                                 float* __restrict__ outq,
                                                 float* __restrict__ outk) {
    __shared__ uint32_t Xs[128][36];
    __shared__ uint32_t Rs[64][36];

    const int t = threadIdx.x;
    const int wid = t >> 5, lane = t & 31;
    const int g = lane >> 2, tg = lane & 3;
    const int warp_m = (wid & 3) * 32;
    const int warp_n = (wid >> 2) * 32;
    const int sel = blockIdx.z >> 3;
    const int h  = blockIdx.z & 7;
    const float* X  = sel ? Xk : Xq;
    const float* hv = sel ? hkv : hqv;
    float* outp     = sel ? outk : outq;
    const int r0 = blockIdx.y * 128;
    const int m0 = blockIdx.x * 64;
    const bool full = (m0 + 64 <= MM);

    const int xr = t >> 1, xq2 = (t & 1) * 16;       // X row, k offset base (two float4)
    const int rr = t >> 2, rq = (t & 3) * 8;         // RF row, k offset base (two float4)

    float c[2][4][4];
    #pragma unroll
    for (int f = 0; f < 2; f++)
        #pragma unroll
        for (int j = 0; j < 4; j++)
            #pragma unroll
            for (int q = 0; q < 4; q++) c[f][j][q] = 0.f;

    // register staging for one 32-k chunk: X 4×float4 (128 rows), RF 2×float4 (64 rows)
    float4 xRg[4], rRg[2];
    auto load_chunk = [&](int kc) {
        #pragma unroll
        for (int i = 0; i < 4; i++) {
            int idx = t + i * 256;
            int r = idx >> 3, q = (idx & 7) * 4;
            xRg[i] = *(const float4*)&X[(size_t)(r0 + r) * DD + h * DHD + kc + q];
        }
        #pragma unroll
        for (int i = 0; i < 2; i++) {
            int idx = t + i * 256;
            int mr = idx >> 3, q = (idx & 7) * 4;
            rRg[i] = make_float4(0.f, 0.f, 0.f, 0.f);
            if (full || m0 + mr < MM)
                rRg[i] = *(const float4*)&RF[(size_t)(m0 + mr) * DHD + kc + q];
        }
    };
    auto store_chunk = [&]() {
        #pragma unroll
        for (int i = 0; i < 4; i++) {
            int idx = t + i * 256;
            int r = idx >> 3, q = (idx & 7) * 4;
            *(uint4*)&Xs[r][q] =
                make_uint4(f2tf(xRg[i].x * INV_S4), f2tf(xRg[i].y * INV_S4),
                           f2tf(xRg[i].z * INV_S4), f2tf(xRg[i].w * INV_S4));
        }
        #pragma unroll
        for (int i = 0; i < 2; i++) {
            int idx = t + i * 256;
            int mr = idx >> 3, q = (idx & 7) * 4;
            *(uint4*)&Rs[mr][q] =
                make_uint4(f2tf(rRg[i].x), f2tf(rRg[i].y), f2tf(rRg[i].z), f2tf(rRg[i].w));
        }
    };

    load_chunk(0);
    store_chunk();
    __syncthreads();

    for (int it = 0; it < 2; it++) {
        if (it == 0) load_chunk(32);     // prefetch chunk 1 during chunk 0 mma
        #pragma unroll
        for (int k8 = 0; k8 < 32; k8 += 8) {
            uint32_t a[2][4];
            #pragma unroll
            for (int f = 0; f < 2; f++) {
                int mw = warp_m + 16 * f;
                a[f][0] = Xs[mw + g][k8 + tg];
                a[f][1] = Xs[mw + g + 8][k8 + tg];
                a[f][2] = Xs[mw + g][k8 + tg + 4];
                a[f][3] = Xs[mw + g + 8][k8 + tg + 4];
            }
            #pragma unroll
            for (int j = 0; j < 4; j++) {
                uint32_t b0 = Rs[warp_n + 8 * j + g][k8 + tg];
                uint32_t b1 = Rs[warp_n + 8 * j + g][k8 + tg + 4];
                mma_tf32(c[0][j], a[0], b0, b1);
                mma_tf32(c[1][j], a[1], b0, b1);
            }
        }
        if (it == 0) {
            __syncthreads();
            store_chunk();
            __syncthreads();
        }
    }

    // epilogue: exp(acc + h), pre-rounded to tf32 before store
    #pragma unroll
    for (int f = 0; f < 2; f++) {
        int ra = r0 + warp_m + 16 * f + g;
        int rb = ra + 8;
        float ha = hv[(size_t)ra * HH + h];
        float hb = hv[(size_t)rb * HH + h];
        int ba = ra >> 12, la = ra & 4095;
        int bb = rb >> 12, lb = rb & 4095;
        size_t basea = (((size_t)(ba * HH + h)) * LL + la) * MM;
        size_t baseb = (((size_t)(bb * HH + h)) * LL + lb) * MM;
        if (full) {
            #pragma unroll
            for (int j = 0; j < 4; j++) {
                int m = m0 + warp_n + 8 * j + 2 * tg;
                *(float2*)&outp[basea + m] = make_float2(
                    __uint_as_float(f2tf(__expf(c[f][j][0] + ha))),
                    __uint_as_float(f2tf(__expf(c[f][j][1] + ha))));
                *(float2*)&outp[baseb + m] = make_float2(
                    __uint_as_float(f2tf(__expf(c[f][j][2] + hb))),
                    __uint_as_float(f2tf(__expf(c[f][j][3] + hb))));
            }
        } else {
            #pragma unroll
            for (int j = 0; j < 4; j++) {
                int m = m0 + warp_n + 8 * j + 2 * tg;
                if (m < MM)     outp[basea + m]     = __uint_as_float(f2tf(__expf(c[f][j][0] + ha)));
                if (m + 1 < MM) outp[basea + m + 1] = __uint_as_float(f2tf(__expf(c[f][j][1] + ha)));
                if (m < MM)     outp[baseb + m]     = __uint_as_float(f2tf(__expf(c[f][j][2] + hb)));
                if (m + 1 < MM) outp[baseb + m + 1] = __uint_as_float(f2tf(__expf(c[f][j][3] + hb)));
            }
        }
    }
}

// ---------------- phase A (TF32 mma; kp already tf32 — bit-copy staging) ----------------
__global__ void __launch_bounds__(544, 2) phaseA_kernel() {
    __shared__ uint32_t sk[2][16][276];
    __shared__ uint32_t sv[2][16][68];

    const int tid = threadIdx.x;
    const int wid = tid >> 5, lane = tid & 31;
    const int g = lane >> 2, tg = lane & 3;
    const int c = blockIdx.x, bh = blockIdx.y;
    const int b = bh >> 3, h = bh & 7;
    const int l0 = c * CHUNK;
    const float* kb = g_kp + ((size_t)bh * LL + l0) * MM;
    const float* vb = g_V + ((size_t)(b * LL + l0)) * DD + h * DHD;
    const int m0 = wid * 16;

    float acc[8][4];
    #pragma unroll
    for (int j = 0; j < 8; j++)
        #pragma unroll
        for (int q = 0; q < 4; q++) acc[j][q] = 0.f;
    float zacc = 0.f;

    const int svt = tid >> 4, svd = (tid & 15) * 4;

    #pragma unroll
    for (int idx = tid; idx < 16 * 136; idx += 544) {
        int t = idx / 136, m2 = (idx % 136) * 2;
        float2 kv = make_float2(0.f, 0.f);
        if (m2 < MM) kv = *(const float2*)&kb[(size_t)t * MM + m2];
        sk[0][t][m2]     = __float_as_uint(kv.x);
        sk[0][t][m2 + 1] = __float_as_uint(kv.y);
    }
    if (tid < 256) {
        float4 vv = *(const float4*)&vb[(size_t)svt * DD + svd];
        sv[0][svt][svd]     = f2tf(vv.x);
        sv[0][svt][svd + 1] = f2tf(vv.y);
        sv[0][svt][svd + 2] = f2tf(vv.z);
        sv[0][svt][svd + 3] = f2tf(vv.w);
    }
    __syncthreads();

    int buf = 0;
    #pragma unroll
    for (int it = 0; it < 4; it++) {
        if (it < 3) {
            int t0 = (it + 1) * 16;
            #pragma unroll
            for (int idx = tid; idx < 16 * 136; idx += 544) {
                int t = idx / 136, m2 = (idx % 136) * 2;
                float2 kv = make_float2(0.f, 0.f);
                if (m2 < MM) kv = *(const float2*)&kb[(size_t)(t0 + t) * MM + m2];
                sk[buf ^ 1][t][m2]     = __float_as_uint(kv.x);
                sk[buf ^ 1][t][m2 + 1] = __float_as_uint(kv.y);
            }
            if (tid < 256) {
                float4 vv = *(const float4*)&vb[(size_t)(t0 + svt) * DD + svd];
                sv[buf ^ 1][svt][svd]     = f2tf(vv.x);
                sv[buf ^ 1][svt][svd + 1] = f2tf(vv.y);
                sv[buf ^ 1][svt][svd + 2] = f2tf(vv.z);
                sv[buf ^ 1][svt][svd + 3] = f2tf(vv.w);
            }
        }
        if (tid < 272) {
            #pragma unroll
            for (int t = 0; t < 16; t++) zacc += __uint_as_float(sk[buf][t][tid]);
        }
        #pragma unroll
        for (int k8 = 0; k8 < 16; k8 += 8) {
            uint32_t a[4];
            a[0] = sk[buf][k8 + tg][m0 + g];
            a[1] = sk[buf][k8 + tg][m0 + g + 8];
            a[2] = sk[buf][k8 + tg + 4][m0 + g];
            a[3] = sk[buf][k8 + tg + 4][m0 + g + 8];
            #pragma unroll
            for (int j = 0; j < 8; j++) {
                uint32_t b0 = sv[buf][k8 + tg][j * 8 + g];
                uint32_t b1 = sv[buf][k8 + tg + 4][j * 8 + g];
                mma_tf32(acc[j], a, b0, b1);
            }
        }
        __syncthreads();
        buf ^= 1;
    }

    float* Sb = g_S + ((size_t)bh * NCH + c) * (MM * DHD);
    int mlo = m0 + g, mhi = m0 + g + 8;
    #pragma unroll
    for (int j = 0; j < 8; j++) {
        int d = j * 8 + 2 * tg;
        if (mlo < MM) *(float2*)&Sb[(size_t)mlo * DHD + d] =
            make_float2(acc[j][0], acc[j][1]);
        if (mhi < MM) *(float2*)&Sb[(size_t)mhi * DHD + d] =
            make_float2(acc[j][2], acc[j][3]);
    }
    if (tid < MM) g_z[((size_t)bh * NCH + c) * MM + tid] = zacc;
}

// ---------------- exclusive prefix over chunks (S and z merged) ----------------
__global__ void scan_kernel(float* dataS, float* dataZ) {
    const int perS = MM * DHD;
    const int totS = BHT * perS;
    int gid = blockIdx.x * blockDim.x + threadIdx.x;
    float* data;
    int per;
    if (gid < totS) {
        data = dataS; per = perS;
    } else {
        gid -= totS;
        if (gid >= BHT * MM) return;
        data = dataZ; per = MM;
    }
    int bh = gid / per, e = gid % per;
    size_t base = (size_t)bh * NCH * per + e;
    float run = 0.f;
    #pragma unroll 4
    for (int c = 0; c < NCH; c++) {
        size_t idx = base + (size_t)c * per;
        float cur = data[idx];
        data[idx] = run;
        run += cur;
    }
}

// ---------------- phase C (TF32 mma; q/k bit-copy staging; prefetch) ----------------
__global__ void __launch_bounds__(256, 2) phaseC_kernel() {
    __shared__ uint32_t A_sh[64][68];
    __shared__ uint32_t wbuf[4608];
    __shared__ uint32_t Ssb[32 * 68];
    __shared__ float zs[32];
    __shared__ float dred[4][64];
    __shared__ float den_sh[64];

    uint32_t (*qs)[36] = (uint32_t(*)[36])wbuf;
    uint32_t (*ks)[36] = (uint32_t(*)[36])(wbuf + 2304);
    uint32_t (*Vs)[68] = (uint32_t(*)[68])wbuf;
    uint32_t (*Ss)[68] = (uint32_t(*)[68])Ssb;

    const int tid = threadIdx.x;
    const int wid = tid >> 5, lane = tid & 31;
    const int g = lane >> 2, tg = lane & 3;
    const int t0 = (wid & 3) * 16;
    const int n0 = (wid >> 2) * 32;
    const int c = blockIdx.x, bh = blockIdx.y;
    const int b = bh >> 3, h = bh & 7;
    const int l0 = c * CHUNK;
    const float* qb = g_qp + ((size_t)bh * LL + l0) * MM;
    const float* kb = g_kp + ((size_t)bh * LL + l0) * MM;
    const float* zb = g_z + ((size_t)bh * NCH + c) * MM;
    const float* Sb = g_S + ((size_t)bh * NCH + c) * (MM * DHD);

    float c1[4][4], c2[4][4];
    #pragma unroll
    for (int j = 0; j < 4; j++)
        #pragma unroll
        for (int q = 0; q < 4; q++) { c1[j][q] = 0.f; c2[j][q] = 0.f; }
    float dq = 0.f;
    const int dt = tid & 63, dslice = tid >> 6;

    const int sqt[4]  = { tid >> 4, (tid + 256) >> 4, (tid + 512) >> 4, (tid + 768) >> 4 };
    const int sqmv    = (tid & 15) * 2;
    const int ssm[2]  = { tid >> 4, (tid + 256) >> 4 };
    const int ssd     = (tid & 15) * 4;

    float2 qR[4], kR[4];
    float4 sR[2];
    float zR = 0.f;

    auto load_tile = [&](int m0k) {
        #pragma unroll
        for (int i = 0; i < 4; i++) {
            int m = m0k + sqmv;
            qR[i] = make_float2(0.f, 0.f);
            kR[i] = make_float2(0.f, 0.f);
            if (m < MM) {
                qR[i] = *(const float2*)&qb[(size_t)sqt[i] * MM + m];
                kR[i] = *(const float2*)&kb[(size_t)sqt[i] * MM + m];
            }
        }
        #pragma unroll
        for (int i = 0; i < 2; i++) {
            int m = m0k + ssm[i];
            sR[i] = make_float4(0.f, 0.f, 0.f, 0.f);
            if (m < MM) sR[i] = *(const float4*)&Sb[(size_t)m * DHD + ssd];
        }
        if (tid < 32) zR = (m0k + tid < MM) ? zb[m0k + tid] : 0.f;
    };
    auto store_tile = [&]() {
        #pragma unroll
        for (int i = 0; i < 4; i++) {
            qs[sqt[i]][sqmv]     = __float_as_uint(qR[i].x);
            qs[sqt[i]][sqmv + 1] = __float_as_uint(qR[i].y);
            ks[sqt[i]][sqmv]     = __float_as_uint(kR[i].x);
            ks[sqt[i]][sqmv + 1] = __float_as_uint(kR[i].y);
        }
        #pragma unroll
        for (int i = 0; i < 2; i++) {
            Ss[ssm[i]][ssd]     = f2tf(sR[i].x);
            Ss[ssm[i]][ssd + 1] = f2tf(sR[i].y);
            Ss[ssm[i]][ssd + 2] = f2tf(sR[i].z);
            Ss[ssm[i]][ssd + 3] = f2tf(sR[i].w);
        }
        if (tid < 32) zs[tid] = zR;
    };

    load_tile(0);
    store_tile();
    __syncthreads();

    for (int mi = 0; mi < 9; mi++) {
        if (mi < 8) load_tile((mi + 1) * 32);
        #pragma unroll
        for (int i = 0; i < 8; i++) {
            int mm = dslice * 8 + i;
            dq += __uint_as_float(qs[dt][mm]) * zs[mm];
        }
        #pragma unroll
        for (int k8 = 0; k8 < 32; k8 += 8) {
            uint32_t a[4];
            a[0] = qs[t0 + g][k8 + tg];
            a[1] = qs[t0 + g + 8][k8 + tg];
            a[2] = qs[t0 + g][k8 + tg + 4];
            a[3] = qs[t0 + g + 8][k8 + tg + 4];
            #pragma unroll
            for (int j = 0; j < 4; j++) {
                uint32_t b0 = ks[n0 + j * 8 + g][k8 + tg];
                uint32_t b1 = ks[n0 + j * 8 + g][k8 + tg + 4];
                mma_tf32(c1[j], a, b0, b1);
            }
            #pragma unroll
            for (int j = 0; j < 4; j++) {
                uint32_t b0 = Ss[k8 + tg][n0 + j * 8 + g];
                uint32_t b1 = Ss[k8 + tg + 4][n0 + j * 8 + g];
                mma_tf32(c2[j], a, b0, b1);
            }
        }
        __syncthreads();
        if (mi < 8) {
            store_tile();
            __syncthreads();
        }
    }
    dred[dslice][dt] = dq;

    {
        int ta = t0 + g, tb2 = t0 + g + 8;
        #pragma unroll
        for (int j = 0; j < 4; j++) {
            int s = n0 + j * 8 + 2 * tg;
            A_sh[ta][s]      = f2tf((s     <= ta)  ? c1[j][0] : 0.f);
            A_sh[ta][s + 1]  = f2tf((s + 1 <= ta)  ? c1[j][1] : 0.f);
            A_sh[tb2][s]     = f2tf((s     <= tb2) ? c1[j][2] : 0.f);
            A_sh[tb2][s + 1] = f2tf((s + 1 <= tb2) ? c1[j][3] : 0.f);
        }
    }
    __syncthreads();

    if (tid < 64) {
        float r = dred[0][tid] + dred[1][tid] + dred[2][tid] + dred[3][tid];
        #pragma unroll 8
        for (int s = 0; s < 64; s++) r += __uint_as_float(A_sh[tid][s]);
        den_sh[tid] = r;
    }

    {
        int t = tid >> 2, d16 = (tid & 3) * 16;
        const float* vr = &g_V[((size_t)(b * LL + l0 + t)) * DD + h * DHD + d16];
        #pragma unroll
        for (int q = 0; q < 4; q++) {
            float4 vv = *(const float4*)&vr[q * 4];
            Vs[t][d16 + q * 4]     = f2tf(vv.x);
            Vs[t][d16 + q * 4 + 1] = f2tf(vv.y);
            Vs[t][d16 + q * 4 + 2] = f2tf(vv.z);
            Vs[t][d16 + q * 4 + 3] = f2tf(vv.w);
        }
    }
    __syncthreads();

    #pragma unroll
    for (int k8 = 0; k8 < 64; k8 += 8) {
        uint32_t a[4];
        a[0] = A_sh[t0 + g][k8 + tg];
        a[1] = A_sh[t0 + g + 8][k8 + tg];
        a[2] = A_sh[t0 + g][k8 + tg + 4];
        a[3] = A_sh[t0 + g + 8][k8 + tg + 4];
        #pragma unroll
        for (int j = 0; j < 4; j++) {
            uint32_t b0 = Vs[k8 + tg][n0 + j * 8 + g];
            uint32_t b1 = Vs[k8 + tg + 4][n0 + j * 8 + g];
            mma_tf32(c2[j], a, b0, b1);
        }
    }

    {
        int ta = t0 + g, tb2 = t0 + g + 8;
        float inva = 1.0f / den_sh[ta];
        float invb = 1.0f / den_sh[tb2];
        #pragma unroll
        for (int j = 0; j < 4; j++) {
            int d = n0 + j * 8 + 2 * tg;
            *(float2*)&g_ctx[((size_t)(b * LL + l0 + ta)) * DD + h * DHD + d] =
                make_float2(c2[j][0] * inva, c2[j][1] * inva);
            *(float2*)&g_ctx[((size_t)(b * LL + l0 + tb2)) * DD + h * DHD + d] =
                make_float2(c2[j][2] * invb, c2[j][3] * invb);
        }
    }
}

// ---------------- launch ----------------
extern "C" void kernel_launch(void* const* d_in, const int* in_sizes, int n_in,
                              void* d_out, int out_size) {
    const float* query = (const float*)d_in[0];
    const float* key   = (const float*)d_in[1];
    const float* value = (const float*)d_in[2];
    const float* Wq    = (const float*)d_in[3];
    const float* bq    = (const float*)d_in[4];
    const float* Wk    = (const float*)d_in[5];
    const float* bk    = (const float*)d_in[6];
    const float* Wv    = (const float*)d_in[7];
    const float* bv    = (const float*)d_in[8];
    const float* Wout  = (const float*)d_in[9];
    const float* bout  = (const float*)d_in[10];
    const float* RF    = (const float*)d_in[11];

    float *Qp, *Kp, *Vp, *hqp, *hkp, *qpp, *kpp, *Sp, *zp, *ctxp;
    cudaGetSymbolAddress((void**)&Qp,  g_Q);
    cudaGetSymbolAddress((void**)&Kp,  g_K);
    cudaGetSymbolAddress((void**)&Vp,  g_V);
    cudaGetSymbolAddress((void**)&hqp, g_hq);
    cudaGetSymbolAddress((void**)&hkp, g_hk);
    cudaGetSymbolAddress((void**)&qpp, g_qp);
    cudaGetSymbolAddress((void**)&kpp, g_kp);
    cudaGetSymbolAddress((void**)&Sp,  g_S);
    cudaGetSymbolAddress((void**)&zp,  g_z);
    cudaGetSymbolAddress((void**)&ctxp, g_ctx);

    dim3 gp(DD / 128, NROWS / 128, 3);
    tf32_gemm<<<gp, 256>>>(query, Wq, bq, Qp,
                           key,   Wk, bk, Kp,
                           value, Wv, bv, Vp);

    dim3 hg(NROWS, 2);
    hq_kernel<<<hg, 256>>>(Qp, Kp, hqp, hkp);

    dim3 fg((MM + 63) / 64, NROWS / 128, 2 * HH);
    feat_gemm<<<fg, 256>>>(Qp, Kp, RF, hqp, hkp, qpp, kpp);

    dim3 pg(NCH, BHT);
    phaseA_kernel<<<pg, 544>>>();

    int tot = BHT * (MM * DHD + MM);
    scan_kernel<<<(tot + 255) / 256, 256>>>(Sp, zp);

    phaseC_kernel<<<pg, 256>>>();

    dim3 go(DD / 128, NROWS / 128, 1);
    tf32_gemm<<<go, 256>>>(ctxp, Wout, bout, (float*)d_out,
                           ctxp, Wout, bout, (float*)d_out,
                           ctxp, Wout, bout, (float*)d_out);
}

// round 15
// speedup vs baseline: 1.5821x; 1.3226x over previous
#include <cuda_runtime.h>
#include <math.h>
#include <stdint.h>

// ---------------- problem constants ----------------
#define BB    2
#define LL    4096
#define DD    512
#define HH    8
#define DHD   64
#define MM    266
#define NROWS (BB*LL)        // 8192
#define CHUNK 64
#define NCH   (LL/CHUNK)     // 64
#define BHT   (BB*HH)        // 16

#define INV_S4      0.21022410381342863f   // 512^-0.25
#define INV_SQRT512 0.04419417382415922f   // 512^-0.5

// ---------------- scratch ----------------
__device__ float g_Q[NROWS*DD];
__device__ float g_K[NROWS*DD];
__device__ float g_V[NROWS*DD];
__device__ float g_hq[NROWS*HH];
__device__ float g_hk[NROWS*HH];
__device__ float g_qp[(size_t)BHT*LL*MM];   // stored pre-rounded to tf32
__device__ float g_kp[(size_t)BHT*LL*MM];   // stored pre-rounded to tf32
__device__ float g_S [(size_t)BHT*NCH*MM*DHD];
__device__ float g_z [(size_t)BHT*NCH*MM];
__device__ float g_ctx[NROWS*DD];

// ---------------- TF32 helpers ----------------
__device__ __forceinline__ uint32_t f2tf(float f) {
    uint32_t u;
    asm("cvt.rna.tf32.f32 %0, %1;" : "=r"(u) : "f"(f));
    return u;
}
__device__ __forceinline__ void mma_tf32(float* c, const uint32_t* a,
                                         uint32_t b0, uint32_t b1) {
    asm volatile(
        "mma.sync.aligned.m16n8k8.row.col.f32.tf32.tf32.f32 "
        "{%0,%1,%2,%3}, {%4,%5,%6,%7}, {%8,%9}, {%0,%1,%2,%3};"
        : "+f"(c[0]), "+f"(c[1]), "+f"(c[2]), "+f"(c[3])
        : "r"(a[0]), "r"(a[1]), "r"(a[2]), "r"(a[3]), "r"(b0), "r"(b1));
}

// ---------------- TF32 GEMM: double-buffered dynamic smem, RNA cvt, 1 sync/kt ----------------
#define GSM_STRIDE 36
#define GSM_STAGE  (128 * GSM_STRIDE)            // one operand, one buffer (uint32)
#define GSM_BYTES  (4 * GSM_STAGE * 4)           // 2 buffers x (A+W)

__global__ void __launch_bounds__(256, 2)
tf32_gemm(const float* __restrict__ A0, const float* __restrict__ W0,
          const float* __restrict__ bb0, float* __restrict__ C0,
          const float* __restrict__ A1, const float* __restrict__ W1,
          const float* __restrict__ bb1, float* __restrict__ C1,
          const float* __restrict__ A2, const float* __restrict__ W2,
          const float* __restrict__ bb2, float* __restrict__ C2) {
    extern __shared__ uint32_t dsm[];            // [2][A 128x36 | W 128x36]

    const float* A; const float* W; const float* bias; float* C;
    if (blockIdx.z == 0)      { A = A0; W = W0; bias = bb0; C = C0; }
    else if (blockIdx.z == 1) { A = A1; W = W1; bias = bb1; C = C1; }
    else                      { A = A2; W = W2; bias = bb2; C = C2; }

    const int t = threadIdx.x;
    const int wid = t >> 5, lane = t & 31;
    const int warp_m = (wid & 3) * 32;
    const int warp_n = (wid >> 2) * 64;
    const int row0 = blockIdx.y * 128, col0 = blockIdx.x * 128;
    const int g = lane >> 2, tg = lane & 3;
    const int rl = t >> 3;
    const int ql = (t & 7) * 4;

    float c[2][8][4];
    #pragma unroll
    for (int f = 0; f < 2; f++)
        #pragma unroll
        for (int j = 0; j < 8; j++)
            #pragma unroll
            for (int q = 0; q < 4; q++) c[f][j][q] = 0.f;

    float4 aR[4], wR[4];
    auto load_regs = [&](int ks) {
        #pragma unroll
        for (int i = 0; i < 4; i++) {
            aR[i] = *(const float4*)&A[(size_t)(row0 + rl + i * 32) * DD + ks + ql];
            wR[i] = *(const float4*)&W[(size_t)(col0 + rl + i * 32) * DD + ks + ql];
        }
    };
    auto store_buf = [&](int s) {
        uint32_t* ab = dsm + s * 2 * GSM_STAGE;
        uint32_t* wb = ab + GSM_STAGE;
        #pragma unroll
        for (int i = 0; i < 4; i++) {
            int r = rl + i * 32;
            *(uint4*)&ab[r * GSM_STRIDE + ql] =
                make_uint4(f2tf(aR[i].x), f2tf(aR[i].y), f2tf(aR[i].z), f2tf(aR[i].w));
            *(uint4*)&wb[r * GSM_STRIDE + ql] =
                make_uint4(f2tf(wR[i].x), f2tf(wR[i].y), f2tf(wR[i].z), f2tf(wR[i].w));
        }
    };

    load_regs(0);
    store_buf(0);
    __syncthreads();

    int buf = 0;
    for (int kt = 0; kt < DD / 32; kt++) {
        if (kt < DD / 32 - 1) load_regs((kt + 1) * 32);

        const uint32_t (*As)[GSM_STRIDE] =
            (const uint32_t(*)[GSM_STRIDE])(dsm + buf * 2 * GSM_STAGE);
        const uint32_t (*Ws)[GSM_STRIDE] =
            (const uint32_t(*)[GSM_STRIDE])(dsm + buf * 2 * GSM_STAGE + GSM_STAGE);

        #pragma unroll
        for (int k8 = 0; k8 < 32; k8 += 8) {
            uint32_t a[2][4];
            #pragma unroll
            for (int f = 0; f < 2; f++) {
                int m0 = warp_m + 16 * f;
                a[f][0] = As[m0 + g][k8 + tg];
                a[f][1] = As[m0 + g + 8][k8 + tg];
                a[f][2] = As[m0 + g][k8 + tg + 4];
                a[f][3] = As[m0 + g + 8][k8 + tg + 4];
            }
            #pragma unroll
            for (int j = 0; j < 8; j++) {
                uint32_t b0 = Ws[warp_n + 8 * j + g][k8 + tg];
                uint32_t b1 = Ws[warp_n + 8 * j + g][k8 + tg + 4];
                mma_tf32(c[0][j], a[0], b0, b1);
                mma_tf32(c[1][j], a[1], b0, b1);
            }
        }
        if (kt < DD / 32 - 1) store_buf(buf ^ 1);   // safe: buf^1 fully consumed last iter
        __syncthreads();
        buf ^= 1;
    }

    #pragma unroll
    for (int f = 0; f < 2; f++) {
        int r0 = row0 + warp_m + 16 * f + g;
        #pragma unroll
        for (int j = 0; j < 8; j++) {
            int cidx = col0 + warp_n + 8 * j + 2 * tg;
            float bx = bias[cidx], by = bias[cidx + 1];
            float2 o0 = make_float2(c[f][j][0] + bx, c[f][j][1] + by);
            float2 o1 = make_float2(c[f][j][2] + bx, c[f][j][3] + by);
            *(float2*)&C[(size_t)r0 * DD + cidx] = o0;
            *(float2*)&C[(size_t)(r0 + 8) * DD + cidx] = o1;
        }
    }
}

// ---------------- hq (merged Q/K) ----------------
__global__ void hq_kernel(const float* __restrict__ Xq, const float* __restrict__ Xk,
                          float* __restrict__ hq, float* __restrict__ hk) {
    int row = blockIdx.x;
    const float* X = blockIdx.y ? Xk : Xq;
    float* hout    = blockIdx.y ? hk : hq;
    int w = threadIdx.x >> 5, lane = threadIdx.x & 31;
    const float* xr = X + (size_t)row * DD + w * DHD;
    float2 v = *(const float2*)&xr[lane * 2];
    float s = v.x * v.x + v.y * v.y;
    #pragma unroll
    for (int off = 16; off; off >>= 1) s += __shfl_xor_sync(0xffffffffu, s, off);
    if (lane == 0) hout[(size_t)row * HH + w] = -0.5f * INV_SQRT512 * s;
}

// ---------------- feature map (TF32 mma; outputs pre-rounded tf32; prefetch) ----------------
__global__ void __launch_bounds__(256) feat_gemm(const float* __restrict__ Xq,
                                                 const float* __restrict__ Xk,
                                                 const float* __restrict__ RF,
                                                 const float* __restrict__ hqv,
                                                 const float* __restrict__ hkv,
                                                 float* __restrict__ outq,
                                                 float* __restrict__ outk) {
    __shared__ uint32_t Xs[128][36];
    __shared__ uint32_t Rs[64][36];

    const int t = threadIdx.x;
    const int wid = t >> 5, lane = t & 31;
    const int g = lane >> 2, tg = lane & 3;
    const int warp_m = (wid & 3) * 32;
    const int warp_n = (wid >> 2) * 32;
    const int sel = blockIdx.z >> 3;
    const int h  = blockIdx.z & 7;
    const float* X  = sel ? Xk : Xq;
    const float* hv = sel ? hkv : hqv;
    float* outp     = sel ? outk : outq;
    const int r0 = blockIdx.y * 128;
    const int m0 = blockIdx.x * 64;
    const bool full = (m0 + 64 <= MM);

    float c[2][4][4];
    #pragma unroll
    for (int f = 0; f < 2; f++)
        #pragma unroll
        for (int j = 0; j < 4; j++)
            #pragma unroll
            for (int q = 0; q < 4; q++) c[f][j][q] = 0.f;

    float4 xRg[4], rRg[2];
    auto load_chunk = [&](int kc) {
        #pragma unroll
        for (int i = 0; i < 4; i++) {
            int idx = t + i * 256;
            int r = idx >> 3, q = (idx & 7) * 4;
            xRg[i] = *(const float4*)&X[(size_t)(r0 + r) * DD + h * DHD + kc + q];
        }
        #pragma unroll
        for (int i = 0; i < 2; i++) {
            int idx = t + i * 256;
            int mr = idx >> 3, q = (idx & 7) * 4;
            rRg[i] = make_float4(0.f, 0.f, 0.f, 0.f);
            if (full || m0 + mr < MM)
                rRg[i] = *(const float4*)&RF[(size_t)(m0 + mr) * DHD + kc + q];
        }
    };
    auto store_chunk = [&]() {
        #pragma unroll
        for (int i = 0; i < 4; i++) {
            int idx = t + i * 256;
            int r = idx >> 3, q = (idx & 7) * 4;
            *(uint4*)&Xs[r][q] =
                make_uint4(f2tf(xRg[i].x * INV_S4), f2tf(xRg[i].y * INV_S4),
                           f2tf(xRg[i].z * INV_S4), f2tf(xRg[i].w * INV_S4));
        }
        #pragma unroll
        for (int i = 0; i < 2; i++) {
            int idx = t + i * 256;
            int mr = idx >> 3, q = (idx & 7) * 4;
            *(uint4*)&Rs[mr][q] =
                make_uint4(f2tf(rRg[i].x), f2tf(rRg[i].y), f2tf(rRg[i].z), f2tf(rRg[i].w));
        }
    };

    load_chunk(0);
    store_chunk();
    __syncthreads();

    for (int it = 0; it < 2; it++) {
        if (it == 0) load_chunk(32);
        #pragma unroll
        for (int k8 = 0; k8 < 32; k8 += 8) {
            uint32_t a[2][4];
            #pragma unroll
            for (int f = 0; f < 2; f++) {
                int mw = warp_m + 16 * f;
                a[f][0] = Xs[mw + g][k8 + tg];
                a[f][1] = Xs[mw + g + 8][k8 + tg];
                a[f][2] = Xs[mw + g][k8 + tg + 4];
                a[f][3] = Xs[mw + g + 8][k8 + tg + 4];
            }
            #pragma unroll
            for (int j = 0; j < 4; j++) {
                uint32_t b0 = Rs[warp_n + 8 * j + g][k8 + tg];
                uint32_t b1 = Rs[warp_n + 8 * j + g][k8 + tg + 4];
                mma_tf32(c[0][j], a[0], b0, b1);
                mma_tf32(c[1][j], a[1], b0, b1);
            }
        }
        if (it == 0) {
            __syncthreads();
            store_chunk();
            __syncthreads();
        }
    }

    #pragma unroll
    for (int f = 0; f < 2; f++) {
        int ra = r0 + warp_m + 16 * f + g;
        int rb = ra + 8;
        float ha = hv[(size_t)ra * HH + h];
        float hb = hv[(size_t)rb * HH + h];
        int ba = ra >> 12, la = ra & 4095;
        int bb = rb >> 12, lb = rb & 4095;
        size_t basea = (((size_t)(ba * HH + h)) * LL + la) * MM;
        size_t baseb = (((size_t)(bb * HH + h)) * LL + lb) * MM;
        if (full) {
            #pragma unroll
            for (int j = 0; j < 4; j++) {
                int m = m0 + warp_n + 8 * j + 2 * tg;
                *(float2*)&outp[basea + m] = make_float2(
                    __uint_as_float(f2tf(__expf(c[f][j][0] + ha))),
                    __uint_as_float(f2tf(__expf(c[f][j][1] + ha))));
                *(float2*)&outp[baseb + m] = make_float2(
                    __uint_as_float(f2tf(__expf(c[f][j][2] + hb))),
                    __uint_as_float(f2tf(__expf(c[f][j][3] + hb))));
            }
        } else {
            #pragma unroll
            for (int j = 0; j < 4; j++) {
                int m = m0 + warp_n + 8 * j + 2 * tg;
                if (m < MM)     outp[basea + m]     = __uint_as_float(f2tf(__expf(c[f][j][0] + ha)));
                if (m + 1 < MM) outp[basea + m + 1] = __uint_as_float(f2tf(__expf(c[f][j][1] + ha)));
                if (m < MM)     outp[baseb + m]     = __uint_as_float(f2tf(__expf(c[f][j][2] + hb)));
                if (m + 1 < MM) outp[baseb + m + 1] = __uint_as_float(f2tf(__expf(c[f][j][3] + hb)));
            }
        }
    }
}

// ---------------- phase A (TF32 mma; kp already tf32 — bit-copy staging) ----------------
__global__ void __launch_bounds__(544, 2) phaseA_kernel() {
    __shared__ uint32_t sk[2][16][276];
    __shared__ uint32_t sv[2][16][68];

    const int tid = threadIdx.x;
    const int wid = tid >> 5, lane = tid & 31;
    const int g = lane >> 2, tg = lane & 3;
    const int c = blockIdx.x, bh = blockIdx.y;
    const int b = bh >> 3, h = bh & 7;
    const int l0 = c * CHUNK;
    const float* kb = g_kp + ((size_t)bh * LL + l0) * MM;
    const float* vb = g_V + ((size_t)(b * LL + l0)) * DD + h * DHD;
    const int m0 = wid * 16;

    float acc[8][4];
    #pragma unroll
    for (int j = 0; j < 8; j++)
        #pragma unroll
        for (int q = 0; q < 4; q++) acc[j][q] = 0.f;
    float zacc = 0.f;

    const int svt = tid >> 4, svd = (tid & 15) * 4;

    #pragma unroll
    for (int idx = tid; idx < 16 * 136; idx += 544) {
        int t = idx / 136, m2 = (idx % 136) * 2;
        float2 kv = make_float2(0.f, 0.f);
        if (m2 < MM) kv = *(const float2*)&kb[(size_t)t * MM + m2];
        sk[0][t][m2]     = __float_as_uint(kv.x);
        sk[0][t][m2 + 1] = __float_as_uint(kv.y);
    }
    if (tid < 256) {
        float4 vv = *(const float4*)&vb[(size_t)svt * DD + svd];
        sv[0][svt][svd]     = f2tf(vv.x);
        sv[0][svt][svd + 1] = f2tf(vv.y);
        sv[0][svt][svd + 2] = f2tf(vv.z);
        sv[0][svt][svd + 3] = f2tf(vv.w);
    }
    __syncthreads();

    int buf = 0;
    #pragma unroll
    for (int it = 0; it < 4; it++) {
        if (it < 3) {
            int t0 = (it + 1) * 16;
            #pragma unroll
            for (int idx = tid; idx < 16 * 136; idx += 544) {
                int t = idx / 136, m2 = (idx % 136) * 2;
                float2 kv = make_float2(0.f, 0.f);
                if (m2 < MM) kv = *(const float2*)&kb[(size_t)(t0 + t) * MM + m2];
                sk[buf ^ 1][t][m2]     = __float_as_uint(kv.x);
                sk[buf ^ 1][t][m2 + 1] = __float_as_uint(kv.y);
            }
            if (tid < 256) {
                float4 vv = *(const float4*)&vb[(size_t)(t0 + svt) * DD + svd];
                sv[buf ^ 1][svt][svd]     = f2tf(vv.x);
                sv[buf ^ 1][svt][svd + 1] = f2tf(vv.y);
                sv[buf ^ 1][svt][svd + 2] = f2tf(vv.z);
                sv[buf ^ 1][svt][svd + 3] = f2tf(vv.w);
            }
        }
        if (tid < 272) {
            #pragma unroll
            for (int t = 0; t < 16; t++) zacc += __uint_as_float(sk[buf][t][tid]);
        }
        #pragma unroll
        for (int k8 = 0; k8 < 16; k8 += 8) {
            uint32_t a[4];
            a[0] = sk[buf][k8 + tg][m0 + g];
            a[1] = sk[buf][k8 + tg][m0 + g + 8];
            a[2] = sk[buf][k8 + tg + 4][m0 + g];
            a[3] = sk[buf][k8 + tg + 4][m0 + g + 8];
            #pragma unroll
            for (int j = 0; j < 8; j++) {
                uint32_t b0 = sv[buf][k8 + tg][j * 8 + g];
                uint32_t b1 = sv[buf][k8 + tg + 4][j * 8 + g];
                mma_tf32(acc[j], a, b0, b1);
            }
        }
        __syncthreads();
        buf ^= 1;
    }

    float* Sb = g_S + ((size_t)bh * NCH + c) * (MM * DHD);
    int mlo = m0 + g, mhi = m0 + g + 8;
    #pragma unroll
    for (int j = 0; j < 8; j++) {
        int d = j * 8 + 2 * tg;
        if (mlo < MM) *(float2*)&Sb[(size_t)mlo * DHD + d] =
            make_float2(acc[j][0], acc[j][1]);
        if (mhi < MM) *(float2*)&Sb[(size_t)mhi * DHD + d] =
            make_float2(acc[j][2], acc[j][3]);
    }
    if (tid < MM) g_z[((size_t)bh * NCH + c) * MM + tid] = zacc;
}

// ---------------- exclusive prefix over chunks (S and z merged, MLP=4) ----------------
__global__ void scan_kernel(float* dataS, float* dataZ) {
    const int perS = MM * DHD;
    const int totS = BHT * perS;
    int gid = blockIdx.x * blockDim.x + threadIdx.x;
    float* data;
    int per;
    if (gid < totS) {
        data = dataS; per = perS;
    } else {
        gid -= totS;
        if (gid >= BHT * MM) return;
        data = dataZ; per = MM;
    }
    int bh = gid / per, e = gid % per;
    size_t base = (size_t)bh * NCH * per + e;
    float run = 0.f;
    for (int c = 0; c < NCH; c += 4) {
        size_t i0 = base + (size_t)c * per;
        size_t i1 = i0 + per, i2 = i1 + per, i3 = i2 + per;
        float v0 = data[i0];
        float v1 = data[i1];
        float v2 = data[i2];
        float v3 = data[i3];
        data[i0] = run; run += v0;
        data[i1] = run; run += v1;
        data[i2] = run; run += v2;
        data[i3] = run; run += v3;
    }
}

// ---------------- phase C (TF32 mma; q/k bit-copy staging; prefetch) ----------------
__global__ void __launch_bounds__(256, 2) phaseC_kernel() {
    __shared__ uint32_t A_sh[64][68];
    __shared__ uint32_t wbuf[4608];
    __shared__ uint32_t Ssb[32 * 68];
    __shared__ float zs[32];
    __shared__ float dred[4][64];
    __shared__ float den_sh[64];

    uint32_t (*qs)[36] = (uint32_t(*)[36])wbuf;
    uint32_t (*ks)[36] = (uint32_t(*)[36])(wbuf + 2304);
    uint32_t (*Vs)[68] = (uint32_t(*)[68])wbuf;
    uint32_t (*Ss)[68] = (uint32_t(*)[68])Ssb;

    const int tid = threadIdx.x;
    const int wid = tid >> 5, lane = tid & 31;
    const int g = lane >> 2, tg = lane & 3;
    const int t0 = (wid & 3) * 16;
    const int n0 = (wid >> 2) * 32;
    const int c = blockIdx.x, bh = blockIdx.y;
    const int b = bh >> 3, h = bh & 7;
    const int l0 = c * CHUNK;
    const float* qb = g_qp + ((size_t)bh * LL + l0) * MM;
    const float* kb = g_kp + ((size_t)bh * LL + l0) * MM;
    const float* zb = g_z + ((size_t)bh * NCH + c) * MM;
    const float* Sb = g_S + ((size_t)bh * NCH + c) * (MM * DHD);

    float c1[4][4], c2[4][4];
    #pragma unroll
    for (int j = 0; j < 4; j++)
        #pragma unroll
        for (int q = 0; q < 4; q++) { c1[j][q] = 0.f; c2[j][q] = 0.f; }
    float dq = 0.f;
    const int dt = tid & 63, dslice = tid >> 6;

    const int sqt[4]  = { tid >> 4, (tid + 256) >> 4, (tid + 512) >> 4, (tid + 768) >> 4 };
    const int sqmv    = (tid & 15) * 2;
    const int ssm[2]  = { tid >> 4, (tid + 256) >> 4 };
    const int ssd     = (tid & 15) * 4;

    float2 qR[4], kR[4];
    float4 sR[2];
    float zR = 0.f;

    auto load_tile = [&](int m0k) {
        #pragma unroll
        for (int i = 0; i < 4; i++) {
            int m = m0k + sqmv;
            qR[i] = make_float2(0.f, 0.f);
            kR[i] = make_float2(0.f, 0.f);
            if (m < MM) {
                qR[i] = *(const float2*)&qb[(size_t)sqt[i] * MM + m];
                kR[i] = *(const float2*)&kb[(size_t)sqt[i] * MM + m];
            }
        }
        #pragma unroll
        for (int i = 0; i < 2; i++) {
            int m = m0k + ssm[i];
            sR[i] = make_float4(0.f, 0.f, 0.f, 0.f);
            if (m < MM) sR[i] = *(const float4*)&Sb[(size_t)m * DHD + ssd];
        }
        if (tid < 32) zR = (m0k + tid < MM) ? zb[m0k + tid] : 0.f;
    };
    auto store_tile = [&]() {
        #pragma unroll
        for (int i = 0; i < 4; i++) {
            qs[sqt[i]][sqmv]     = __float_as_uint(qR[i].x);
            qs[sqt[i]][sqmv + 1] = __float_as_uint(qR[i].y);
            ks[sqt[i]][sqmv]     = __float_as_uint(kR[i].x);
            ks[sqt[i]][sqmv + 1] = __float_as_uint(kR[i].y);
        }
        #pragma unroll
        for (int i = 0; i < 2; i++) {
            Ss[ssm[i]][ssd]     = f2tf(sR[i].x);
            Ss[ssm[i]][ssd + 1] = f2tf(sR[i].y);
            Ss[ssm[i]][ssd + 2] = f2tf(sR[i].z);
            Ss[ssm[i]][ssd + 3] = f2tf(sR[i].w);
        }
        if (tid < 32) zs[tid] = zR;
    };

    load_tile(0);
    store_tile();
    __syncthreads();

    for (int mi = 0; mi < 9; mi++) {
        if (mi < 8) load_tile((mi + 1) * 32);
        #pragma unroll
        for (int i = 0; i < 8; i++) {
            int mm = dslice * 8 + i;
            dq += __uint_as_float(qs[dt][mm]) * zs[mm];
        }
        #pragma unroll
        for (int k8 = 0; k8 < 32; k8 += 8) {
            uint32_t a[4];
            a[0] = qs[t0 + g][k8 + tg];
            a[1] = qs[t0 + g + 8][k8 + tg];
            a[2] = qs[t0 + g][k8 + tg + 4];
            a[3] = qs[t0 + g + 8][k8 + tg + 4];
            #pragma unroll
            for (int j = 0; j < 4; j++) {
                uint32_t b0 = ks[n0 + j * 8 + g][k8 + tg];
                uint32_t b1 = ks[n0 + j * 8 + g][k8 + tg + 4];
                mma_tf32(c1[j], a, b0, b1);
            }
            #pragma unroll
            for (int j = 0; j < 4; j++) {
                uint32_t b0 = Ss[k8 + tg][n0 + j * 8 + g];
                uint32_t b1 = Ss[k8 + tg + 4][n0 + j * 8 + g];
                mma_tf32(c2[j], a, b0, b1);
            }
        }
        __syncthreads();
        if (mi < 8) {
            store_tile();
            __syncthreads();
        }
    }
    dred[dslice][dt] = dq;

    {
        int ta = t0 + g, tb2 = t0 + g + 8;
        #pragma unroll
        for (int j = 0; j < 4; j++) {
            int s = n0 + j * 8 + 2 * tg;
            A_sh[ta][s]      = f2tf((s     <= ta)  ? c1[j][0] : 0.f);
            A_sh[ta][s + 1]  = f2tf((s + 1 <= ta)  ? c1[j][1] : 0.f);
            A_sh[tb2][s]     = f2tf((s     <= tb2) ? c1[j][2] : 0.f);
            A_sh[tb2][s + 1] = f2tf((s + 1 <= tb2) ? c1[j][3] : 0.f);
        }
    }
    __syncthreads();

    if (tid < 64) {
        float r = dred[0][tid] + dred[1][tid] + dred[2][tid] + dred[3][tid];
        #pragma unroll 8
        for (int s = 0; s < 64; s++) r += __uint_as_float(A_sh[tid][s]);
        den_sh[tid] = r;
    }

    {
        int t = tid >> 2, d16 = (tid & 3) * 16;
        const float* vr = &g_V[((size_t)(b * LL + l0 + t)) * DD + h * DHD + d16];
        #pragma unroll
        for (int q = 0; q < 4; q++) {
            float4 vv = *(const float4*)&vr[q * 4];
            Vs[t][d16 + q * 4]     = f2tf(vv.x);
            Vs[t][d16 + q * 4 + 1] = f2tf(vv.y);
            Vs[t][d16 + q * 4 + 2] = f2tf(vv.z);
            Vs[t][d16 + q * 4 + 3] = f2tf(vv.w);
        }
    }
    __syncthreads();

    #pragma unroll
    for (int k8 = 0; k8 < 64; k8 += 8) {
        uint32_t a[4];
        a[0] = A_sh[t0 + g][k8 + tg];
        a[1] = A_sh[t0 + g + 8][k8 + tg];
        a[2] = A_sh[t0 + g][k8 + tg + 4];
        a[3] = A_sh[t0 + g + 8][k8 + tg + 4];
        #pragma unroll
        for (int j = 0; j < 4; j++) {
            uint32_t b0 = Vs[k8 + tg][n0 + j * 8 + g];
            uint32_t b1 = Vs[k8 + tg + 4][n0 + j * 8 + g];
            mma_tf32(c2[j], a, b0, b1);
        }
    }

    {
        int ta = t0 + g, tb2 = t0 + g + 8;
        float inva = 1.0f / den_sh[ta];
        float invb = 1.0f / den_sh[tb2];
        #pragma unroll
        for (int j = 0; j < 4; j++) {
            int d = n0 + j * 8 + 2 * tg;
            *(float2*)&g_ctx[((size_t)(b * LL + l0 + ta)) * DD + h * DHD + d] =
                make_float2(c2[j][0] * inva, c2[j][1] * inva);
            *(float2*)&g_ctx[((size_t)(b * LL + l0 + tb2)) * DD + h * DHD + d] =
                make_float2(c2[j][2] * invb, c2[j][3] * invb);
        }
    }
}

// ---------------- launch ----------------
extern "C" void kernel_launch(void* const* d_in, const int* in_sizes, int n_in,
                              void* d_out, int out_size) {
    const float* query = (const float*)d_in[0];
    const float* key   = (const float*)d_in[1];
    const float* value = (const float*)d_in[2];
    const float* Wq    = (const float*)d_in[3];
    const float* bq    = (const float*)d_in[4];
    const float* Wk    = (const float*)d_in[5];
    const float* bk    = (const float*)d_in[6];
    const float* Wv    = (const float*)d_in[7];
    const float* bv    = (const float*)d_in[8];
    const float* Wout  = (const float*)d_in[9];
    const float* bout  = (const float*)d_in[10];
    const float* RF    = (const float*)d_in[11];

    float *Qp, *Kp, *Vp, *hqp, *hkp, *qpp, *kpp, *Sp, *zp, *ctxp;
    cudaGetSymbolAddress((void**)&Qp,  g_Q);
    cudaGetSymbolAddress((void**)&Kp,  g_K);
    cudaGetSymbolAddress((void**)&Vp,  g_V);
    cudaGetSymbolAddress((void**)&hqp, g_hq);
    cudaGetSymbolAddress((void**)&hkp, g_hk);
    cudaGetSymbolAddress((void**)&qpp, g_qp);
    cudaGetSymbolAddress((void**)&kpp, g_kp);
    cudaGetSymbolAddress((void**)&Sp,  g_S);
    cudaGetSymbolAddress((void**)&zp,  g_z);
    cudaGetSymbolAddress((void**)&ctxp, g_ctx);

    cudaFuncSetAttribute(tf32_gemm, cudaFuncAttributeMaxDynamicSharedMemorySize, GSM_BYTES);

    dim3 gp(DD / 128, NROWS / 128, 3);
    tf32_gemm<<<gp, 256, GSM_BYTES>>>(query, Wq, bq, Qp,
                                      key,   Wk, bk, Kp,
                                      value, Wv, bv, Vp);

    dim3 hg(NROWS, 2);
    hq_kernel<<<hg, 256>>>(Qp, Kp, hqp, hkp);

    dim3 fg((MM + 63) / 64, NROWS / 128, 2 * HH);
    feat_gemm<<<fg, 256>>>(Qp, Kp, RF, hqp, hkp, qpp, kpp);

    dim3 pg(NCH, BHT);
    phaseA_kernel<<<pg, 544>>>();

    int tot = BHT * (MM * DHD + MM);
    scan_kernel<<<(tot + 255) / 256, 256>>>(Sp, zp);

    phaseC_kernel<<<pg, 256>>>();

    dim3 go(DD / 128, NROWS / 128, 1);
    tf32_gemm<<<go, 256, GSM_BYTES>>>(ctxp, Wout, bout, (float*)d_out,
                                      ctxp, Wout, bout, (float*)d_out,
                                      ctxp, Wout, bout, (float*)d_out);
}

// round 16
// speedup vs baseline: 1.6194x; 1.0236x over previous
#include <cuda_runtime.h>
#include <math.h>
#include <stdint.h>

// ---------------- problem constants ----------------
#define BB    2
#define LL    4096
#define DD    512
#define HH    8
#define DHD   64
#define MM    266
#define NROWS (BB*LL)        // 8192
#define CHUNK 64
#define NCH   (LL/CHUNK)     // 64
#define BHT   (BB*HH)        // 16

#define INV_S4      0.21022410381342863f   // 512^-0.25
#define INV_SQRT512 0.04419417382415922f   // 512^-0.5

// ---------------- scratch ----------------
__device__ float g_Q[NROWS*DD];
__device__ float g_K[NROWS*DD];
__device__ float g_V[NROWS*DD];
__device__ float g_qp[(size_t)BHT*LL*MM];   // stored pre-rounded to tf32
__device__ float g_kp[(size_t)BHT*LL*MM];   // stored pre-rounded to tf32
__device__ float g_S [(size_t)BHT*NCH*MM*DHD];
__device__ float g_z [(size_t)BHT*NCH*MM];
__device__ float g_ctx[NROWS*DD];

// ---------------- TF32 helpers ----------------
__device__ __forceinline__ uint32_t f2tf(float f) {
    uint32_t u;
    asm("cvt.rna.tf32.f32 %0, %1;" : "=r"(u) : "f"(f));
    return u;
}
__device__ __forceinline__ void mma_tf32(float* c, const uint32_t* a,
                                         uint32_t b0, uint32_t b1) {
    asm volatile(
        "mma.sync.aligned.m16n8k8.row.col.f32.tf32.tf32.f32 "
        "{%0,%1,%2,%3}, {%4,%5,%6,%7}, {%8,%9}, {%0,%1,%2,%3};"
        : "+f"(c[0]), "+f"(c[1]), "+f"(c[2]), "+f"(c[3])
        : "r"(a[0]), "r"(a[1]), "r"(a[2]), "r"(a[3]), "r"(b0), "r"(b1));
}

// ---------------- TF32 GEMM: double-buffered dynamic smem, RNA cvt, 1 sync/kt ----------------
#define GSM_STRIDE 36
#define GSM_STAGE  (128 * GSM_STRIDE)
#define GSM_BYTES  (4 * GSM_STAGE * 4)

__global__ void __launch_bounds__(256, 2)
tf32_gemm(const float* __restrict__ A0, const float* __restrict__ W0,
          const float* __restrict__ bb0, float* __restrict__ C0,
          const float* __restrict__ A1, const float* __restrict__ W1,
          const float* __restrict__ bb1, float* __restrict__ C1,
          const float* __restrict__ A2, const float* __restrict__ W2,
          const float* __restrict__ bb2, float* __restrict__ C2) {
    extern __shared__ uint32_t dsm[];

    const float* A; const float* W; const float* bias; float* C;
    if (blockIdx.z == 0)      { A = A0; W = W0; bias = bb0; C = C0; }
    else if (blockIdx.z == 1) { A = A1; W = W1; bias = bb1; C = C1; }
    else                      { A = A2; W = W2; bias = bb2; C = C2; }

    const int t = threadIdx.x;
    const int wid = t >> 5, lane = t & 31;
    const int warp_m = (wid & 3) * 32;
    const int warp_n = (wid >> 2) * 64;
    const int row0 = blockIdx.y * 128, col0 = blockIdx.x * 128;
    const int g = lane >> 2, tg = lane & 3;
    const int rl = t >> 3;
    const int ql = (t & 7) * 4;

    float c[2][8][4];
    #pragma unroll
    for (int f = 0; f < 2; f++)
        #pragma unroll
        for (int j = 0; j < 8; j++)
            #pragma unroll
            for (int q = 0; q < 4; q++) c[f][j][q] = 0.f;

    float4 aR[4], wR[4];
    auto load_regs = [&](int ks) {
        #pragma unroll
        for (int i = 0; i < 4; i++) {
            aR[i] = *(const float4*)&A[(size_t)(row0 + rl + i * 32) * DD + ks + ql];
            wR[i] = *(const float4*)&W[(size_t)(col0 + rl + i * 32) * DD + ks + ql];
        }
    };
    auto store_buf = [&](int s) {
        uint32_t* ab = dsm + s * 2 * GSM_STAGE;
        uint32_t* wb = ab + GSM_STAGE;
        #pragma unroll
        for (int i = 0; i < 4; i++) {
            int r = rl + i * 32;
            *(uint4*)&ab[r * GSM_STRIDE + ql] =
                make_uint4(f2tf(aR[i].x), f2tf(aR[i].y), f2tf(aR[i].z), f2tf(aR[i].w));
            *(uint4*)&wb[r * GSM_STRIDE + ql] =
                make_uint4(f2tf(wR[i].x), f2tf(wR[i].y), f2tf(wR[i].z), f2tf(wR[i].w));
        }
    };

    load_regs(0);
    store_buf(0);
    __syncthreads();

    int buf = 0;
    for (int kt = 0; kt < DD / 32; kt++) {
        if (kt < DD / 32 - 1) load_regs((kt + 1) * 32);

        const uint32_t (*As)[GSM_STRIDE] =
            (const uint32_t(*)[GSM_STRIDE])(dsm + buf * 2 * GSM_STAGE);
        const uint32_t (*Ws)[GSM_STRIDE] =
            (const uint32_t(*)[GSM_STRIDE])(dsm + buf * 2 * GSM_STAGE + GSM_STAGE);

        #pragma unroll
        for (int k8 = 0; k8 < 32; k8 += 8) {
            uint32_t a[2][4];
            #pragma unroll
            for (int f = 0; f < 2; f++) {
                int m0 = warp_m + 16 * f;
                a[f][0] = As[m0 + g][k8 + tg];
                a[f][1] = As[m0 + g + 8][k8 + tg];
                a[f][2] = As[m0 + g][k8 + tg + 4];
                a[f][3] = As[m0 + g + 8][k8 + tg + 4];
            }
            #pragma unroll
            for (int j = 0; j < 8; j++) {
                uint32_t b0 = Ws[warp_n + 8 * j + g][k8 + tg];
                uint32_t b1 = Ws[warp_n + 8 * j + g][k8 + tg + 4];
                mma_tf32(c[0][j], a[0], b0, b1);
                mma_tf32(c[1][j], a[1], b0, b1);
            }
        }
        if (kt < DD / 32 - 1) store_buf(buf ^ 1);
        __syncthreads();
        buf ^= 1;
    }

    #pragma unroll
    for (int f = 0; f < 2; f++) {
        int r0 = row0 + warp_m + 16 * f + g;
        #pragma unroll
        for (int j = 0; j < 8; j++) {
            int cidx = col0 + warp_n + 8 * j + 2 * tg;
            float bx = bias[cidx], by = bias[cidx + 1];
            float2 o0 = make_float2(c[f][j][0] + bx, c[f][j][1] + by);
            float2 o1 = make_float2(c[f][j][2] + bx, c[f][j][3] + by);
            *(float2*)&C[(size_t)r0 * DD + cidx] = o0;
            *(float2*)&C[(size_t)(r0 + 8) * DD + cidx] = o1;
        }
    }
}

// ---------------- feature map (TF32 mma; h-norm fused; outputs pre-rounded tf32) ----------------
__global__ void __launch_bounds__(256) feat_gemm(const float* __restrict__ Xq,
                                                 const float* __restrict__ Xk,
                                                 const float* __restrict__ RF,
                                                 float* __restrict__ outq,
                                                 float* __restrict__ outk) {
    __shared__ uint32_t Xs[128][36];
    __shared__ uint32_t Rs[64][36];
    __shared__ float hsh[128];

    const int t = threadIdx.x;
    const int wid = t >> 5, lane = t & 31;
    const int g = lane >> 2, tg = lane & 3;
    const int warp_m = (wid & 3) * 32;
    const int warp_n = (wid >> 2) * 32;
    const int sel = blockIdx.z >> 3;
    const int h  = blockIdx.z & 7;
    const float* X  = sel ? Xk : Xq;
    float* outp     = sel ? outk : outq;
    const int r0 = blockIdx.y * 128;
    const int m0 = blockIdx.x * 64;
    const bool full = (m0 + 64 <= MM);

    float c[2][4][4];
    #pragma unroll
    for (int f = 0; f < 2; f++)
        #pragma unroll
        for (int j = 0; j < 4; j++)
            #pragma unroll
            for (int q = 0; q < 4; q++) c[f][j][q] = 0.f;

    float sq[4] = {0.f, 0.f, 0.f, 0.f};   // row-norm partials (row (t>>3)+32i)

    float4 xRg[4], rRg[2];
    auto load_chunk = [&](int kc) {
        #pragma unroll
        for (int i = 0; i < 4; i++) {
            int idx = t + i * 256;
            int r = idx >> 3, q = (idx & 7) * 4;
            xRg[i] = *(const float4*)&X[(size_t)(r0 + r) * DD + h * DHD + kc + q];
        }
        #pragma unroll
        for (int i = 0; i < 2; i++) {
            int idx = t + i * 256;
            int mr = idx >> 3, q = (idx & 7) * 4;
            rRg[i] = make_float4(0.f, 0.f, 0.f, 0.f);
            if (full || m0 + mr < MM)
                rRg[i] = *(const float4*)&RF[(size_t)(m0 + mr) * DHD + kc + q];
        }
    };
    auto store_chunk = [&]() {
        #pragma unroll
        for (int i = 0; i < 4; i++) {
            int idx = t + i * 256;
            int r = idx >> 3, q = (idx & 7) * 4;
            sq[i] += xRg[i].x * xRg[i].x + xRg[i].y * xRg[i].y
                   + xRg[i].z * xRg[i].z + xRg[i].w * xRg[i].w;
            *(uint4*)&Xs[r][q] =
                make_uint4(f2tf(xRg[i].x * INV_S4), f2tf(xRg[i].y * INV_S4),
                           f2tf(xRg[i].z * INV_S4), f2tf(xRg[i].w * INV_S4));
        }
        #pragma unroll
        for (int i = 0; i < 2; i++) {
            int idx = t + i * 256;
            int mr = idx >> 3, q = (idx & 7) * 4;
            *(uint4*)&Rs[mr][q] =
                make_uint4(f2tf(rRg[i].x), f2tf(rRg[i].y), f2tf(rRg[i].z), f2tf(rRg[i].w));
        }
    };

    load_chunk(0);
    store_chunk();
    __syncthreads();

    for (int it = 0; it < 2; it++) {
        if (it == 0) load_chunk(32);
        #pragma unroll
        for (int k8 = 0; k8 < 32; k8 += 8) {
            uint32_t a[2][4];
            #pragma unroll
            for (int f = 0; f < 2; f++) {
                int mw = warp_m + 16 * f;
                a[f][0] = Xs[mw + g][k8 + tg];
                a[f][1] = Xs[mw + g + 8][k8 + tg];
                a[f][2] = Xs[mw + g][k8 + tg + 4];
                a[f][3] = Xs[mw + g + 8][k8 + tg + 4];
            }
            #pragma unroll
            for (int j = 0; j < 4; j++) {
                uint32_t b0 = Rs[warp_n + 8 * j + g][k8 + tg];
                uint32_t b1 = Rs[warp_n + 8 * j + g][k8 + tg + 4];
                mma_tf32(c[0][j], a[0], b0, b1);
                mma_tf32(c[1][j], a[1], b0, b1);
            }
        }
        if (it == 0) {
            __syncthreads();
            store_chunk();
            __syncthreads();
        }
    }

    // h-norm: reduce sq over the 8 contiguous lanes holding each row
    #pragma unroll
    for (int i = 0; i < 4; i++) {
        #pragma unroll
        for (int off = 4; off; off >>= 1)
            sq[i] += __shfl_down_sync(0xffffffffu, sq[i], off, 8);
        if ((t & 7) == 0) hsh[(t >> 3) + 32 * i] = -0.5f * INV_SQRT512 * sq[i];
    }
    __syncthreads();

    // epilogue: exp(acc + h), pre-rounded to tf32
    #pragma unroll
    for (int f = 0; f < 2; f++) {
        int lra = warp_m + 16 * f + g;
        int ra = r0 + lra;
        int rb = ra + 8;
        float ha = hsh[lra];
        float hb = hsh[lra + 8];
        int ba = ra >> 12, la = ra & 4095;
        int bb = rb >> 12, lb = rb & 4095;
        size_t basea = (((size_t)(ba * HH + h)) * LL + la) * MM;
        size_t baseb = (((size_t)(bb * HH + h)) * LL + lb) * MM;
        if (full) {
            #pragma unroll
            for (int j = 0; j < 4; j++) {
                int m = m0 + warp_n + 8 * j + 2 * tg;
                *(float2*)&outp[basea + m] = make_float2(
                    __uint_as_float(f2tf(__expf(c[f][j][0] + ha))),
                    __uint_as_float(f2tf(__expf(c[f][j][1] + ha))));
                *(float2*)&outp[baseb + m] = make_float2(
                    __uint_as_float(f2tf(__expf(c[f][j][2] + hb))),
                    __uint_as_float(f2tf(__expf(c[f][j][3] + hb))));
            }
        } else {
            #pragma unroll
            for (int j = 0; j < 4; j++) {
                int m = m0 + warp_n + 8 * j + 2 * tg;
                if (m < MM)     outp[basea + m]     = __uint_as_float(f2tf(__expf(c[f][j][0] + ha)));
                if (m + 1 < MM) outp[basea + m + 1] = __uint_as_float(f2tf(__expf(c[f][j][1] + ha)));
                if (m < MM)     outp[baseb + m]     = __uint_as_float(f2tf(__expf(c[f][j][2] + hb)));
                if (m + 1 < MM) outp[baseb + m + 1] = __uint_as_float(f2tf(__expf(c[f][j][3] + hb)));
            }
        }
    }
}

// ---------------- phase A (TF32 mma; kp already tf32 — bit-copy staging) ----------------
__global__ void __launch_bounds__(544, 2) phaseA_kernel() {
    __shared__ uint32_t sk[2][16][276];
    __shared__ uint32_t sv[2][16][68];

    const int tid = threadIdx.x;
    const int wid = tid >> 5, lane = tid & 31;
    const int g = lane >> 2, tg = lane & 3;
    const int c = blockIdx.x, bh = blockIdx.y;
    const int b = bh >> 3, h = bh & 7;
    const int l0 = c * CHUNK;
    const float* kb = g_kp + ((size_t)bh * LL + l0) * MM;
    const float* vb = g_V + ((size_t)(b * LL + l0)) * DD + h * DHD;
    const int m0 = wid * 16;

    float acc[8][4];
    #pragma unroll
    for (int j = 0; j < 8; j++)
        #pragma unroll
        for (int q = 0; q < 4; q++) acc[j][q] = 0.f;
    float zacc = 0.f;

    const int svt = tid >> 4, svd = (tid & 15) * 4;

    #pragma unroll
    for (int idx = tid; idx < 16 * 136; idx += 544) {
        int t = idx / 136, m2 = (idx % 136) * 2;
        float2 kv = make_float2(0.f, 0.f);
        if (m2 < MM) kv = *(const float2*)&kb[(size_t)t * MM + m2];
        sk[0][t][m2]     = __float_as_uint(kv.x);
        sk[0][t][m2 + 1] = __float_as_uint(kv.y);
    }
    if (tid < 256) {
        float4 vv = *(const float4*)&vb[(size_t)svt * DD + svd];
        sv[0][svt][svd]     = f2tf(vv.x);
        sv[0][svt][svd + 1] = f2tf(vv.y);
        sv[0][svt][svd + 2] = f2tf(vv.z);
        sv[0][svt][svd + 3] = f2tf(vv.w);
    }
    __syncthreads();

    int buf = 0;
    #pragma unroll
    for (int it = 0; it < 4; it++) {
        if (it < 3) {
            int t0 = (it + 1) * 16;
            #pragma unroll
            for (int idx = tid; idx < 16 * 136; idx += 544) {
                int t = idx / 136, m2 = (idx % 136) * 2;
                float2 kv = make_float2(0.f, 0.f);
                if (m2 < MM) kv = *(const float2*)&kb[(size_t)(t0 + t) * MM + m2];
                sk[buf ^ 1][t][m2]     = __float_as_uint(kv.x);
                sk[buf ^ 1][t][m2 + 1] = __float_as_uint(kv.y);
            }
            if (tid < 256) {
                float4 vv = *(const float4*)&vb[(size_t)(t0 + svt) * DD + svd];
                sv[buf ^ 1][svt][svd]     = f2tf(vv.x);
                sv[buf ^ 1][svt][svd + 1] = f2tf(vv.y);
                sv[buf ^ 1][svt][svd + 2] = f2tf(vv.z);
                sv[buf ^ 1][svt][svd + 3] = f2tf(vv.w);
            }
        }
        if (tid < 272) {
            #pragma unroll
            for (int t = 0; t < 16; t++) zacc += __uint_as_float(sk[buf][t][tid]);
        }
        #pragma unroll
        for (int k8 = 0; k8 < 16; k8 += 8) {
            uint32_t a[4];
            a[0] = sk[buf][k8 + tg][m0 + g];
            a[1] = sk[buf][k8 + tg][m0 + g + 8];
            a[2] = sk[buf][k8 + tg + 4][m0 + g];
            a[3] = sk[buf][k8 + tg + 4][m0 + g + 8];
            #pragma unroll
            for (int j = 0; j < 8; j++) {
                uint32_t b0 = sv[buf][k8 + tg][j * 8 + g];
                uint32_t b1 = sv[buf][k8 + tg + 4][j * 8 + g];
                mma_tf32(acc[j], a, b0, b1);
            }
        }
        __syncthreads();
        buf ^= 1;
    }

    float* Sb = g_S + ((size_t)bh * NCH + c) * (MM * DHD);
    int mlo = m0 + g, mhi = m0 + g + 8;
    #pragma unroll
    for (int j = 0; j < 8; j++) {
        int d = j * 8 + 2 * tg;
        if (mlo < MM) *(float2*)&Sb[(size_t)mlo * DHD + d] =
            make_float2(acc[j][0], acc[j][1]);
        if (mhi < MM) *(float2*)&Sb[(size_t)mhi * DHD + d] =
            make_float2(acc[j][2], acc[j][3]);
    }
    if (tid < MM) g_z[((size_t)bh * NCH + c) * MM + tid] = zacc;
}

// ---------------- exclusive prefix over chunks (S and z merged, MLP=4) ----------------
__global__ void scan_kernel(float* dataS, float* dataZ) {
    const int perS = MM * DHD;
    const int totS = BHT * perS;
    int gid = blockIdx.x * blockDim.x + threadIdx.x;
    float* data;
    int per;
    if (gid < totS) {
        data = dataS; per = perS;
    } else {
        gid -= totS;
        if (gid >= BHT * MM) return;
        data = dataZ; per = MM;
    }
    int bh = gid / per, e = gid % per;
    size_t base = (size_t)bh * NCH * per + e;
    float run = 0.f;
    for (int c = 0; c < NCH; c += 4) {
        size_t i0 = base + (size_t)c * per;
        size_t i1 = i0 + per, i2 = i1 + per, i3 = i2 + per;
        float v0 = data[i0];
        float v1 = data[i1];
        float v2 = data[i2];
        float v3 = data[i3];
        data[i0] = run; run += v0;
        data[i1] = run; run += v1;
        data[i2] = run; run += v2;
        data[i3] = run; run += v3;
    }
}

// ---------------- phase C (TF32 mma; q/k bit-copy staging; prefetch) ----------------
__global__ void __launch_bounds__(256, 2) phaseC_kernel() {
    __shared__ uint32_t A_sh[64][68];
    __shared__ uint32_t wbuf[4608];
    __shared__ uint32_t Ssb[32 * 68];
    __shared__ float zs[32];
    __shared__ float dred[4][64];
    __shared__ float den_sh[64];

    uint32_t (*qs)[36] = (uint32_t(*)[36])wbuf;
    uint32_t (*ks)[36] = (uint32_t(*)[36])(wbuf + 2304);
    uint32_t (*Vs)[68] = (uint32_t(*)[68])wbuf;
    uint32_t (*Ss)[68] = (uint32_t(*)[68])Ssb;

    const int tid = threadIdx.x;
    const int wid = tid >> 5, lane = tid & 31;
    const int g = lane >> 2, tg = lane & 3;
    const int t0 = (wid & 3) * 16;
    const int n0 = (wid >> 2) * 32;
    const int c = blockIdx.x, bh = blockIdx.y;
    const int b = bh >> 3, h = bh & 7;
    const int l0 = c * CHUNK;
    const float* qb = g_qp + ((size_t)bh * LL + l0) * MM;
    const float* kb = g_kp + ((size_t)bh * LL + l0) * MM;
    const float* zb = g_z + ((size_t)bh * NCH + c) * MM;
    const float* Sb = g_S + ((size_t)bh * NCH + c) * (MM * DHD);

    float c1[4][4], c2[4][4];
    #pragma unroll
    for (int j = 0; j < 4; j++)
        #pragma unroll
        for (int q = 0; q < 4; q++) { c1[j][q] = 0.f; c2[j][q] = 0.f; }
    float dq = 0.f;
    const int dt = tid & 63, dslice = tid >> 6;

    const int sqt[4]  = { tid >> 4, (tid + 256) >> 4, (tid + 512) >> 4, (tid + 768) >> 4 };
    const int sqmv    = (tid & 15) * 2;
    const int ssm[2]  = { tid >> 4, (tid + 256) >> 4 };
    const int ssd     = (tid & 15) * 4;

    float2 qR[4], kR[4];
    float4 sR[2];
    float zR = 0.f;

    auto load_tile = [&](int m0k) {
        #pragma unroll
        for (int i = 0; i < 4; i++) {
            int m = m0k + sqmv;
            qR[i] = make_float2(0.f, 0.f);
            kR[i] = make_float2(0.f, 0.f);
            if (m < MM) {
                qR[i] = *(const float2*)&qb[(size_t)sqt[i] * MM + m];
                kR[i] = *(const float2*)&kb[(size_t)sqt[i] * MM + m];
            }
        }
        #pragma unroll
        for (int i = 0; i < 2; i++) {
            int m = m0k + ssm[i];
            sR[i] = make_float4(0.f, 0.f, 0.f, 0.f);
            if (m < MM) sR[i] = *(const float4*)&Sb[(size_t)m * DHD + ssd];
        }
        if (tid < 32) zR = (m0k + tid < MM) ? zb[m0k + tid] : 0.f;
    };
    auto store_tile = [&]() {
        #pragma unroll
        for (int i = 0; i < 4; i++) {
            qs[sqt[i]][sqmv]     = __float_as_uint(qR[i].x);
            qs[sqt[i]][sqmv + 1] = __float_as_uint(qR[i].y);
            ks[sqt[i]][sqmv]     = __float_as_uint(kR[i].x);
            ks[sqt[i]][sqmv + 1] = __float_as_uint(kR[i].y);
        }
        #pragma unroll
        for (int i = 0; i < 2; i++) {
            Ss[ssm[i]][ssd]     = f2tf(sR[i].x);
            Ss[ssm[i]][ssd + 1] = f2tf(sR[i].y);
            Ss[ssm[i]][ssd + 2] = f2tf(sR[i].z);
            Ss[ssm[i]][ssd + 3] = f2tf(sR[i].w);
        }
        if (tid < 32) zs[tid] = zR;
    };

    load_tile(0);
    store_tile();
    __syncthreads();

    for (int mi = 0; mi < 9; mi++) {
        if (mi < 8) load_tile((mi + 1) * 32);
        #pragma unroll
        for (int i = 0; i < 8; i++) {
            int mm = dslice * 8 + i;
            dq += __uint_as_float(qs[dt][mm]) * zs[mm];
        }
        #pragma unroll
        for (int k8 = 0; k8 < 32; k8 += 8) {
            uint32_t a[4];
            a[0] = qs[t0 + g][k8 + tg];
            a[1] = qs[t0 + g + 8][k8 + tg];
            a[2] = qs[t0 + g][k8 + tg + 4];
            a[3] = qs[t0 + g + 8][k8 + tg + 4];
            #pragma unroll
            for (int j = 0; j < 4; j++) {
                uint32_t b0 = ks[n0 + j * 8 + g][k8 + tg];
                uint32_t b1 = ks[n0 + j * 8 + g][k8 + tg + 4];
                mma_tf32(c1[j], a, b0, b1);
            }
            #pragma unroll
            for (int j = 0; j < 4; j++) {
                uint32_t b0 = Ss[k8 + tg][n0 + j * 8 + g];
                uint32_t b1 = Ss[k8 + tg + 4][n0 + j * 8 + g];
                mma_tf32(c2[j], a, b0, b1);
            }
        }
        __syncthreads();
        if (mi < 8) {
            store_tile();
            __syncthreads();
        }
    }
    dred[dslice][dt] = dq;

    {
        int ta = t0 + g, tb2 = t0 + g + 8;
        #pragma unroll
        for (int j = 0; j < 4; j++) {
            int s = n0 + j * 8 + 2 * tg;
            A_sh[ta][s]      = f2tf((s     <= ta)  ? c1[j][0] : 0.f);
            A_sh[ta][s + 1]  = f2tf((s + 1 <= ta)  ? c1[j][1] : 0.f);
            A_sh[tb2][s]     = f2tf((s     <= tb2) ? c1[j][2] : 0.f);
            A_sh[tb2][s + 1] = f2tf((s + 1 <= tb2) ? c1[j][3] : 0.f);
        }
    }
    __syncthreads();

    if (tid < 64) {
        float r = dred[0][tid] + dred[1][tid] + dred[2][tid] + dred[3][tid];
        #pragma unroll 8
        for (int s = 0; s < 64; s++) r += __uint_as_float(A_sh[tid][s]);
        den_sh[tid] = r;
    }

    {
        int t = tid >> 2, d16 = (tid & 3) * 16;
        const float* vr = &g_V[((size_t)(b * LL + l0 + t)) * DD + h * DHD + d16];
        #pragma unroll
        for (int q = 0; q < 4; q++) {
            float4 vv = *(const float4*)&vr[q * 4];
            Vs[t][d16 + q * 4]     = f2tf(vv.x);
            Vs[t][d16 + q * 4 + 1] = f2tf(vv.y);
            Vs[t][d16 + q * 4 + 2] = f2tf(vv.z);
            Vs[t][d16 + q * 4 + 3] = f2tf(vv.w);
        }
    }
    __syncthreads();

    #pragma unroll
    for (int k8 = 0; k8 < 64; k8 += 8) {
        uint32_t a[4];
        a[0] = A_sh[t0 + g][k8 + tg];
        a[1] = A_sh[t0 + g + 8][k8 + tg];
        a[2] = A_sh[t0 + g][k8 + tg + 4];
        a[3] = A_sh[t0 + g + 8][k8 + tg + 4];
        #pragma unroll
        for (int j = 0; j < 4; j++) {
            uint32_t b0 = Vs[k8 + tg][n0 + j * 8 + g];
            uint32_t b1 = Vs[k8 + tg + 4][n0 + j * 8 + g];
            mma_tf32(c2[j], a, b0, b1);
        }
    }

    {
        int ta = t0 + g, tb2 = t0 + g + 8;
        float inva = 1.0f / den_sh[ta];
        float invb = 1.0f / den_sh[tb2];
        #pragma unroll
        for (int j = 0; j < 4; j++) {
            int d = n0 + j * 8 + 2 * tg;
            *(float2*)&g_ctx[((size_t)(b * LL + l0 + ta)) * DD + h * DHD + d] =
                make_float2(c2[j][0] * inva, c2[j][1] * inva);
            *(float2*)&g_ctx[((size_t)(b * LL + l0 + tb2)) * DD + h * DHD + d] =
                make_float2(c2[j][2] * invb, c2[j][3] * invb);
        }
    }
}

// ---------------- launch ----------------
extern "C" void kernel_launch(void* const* d_in, const int* in_sizes, int n_in,
                              void* d_out, int out_size) {
    const float* query = (const float*)d_in[0];
    const float* key   = (const float*)d_in[1];
    const float* value = (const float*)d_in[2];
    const float* Wq    = (const float*)d_in[3];
    const float* bq    = (const float*)d_in[4];
    const float* Wk    = (const float*)d_in[5];
    const float* bk    = (const float*)d_in[6];
    const float* Wv    = (const float*)d_in[7];
    const float* bv    = (const float*)d_in[8];
    const float* Wout  = (const float*)d_in[9];
    const float* bout  = (const float*)d_in[10];
    const float* RF    = (const float*)d_in[11];

    float *Qp, *Kp, *Vp, *qpp, *kpp, *Sp, *zp, *ctxp;
    cudaGetSymbolAddress((void**)&Qp,  g_Q);
    cudaGetSymbolAddress((void**)&Kp,  g_K);
    cudaGetSymbolAddress((void**)&Vp,  g_V);
    cudaGetSymbolAddress((void**)&qpp, g_qp);
    cudaGetSymbolAddress((void**)&kpp, g_kp);
    cudaGetSymbolAddress((void**)&Sp,  g_S);
    cudaGetSymbolAddress((void**)&zp,  g_z);
    cudaGetSymbolAddress((void**)&ctxp, g_ctx);

    cudaFuncSetAttribute(tf32_gemm, cudaFuncAttributeMaxDynamicSharedMemorySize, GSM_BYTES);

    dim3 gp(DD / 128, NROWS / 128, 3);
    tf32_gemm<<<gp, 256, GSM_BYTES>>>(query, Wq, bq, Qp,
                                      key,   Wk, bk, Kp,
                                      value, Wv, bv, Vp);

    dim3 fg((MM + 63) / 64, NROWS / 128, 2 * HH);
    feat_gemm<<<fg, 256>>>(Qp, Kp, RF, qpp, kpp);

    dim3 pg(NCH, BHT);
    phaseA_kernel<<<pg, 544>>>();

    int tot = BHT * (MM * DHD + MM);
    scan_kernel<<<(tot + 255) / 256, 256>>>(Sp, zp);

    phaseC_kernel<<<pg, 256>>>();

    dim3 go(DD / 128, NROWS / 128, 1);
    tf32_gemm<<<go, 256, GSM_BYTES>>>(ctxp, Wout, bout, (float*)d_out,
                                      ctxp, Wout, bout, (float*)d_out,
                                      ctxp, Wout, bout, (float*)d_out);
}

// round 17
// speedup vs baseline: 1.8024x; 1.1130x over previous
#include <cuda_runtime.h>
#include <math.h>
#include <stdint.h>

// ---------------- problem constants ----------------
#define BB    2
#define LL    4096
#define DD    512
#define HH    8
#define DHD   64
#define MM    266
#define NROWS (BB*LL)        // 8192
#define CHUNK 64
#define NCH   (LL/CHUNK)     // 64
#define BHT   (BB*HH)        // 16

#define INV_S4      0.21022410381342863f   // 512^-0.25
#define INV_SQRT512 0.04419417382415922f   // 512^-0.5

// ---------------- scratch ----------------
__device__ float g_Q[NROWS*DD];
__device__ float g_K[NROWS*DD];
__device__ float g_V[NROWS*DD];
__device__ float g_qp[(size_t)BHT*LL*MM];   // stored pre-rounded to tf32
__device__ float g_kp[(size_t)BHT*LL*MM];   // stored pre-rounded to tf32
__device__ float g_S [(size_t)BHT*NCH*MM*DHD];
__device__ float g_z [(size_t)BHT*NCH*MM];
__device__ float g_ctx[NROWS*DD];

// ---------------- TF32 helpers ----------------
__device__ __forceinline__ uint32_t f2tf(float f) {
    uint32_t u;
    asm("cvt.rna.tf32.f32 %0, %1;" : "=r"(u) : "f"(f));
    return u;
}
__device__ __forceinline__ void mma_tf32(float* c, const uint32_t* a,
                                         uint32_t b0, uint32_t b1) {
    asm volatile(
        "mma.sync.aligned.m16n8k8.row.col.f32.tf32.tf32.f32 "
        "{%0,%1,%2,%3}, {%4,%5,%6,%7}, {%8,%9}, {%0,%1,%2,%3};"
        : "+f"(c[0]), "+f"(c[1]), "+f"(c[2]), "+f"(c[3])
        : "r"(a[0]), "r"(a[1]), "r"(a[2]), "r"(a[3]), "r"(b0), "r"(b1));
}

// ---------------- TF32 GEMM: double-buffered dynamic smem, RNA cvt, 1 sync/kt ----------------
#define GSM_STRIDE 36
#define GSM_STAGE  (128 * GSM_STRIDE)
#define GSM_BYTES  (4 * GSM_STAGE * 4)

__global__ void __launch_bounds__(256, 2)
tf32_gemm(const float* __restrict__ A0, const float* __restrict__ W0,
          const float* __restrict__ bb0, float* __restrict__ C0,
          const float* __restrict__ A1, const float* __restrict__ W1,
          const float* __restrict__ bb1, float* __restrict__ C1,
          const float* __restrict__ A2, const float* __restrict__ W2,
          const float* __restrict__ bb2, float* __restrict__ C2) {
    extern __shared__ uint32_t dsm[];

    const float* A; const float* W; const float* bias; float* C;
    if (blockIdx.z == 0)      { A = A0; W = W0; bias = bb0; C = C0; }
    else if (blockIdx.z == 1) { A = A1; W = W1; bias = bb1; C = C1; }
    else                      { A = A2; W = W2; bias = bb2; C = C2; }

    const int t = threadIdx.x;
    const int wid = t >> 5, lane = t & 31;
    const int warp_m = (wid & 3) * 32;
    const int warp_n = (wid >> 2) * 64;
    const int row0 = blockIdx.y * 128, col0 = blockIdx.x * 128;
    const int g = lane >> 2, tg = lane & 3;
    const int rl = t >> 3;
    const int ql = (t & 7) * 4;

    float c[2][8][4];
    #pragma unroll
    for (int f = 0; f < 2; f++)
        #pragma unroll
        for (int j = 0; j < 8; j++)
            #pragma unroll
            for (int q = 0; q < 4; q++) c[f][j][q] = 0.f;

    float4 aR[4], wR[4];
    auto load_regs = [&](int ks) {
        #pragma unroll
        for (int i = 0; i < 4; i++) {
            aR[i] = *(const float4*)&A[(size_t)(row0 + rl + i * 32) * DD + ks + ql];
            wR[i] = *(const float4*)&W[(size_t)(col0 + rl + i * 32) * DD + ks + ql];
        }
    };
    auto store_buf = [&](int s) {
        uint32_t* ab = dsm + s * 2 * GSM_STAGE;
        uint32_t* wb = ab + GSM_STAGE;
        #pragma unroll
        for (int i = 0; i < 4; i++) {
            int r = rl + i * 32;
            *(uint4*)&ab[r * GSM_STRIDE + ql] =
                make_uint4(f2tf(aR[i].x), f2tf(aR[i].y), f2tf(aR[i].z), f2tf(aR[i].w));
            *(uint4*)&wb[r * GSM_STRIDE + ql] =
                make_uint4(f2tf(wR[i].x), f2tf(wR[i].y), f2tf(wR[i].z), f2tf(wR[i].w));
        }
    };

    load_regs(0);
    store_buf(0);
    __syncthreads();

    int buf = 0;
    for (int kt = 0; kt < DD / 32; kt++) {
        if (kt < DD / 32 - 1) load_regs((kt + 1) * 32);

        const uint32_t (*As)[GSM_STRIDE] =
            (const uint32_t(*)[GSM_STRIDE])(dsm + buf * 2 * GSM_STAGE);
        const uint32_t (*Ws)[GSM_STRIDE] =
            (const uint32_t(*)[GSM_STRIDE])(dsm + buf * 2 * GSM_STAGE + GSM_STAGE);

        #pragma unroll
        for (int k8 = 0; k8 < 32; k8 += 8) {
            uint32_t a[2][4];
            #pragma unroll
            for (int f = 0; f < 2; f++) {
                int m0 = warp_m + 16 * f;
                a[f][0] = As[m0 + g][k8 + tg];
                a[f][1] = As[m0 + g + 8][k8 + tg];
                a[f][2] = As[m0 + g][k8 + tg + 4];
                a[f][3] = As[m0 + g + 8][k8 + tg + 4];
            }
            #pragma unroll
            for (int j = 0; j < 8; j++) {
                uint32_t b0 = Ws[warp_n + 8 * j + g][k8 + tg];
                uint32_t b1 = Ws[warp_n + 8 * j + g][k8 + tg + 4];
                mma_tf32(c[0][j], a[0], b0, b1);
                mma_tf32(c[1][j], a[1], b0, b1);
            }
        }
        if (kt < DD / 32 - 1) store_buf(buf ^ 1);
        __syncthreads();
        buf ^= 1;
    }

    #pragma unroll
    for (int f = 0; f < 2; f++) {
        int r0 = row0 + warp_m + 16 * f + g;
        #pragma unroll
        for (int j = 0; j < 8; j++) {
            int cidx = col0 + warp_n + 8 * j + 2 * tg;
            float bx = bias[cidx], by = bias[cidx + 1];
            float2 o0 = make_float2(c[f][j][0] + bx, c[f][j][1] + by);
            float2 o1 = make_float2(c[f][j][2] + bx, c[f][j][3] + by);
            *(float2*)&C[(size_t)r0 * DD + cidx] = o0;
            *(float2*)&C[(size_t)(r0 + 8) * DD + cidx] = o1;
        }
    }
}

// ---------------- feature map (TF32 mma; h-norm fused; outputs pre-rounded tf32) ----------------
__global__ void __launch_bounds__(256) feat_gemm(const float* __restrict__ Xq,
                                                 const float* __restrict__ Xk,
                                                 const float* __restrict__ RF,
                                                 float* __restrict__ outq,
                                                 float* __restrict__ outk) {
    __shared__ uint32_t Xs[128][36];
    __shared__ uint32_t Rs[64][36];
    __shared__ float hsh[128];

    const int t = threadIdx.x;
    const int wid = t >> 5, lane = t & 31;
    const int g = lane >> 2, tg = lane & 3;
    const int warp_m = (wid & 3) * 32;
    const int warp_n = (wid >> 2) * 32;
    const int sel = blockIdx.z >> 3;
    const int h  = blockIdx.z & 7;
    const float* X  = sel ? Xk : Xq;
    float* outp     = sel ? outk : outq;
    const int r0 = blockIdx.y * 128;
    const int m0 = blockIdx.x * 64;
    const bool full = (m0 + 64 <= MM);

    float c[2][4][4];
    #pragma unroll
    for (int f = 0; f < 2; f++)
        #pragma unroll
        for (int j = 0; j < 4; j++)
            #pragma unroll
            for (int q = 0; q < 4; q++) c[f][j][q] = 0.f;

    float sq[4] = {0.f, 0.f, 0.f, 0.f};

    float4 xRg[4], rRg[2];
    auto load_chunk = [&](int kc) {
        #pragma unroll
        for (int i = 0; i < 4; i++) {
            int idx = t + i * 256;
            int r = idx >> 3, q = (idx & 7) * 4;
            xRg[i] = *(const float4*)&X[(size_t)(r0 + r) * DD + h * DHD + kc + q];
        }
        #pragma unroll
        for (int i = 0; i < 2; i++) {
            int idx = t + i * 256;
            int mr = idx >> 3, q = (idx & 7) * 4;
            rRg[i] = make_float4(0.f, 0.f, 0.f, 0.f);
            if (full || m0 + mr < MM)
                rRg[i] = *(const float4*)&RF[(size_t)(m0 + mr) * DHD + kc + q];
        }
    };
    auto store_chunk = [&]() {
        #pragma unroll
        for (int i = 0; i < 4; i++) {
            int idx = t + i * 256;
            int r = idx >> 3, q = (idx & 7) * 4;
            sq[i] += xRg[i].x * xRg[i].x + xRg[i].y * xRg[i].y
                   + xRg[i].z * xRg[i].z + xRg[i].w * xRg[i].w;
            *(uint4*)&Xs[r][q] =
                make_uint4(f2tf(xRg[i].x * INV_S4), f2tf(xRg[i].y * INV_S4),
                           f2tf(xRg[i].z * INV_S4), f2tf(xRg[i].w * INV_S4));
        }
        #pragma unroll
        for (int i = 0; i < 2; i++) {
            int idx = t + i * 256;
            int mr = idx >> 3, q = (idx & 7) * 4;
            *(uint4*)&Rs[mr][q] =
                make_uint4(f2tf(rRg[i].x), f2tf(rRg[i].y), f2tf(rRg[i].z), f2tf(rRg[i].w));
        }
    };

    load_chunk(0);
    store_chunk();
    __syncthreads();

    for (int it = 0; it < 2; it++) {
        if (it == 0) load_chunk(32);
        #pragma unroll
        for (int k8 = 0; k8 < 32; k8 += 8) {
            uint32_t a[2][4];
            #pragma unroll
            for (int f = 0; f < 2; f++) {
                int mw = warp_m + 16 * f;
                a[f][0] = Xs[mw + g][k8 + tg];
                a[f][1] = Xs[mw + g + 8][k8 + tg];
                a[f][2] = Xs[mw + g][k8 + tg + 4];
                a[f][3] = Xs[mw + g + 8][k8 + tg + 4];
            }
            #pragma unroll
            for (int j = 0; j < 4; j++) {
                uint32_t b0 = Rs[warp_n + 8 * j + g][k8 + tg];
                uint32_t b1 = Rs[warp_n + 8 * j + g][k8 + tg + 4];
                mma_tf32(c[0][j], a[0], b0, b1);
                mma_tf32(c[1][j], a[1], b0, b1);
            }
        }
        if (it == 0) {
            __syncthreads();
            store_chunk();
            __syncthreads();
        }
    }

    #pragma unroll
    for (int i = 0; i < 4; i++) {
        #pragma unroll
        for (int off = 4; off; off >>= 1)
            sq[i] += __shfl_down_sync(0xffffffffu, sq[i], off, 8);
        if ((t & 7) == 0) hsh[(t >> 3) + 32 * i] = -0.5f * INV_SQRT512 * sq[i];
    }
    __syncthreads();

    #pragma unroll
    for (int f = 0; f < 2; f++) {
        int lra = warp_m + 16 * f + g;
        int ra = r0 + lra;
        int rb = ra + 8;
        float ha = hsh[lra];
        float hb = hsh[lra + 8];
        int ba = ra >> 12, la = ra & 4095;
        int bb = rb >> 12, lb = rb & 4095;
        size_t basea = (((size_t)(ba * HH + h)) * LL + la) * MM;
        size_t baseb = (((size_t)(bb * HH + h)) * LL + lb) * MM;
        if (full) {
            #pragma unroll
            for (int j = 0; j < 4; j++) {
                int m = m0 + warp_n + 8 * j + 2 * tg;
                *(float2*)&outp[basea + m] = make_float2(
                    __uint_as_float(f2tf(__expf(c[f][j][0] + ha))),
                    __uint_as_float(f2tf(__expf(c[f][j][1] + ha))));
                *(float2*)&outp[baseb + m] = make_float2(
                    __uint_as_float(f2tf(__expf(c[f][j][2] + hb))),
                    __uint_as_float(f2tf(__expf(c[f][j][3] + hb))));
            }
        } else {
            #pragma unroll
            for (int j = 0; j < 4; j++) {
                int m = m0 + warp_n + 8 * j + 2 * tg;
                if (m < MM)     outp[basea + m]     = __uint_as_float(f2tf(__expf(c[f][j][0] + ha)));
                if (m + 1 < MM) outp[basea + m + 1] = __uint_as_float(f2tf(__expf(c[f][j][1] + ha)));
                if (m < MM)     outp[baseb + m]     = __uint_as_float(f2tf(__expf(c[f][j][2] + hb)));
                if (m + 1 < MM) outp[baseb + m + 1] = __uint_as_float(f2tf(__expf(c[f][j][3] + hb)));
            }
        }
    }
}

// ---------------- phase A (TF32 mma; kp already tf32 — bit-copy staging) ----------------
__global__ void __launch_bounds__(544, 2) phaseA_kernel() {
    __shared__ uint32_t sk[2][16][276];
    __shared__ uint32_t sv[2][16][68];

    const int tid = threadIdx.x;
    const int wid = tid >> 5, lane = tid & 31;
    const int g = lane >> 2, tg = lane & 3;
    const int c = blockIdx.x, bh = blockIdx.y;
    const int b = bh >> 3, h = bh & 7;
    const int l0 = c * CHUNK;
    const float* kb = g_kp + ((size_t)bh * LL + l0) * MM;
    const float* vb = g_V + ((size_t)(b * LL + l0)) * DD + h * DHD;
    const int m0 = wid * 16;

    float acc[8][4];
    #pragma unroll
    for (int j = 0; j < 8; j++)
        #pragma unroll
        for (int q = 0; q < 4; q++) acc[j][q] = 0.f;
    float zacc = 0.f;

    const int svt = tid >> 4, svd = (tid & 15) * 4;

    #pragma unroll
    for (int idx = tid; idx < 16 * 136; idx += 544) {
        int t = idx / 136, m2 = (idx % 136) * 2;
        float2 kv = make_float2(0.f, 0.f);
        if (m2 < MM) kv = *(const float2*)&kb[(size_t)t * MM + m2];
        sk[0][t][m2]     = __float_as_uint(kv.x);
        sk[0][t][m2 + 1] = __float_as_uint(kv.y);
    }
    if (tid < 256) {
        float4 vv = *(const float4*)&vb[(size_t)svt * DD + svd];
        sv[0][svt][svd]     = f2tf(vv.x);
        sv[0][svt][svd + 1] = f2tf(vv.y);
        sv[0][svt][svd + 2] = f2tf(vv.z);
        sv[0][svt][svd + 3] = f2tf(vv.w);
    }
    __syncthreads();

    int buf = 0;
    #pragma unroll
    for (int it = 0; it < 4; it++) {
        if (it < 3) {
            int t0 = (it + 1) * 16;
            #pragma unroll
            for (int idx = tid; idx < 16 * 136; idx += 544) {
                int t = idx / 136, m2 = (idx % 136) * 2;
                float2 kv = make_float2(0.f, 0.f);
                if (m2 < MM) kv = *(const float2*)&kb[(size_t)(t0 + t) * MM + m2];
                sk[buf ^ 1][t][m2]     = __float_as_uint(kv.x);
                sk[buf ^ 1][t][m2 + 1] = __float_as_uint(kv.y);
            }
            if (tid < 256) {
                float4 vv = *(const float4*)&vb[(size_t)(t0 + svt) * DD + svd];
                sv[buf ^ 1][svt][svd]     = f2tf(vv.x);
                sv[buf ^ 1][svt][svd + 1] = f2tf(vv.y);
                sv[buf ^ 1][svt][svd + 2] = f2tf(vv.z);
                sv[buf ^ 1][svt][svd + 3] = f2tf(vv.w);
            }
        }
        if (tid < 272) {
            #pragma unroll
            for (int t = 0; t < 16; t++) zacc += __uint_as_float(sk[buf][t][tid]);
        }
        #pragma unroll
        for (int k8 = 0; k8 < 16; k8 += 8) {
            uint32_t a[4];
            a[0] = sk[buf][k8 + tg][m0 + g];
            a[1] = sk[buf][k8 + tg][m0 + g + 8];
            a[2] = sk[buf][k8 + tg + 4][m0 + g];
            a[3] = sk[buf][k8 + tg + 4][m0 + g + 8];
            #pragma unroll
            for (int j = 0; j < 8; j++) {
                uint32_t b0 = sv[buf][k8 + tg][j * 8 + g];
                uint32_t b1 = sv[buf][k8 + tg + 4][j * 8 + g];
                mma_tf32(acc[j], a, b0, b1);
            }
        }
        __syncthreads();
        buf ^= 1;
    }

    float* Sb = g_S + ((size_t)bh * NCH + c) * (MM * DHD);
    int mlo = m0 + g, mhi = m0 + g + 8;
    #pragma unroll
    for (int j = 0; j < 8; j++) {
        int d = j * 8 + 2 * tg;
        if (mlo < MM) *(float2*)&Sb[(size_t)mlo * DHD + d] =
            make_float2(acc[j][0], acc[j][1]);
        if (mhi < MM) *(float2*)&Sb[(size_t)mhi * DHD + d] =
            make_float2(acc[j][2], acc[j][3]);
    }
    if (tid < MM) g_z[((size_t)bh * NCH + c) * MM + tid] = zacc;
}

// ---------------- exclusive prefix over chunks: float4 for S, scalar for z ----------------
__global__ void scan_kernel(float* dataS, float* dataZ) {
    const int perS = MM * DHD;          // 17024
    const int vecS = perS / 4;          // 4256
    const int totV = BHT * vecS;        // 68096
    int gid = blockIdx.x * blockDim.x + threadIdx.x;
    if (gid < totV) {
        int bh = gid / vecS, e4 = gid % vecS;
        float4* base = (float4*)(dataS + (size_t)bh * NCH * perS) + e4;
        float4 run = make_float4(0.f, 0.f, 0.f, 0.f);
        for (int c = 0; c < NCH; c += 4) {
            float4* p0 = base + (size_t)(c + 0) * vecS;
            float4* p1 = base + (size_t)(c + 1) * vecS;
            float4* p2 = base + (size_t)(c + 2) * vecS;
            float4* p3 = base + (size_t)(c + 3) * vecS;
            float4 v0 = *p0;
            float4 v1 = *p1;
            float4 v2 = *p2;
            float4 v3 = *p3;
            *p0 = run;
            run.x += v0.x; run.y += v0.y; run.z += v0.z; run.w += v0.w;
            *p1 = run;
            run.x += v1.x; run.y += v1.y; run.z += v1.z; run.w += v1.w;
            *p2 = run;
            run.x += v2.x; run.y += v2.y; run.z += v2.z; run.w += v2.w;
            *p3 = run;
            run.x += v3.x; run.y += v3.y; run.z += v3.z; run.w += v3.w;
        }
    } else {
        int zg = gid - totV;
        if (zg >= BHT * MM) return;
        int bh = zg / MM, e = zg % MM;
        size_t base = (size_t)bh * NCH * MM + e;
        float run = 0.f;
        for (int c = 0; c < NCH; c += 4) {
            size_t i0 = base + (size_t)c * MM;
            size_t i1 = i0 + MM, i2 = i1 + MM, i3 = i2 + MM;
            float v0 = dataZ[i0];
            float v1 = dataZ[i1];
            float v2 = dataZ[i2];
            float v3 = dataZ[i3];
            dataZ[i0] = run; run += v0;
            dataZ[i1] = run; run += v1;
            dataZ[i2] = run; run += v2;
            dataZ[i3] = run; run += v3;
        }
    }
}

// ---------------- phase C (TF32 mma; q/k bit-copy staging; prefetch) ----------------
__global__ void __launch_bounds__(256, 2) phaseC_kernel() {
    __shared__ uint32_t A_sh[64][68];
    __shared__ uint32_t wbuf[4608];
    __shared__ uint32_t Ssb[32 * 68];
    __shared__ float zs[32];
    __shared__ float dred[4][64];
    __shared__ float den_sh[64];

    uint32_t (*qs)[36] = (uint32_t(*)[36])wbuf;
    uint32_t (*ks)[36] = (uint32_t(*)[36])(wbuf + 2304);
    uint32_t (*Vs)[68] = (uint32_t(*)[68])wbuf;
    uint32_t (*Ss)[68] = (uint32_t(*)[68])Ssb;

    const int tid = threadIdx.x;
    const int wid = tid >> 5, lane = tid & 31;
    const int g = lane >> 2, tg = lane & 3;
    const int t0 = (wid & 3) * 16;
    const int n0 = (wid >> 2) * 32;
    const int c = blockIdx.x, bh = blockIdx.y;
    const int b = bh >> 3, h = bh & 7;
    const int l0 = c * CHUNK;
    const float* qb = g_qp + ((size_t)bh * LL + l0) * MM;
    const float* kb = g_kp + ((size_t)bh * LL + l0) * MM;
    const float* zb = g_z + ((size_t)bh * NCH + c) * MM;
    const float* Sb = g_S + ((size_t)bh * NCH + c) * (MM * DHD);

    float c1[4][4], c2[4][4];
    #pragma unroll
    for (int j = 0; j < 4; j++)
        #pragma unroll
        for (int q = 0; q < 4; q++) { c1[j][q] = 0.f; c2[j][q] = 0.f; }
    float dq = 0.f;
    const int dt = tid & 63, dslice = tid >> 6;

    const int sqt[4]  = { tid >> 4, (tid + 256) >> 4, (tid + 512) >> 4, (tid + 768) >> 4 };
    const int sqmv    = (tid & 15) * 2;
    const int ssm[2]  = { tid >> 4, (tid + 256) >> 4 };
    const int ssd     = (tid & 15) * 4;

    float2 qR[4], kR[4];
    float4 sR[2];
    float zR = 0.f;

    auto load_tile = [&](int m0k) {
        #pragma unroll
        for (int i = 0; i < 4; i++) {
            int m = m0k + sqmv;
            qR[i] = make_float2(0.f, 0.f);
            kR[i] = make_float2(0.f, 0.f);
            if (m < MM) {
                qR[i] = *(const float2*)&qb[(size_t)sqt[i] * MM + m];
                kR[i] = *(const float2*)&kb[(size_t)sqt[i] * MM + m];
            }
        }
        #pragma unroll
        for (int i = 0; i < 2; i++) {
            int m = m0k + ssm[i];
            sR[i] = make_float4(0.f, 0.f, 0.f, 0.f);
            if (m < MM) sR[i] = *(const float4*)&Sb[(size_t)m * DHD + ssd];
        }
        if (tid < 32) zR = (m0k + tid < MM) ? zb[m0k + tid] : 0.f;
    };
    auto store_tile = [&]() {
        #pragma unroll
        for (int i = 0; i < 4; i++) {
            qs[sqt[i]][sqmv]     = __float_as_uint(qR[i].x);
            qs[sqt[i]][sqmv + 1] = __float_as_uint(qR[i].y);
            ks[sqt[i]][sqmv]     = __float_as_uint(kR[i].x);
            ks[sqt[i]][sqmv + 1] = __float_as_uint(kR[i].y);
        }
        #pragma unroll
        for (int i = 0; i < 2; i++) {
            Ss[ssm[i]][ssd]     = f2tf(sR[i].x);
            Ss[ssm[i]][ssd + 1] = f2tf(sR[i].y);
            Ss[ssm[i]][ssd + 2] = f2tf(sR[i].z);
            Ss[ssm[i]][ssd + 3] = f2tf(sR[i].w);
        }
        if (tid < 32) zs[tid] = zR;
    };

    load_tile(0);
    store_tile();
    __syncthreads();

    for (int mi = 0; mi < 9; mi++) {
        if (mi < 8) load_tile((mi + 1) * 32);
        #pragma unroll
        for (int i = 0; i < 8; i++) {
            int mm = dslice * 8 + i;
            dq += __uint_as_float(qs[dt][mm]) * zs[mm];
        }
        #pragma unroll
        for (int k8 = 0; k8 < 32; k8 += 8) {
            uint32_t a[4];
            a[0] = qs[t0 + g][k8 + tg];
            a[1] = qs[t0 + g + 8][k8 + tg];
            a[2] = qs[t0 + g][k8 + tg + 4];
            a[3] = qs[t0 + g + 8][k8 + tg + 4];
            #pragma unroll
            for (int j = 0; j < 4; j++) {
                uint32_t b0 = ks[n0 + j * 8 + g][k8 + tg];
                uint32_t b1 = ks[n0 + j * 8 + g][k8 + tg + 4];
                mma_tf32(c1[j], a, b0, b1);
            }
            #pragma unroll
            for (int j = 0; j < 4; j++) {
                uint32_t b0 = Ss[k8 + tg][n0 + j * 8 + g];
                uint32_t b1 = Ss[k8 + tg + 4][n0 + j * 8 + g];
                mma_tf32(c2[j], a, b0, b1);
            }
        }
        __syncthreads();
        if (mi < 8) {
            store_tile();
            __syncthreads();
        }
    }
    dred[dslice][dt] = dq;

    {
        int ta = t0 + g, tb2 = t0 + g + 8;
        #pragma unroll
        for (int j = 0; j < 4; j++) {
            int s = n0 + j * 8 + 2 * tg;
            A_sh[ta][s]      = f2tf((s     <= ta)  ? c1[j][0] : 0.f);
            A_sh[ta][s + 1]  = f2tf((s + 1 <= ta)  ? c1[j][1] : 0.f);
            A_sh[tb2][s]     = f2tf((s     <= tb2) ? c1[j][2] : 0.f);
            A_sh[tb2][s + 1] = f2tf((s + 1 <= tb2) ? c1[j][3] : 0.f);
        }
    }
    __syncthreads();

    if (tid < 64) {
        float r = dred[0][tid] + dred[1][tid] + dred[2][tid] + dred[3][tid];
        #pragma unroll 8
        for (int s = 0; s < 64; s++) r += __uint_as_float(A_sh[tid][s]);
        den_sh[tid] = r;
    }

    {
        int t = tid >> 2, d16 = (tid & 3) * 16;
        const float* vr = &g_V[((size_t)(b * LL + l0 + t)) * DD + h * DHD + d16];
        #pragma unroll
        for (int q = 0; q < 4; q++) {
            float4 vv = *(const float4*)&vr[q * 4];
            Vs[t][d16 + q * 4]     = f2tf(vv.x);
            Vs[t][d16 + q * 4 + 1] = f2tf(vv.y);
            Vs[t][d16 + q * 4 + 2] = f2tf(vv.z);
            Vs[t][d16 + q * 4 + 3] = f2tf(vv.w);
        }
    }
    __syncthreads();

    #pragma unroll
    for (int k8 = 0; k8 < 64; k8 += 8) {
        uint32_t a[4];
        a[0] = A_sh[t0 + g][k8 + tg];
        a[1] = A_sh[t0 + g + 8][k8 + tg];
        a[2] = A_sh[t0 + g][k8 + tg + 4];
        a[3] = A_sh[t0 + g + 8][k8 + tg + 4];
        #pragma unroll
        for (int j = 0; j < 4; j++) {
            uint32_t b0 = Vs[k8 + tg][n0 + j * 8 + g];
            uint32_t b1 = Vs[k8 + tg + 4][n0 + j * 8 + g];
            mma_tf32(c2[j], a, b0, b1);
        }
    }

    {
        int ta = t0 + g, tb2 = t0 + g + 8;
        float inva = 1.0f / den_sh[ta];
        float invb = 1.0f / den_sh[tb2];
        #pragma unroll
        for (int j = 0; j < 4; j++) {
            int d = n0 + j * 8 + 2 * tg;
            *(float2*)&g_ctx[((size_t)(b * LL + l0 + ta)) * DD + h * DHD + d] =
                make_float2(c2[j][0] * inva, c2[j][1] * inva);
            *(float2*)&g_ctx[((size_t)(b * LL + l0 + tb2)) * DD + h * DHD + d] =
                make_float2(c2[j][2] * invb, c2[j][3] * invb);
        }
    }
}

// ---------------- launch ----------------
extern "C" void kernel_launch(void* const* d_in, const int* in_sizes, int n_in,
                              void* d_out, int out_size) {
    const float* query = (const float*)d_in[0];
    const float* key   = (const float*)d_in[1];
    const float* value = (const float*)d_in[2];
    const float* Wq    = (const float*)d_in[3];
    const float* bq    = (const float*)d_in[4];
    const float* Wk    = (const float*)d_in[5];
    const float* bk    = (const float*)d_in[6];
    const float* Wv    = (const float*)d_in[7];
    const float* bv    = (const float*)d_in[8];
    const float* Wout  = (const float*)d_in[9];
    const float* bout  = (const float*)d_in[10];
    const float* RF    = (const float*)d_in[11];

    float *Qp, *Kp, *Vp, *qpp, *kpp, *Sp, *zp, *ctxp;
    cudaGetSymbolAddress((void**)&Qp,  g_Q);
    cudaGetSymbolAddress((void**)&Kp,  g_K);
    cudaGetSymbolAddress((void**)&Vp,  g_V);
    cudaGetSymbolAddress((void**)&qpp, g_qp);
    cudaGetSymbolAddress((void**)&kpp, g_kp);
    cudaGetSymbolAddress((void**)&Sp,  g_S);
    cudaGetSymbolAddress((void**)&zp,  g_z);
    cudaGetSymbolAddress((void**)&ctxp, g_ctx);

    cudaFuncSetAttribute(tf32_gemm, cudaFuncAttributeMaxDynamicSharedMemorySize, GSM_BYTES);

    dim3 gp(DD / 128, NROWS / 128, 3);
    tf32_gemm<<<gp, 256, GSM_BYTES>>>(query, Wq, bq, Qp,
                                      key,   Wk, bk, Kp,
                                      value, Wv, bv, Vp);

    dim3 fg((MM + 63) / 64, NROWS / 128, 2 * HH);
    feat_gemm<<<fg, 256>>>(Qp, Kp, RF, qpp, kpp);

    dim3 pg(NCH, BHT);
    phaseA_kernel<<<pg, 544>>>();

    int totThreads = BHT * (MM * DHD / 4) + BHT * MM;   // 68096 + 4256
    scan_kernel<<<(totThreads + 255) / 256, 256>>>(Sp, zp);

    phaseC_kernel<<<pg, 256>>>();

    dim3 go(DD / 128, NROWS / 128, 1);
    tf32_gemm<<<go, 256, GSM_BYTES>>>(ctxp, Wout, bout, (float*)d_out,
                                      ctxp, Wout, bout, (float*)d_out,
                                      ctxp, Wout, bout, (float*)d_out);
}